// round 3
// baseline (speedup 1.0000x reference)
#include <cuda_runtime.h>
#include <math.h>

#define HW 16384
#define BB 4

// ---------------- device scratch ----------------
__device__ float g_fused[BB*64*HW];            // conv_cd output [b][64][hw]
__device__ float g_xt[BB*130*130*64];          // padded x, channel-last [b][r][cc][c]
__device__ float g_off[BB*27*HW];              // offset(18)+m(9) [b][ch][hw]
__device__ float g_coff[(size_t)BB*HW*9*64];   // tanh(c_off) [b][pix][n][c]
__device__ float g_wpackT[576*640];            // [(ci*9+k)][co] packed conv weights (603->640)
__device__ float g_bias640[640];
__device__ float g_wcdT[128*64];               // [ci][co]
__device__ float g_wc2T[576*64];               // [(n*64+c)][oc] final conv weights

// ---------------- prep: pack / transpose weights ----------------
__global__ void prep_pack(const float* __restrict__ wp, const float* __restrict__ bp,
                          const float* __restrict__ wm, const float* __restrict__ bm,
                          const float* __restrict__ wc, const float* __restrict__ bc,
                          const float* __restrict__ wcd, const float* __restrict__ wconv)
{
    int idx = blockIdx.x * blockDim.x + threadIdx.x;
    if (idx < 576*640) {
        int k  = idx / 640, co = idx % 640;
        int ci = k / 9,     kk = k % 9;
        float v = 0.f;
        if      (co < 18)  v = wp[(co*64 + ci)*9 + kk];
        else if (co < 27)  v = wm[((co-18)*64 + ci)*9 + kk];
        else if (co < 603) v = wc[((co-27)*64 + ci)*9 + kk];
        g_wpackT[idx] = v;
    }
    if (idx < 640) {
        float bv = 0.f;
        if      (idx < 18)  bv = bp[idx];
        else if (idx < 27)  bv = bm[idx-18];
        else if (idx < 603) bv = bc[idx-27];
        g_bias640[idx] = bv;
    }
    if (idx < 128*64) {
        int ci = idx >> 6, co = idx & 63;
        g_wcdT[idx] = wcd[co*128 + ci];
    }
    if (idx < 576*64) {
        int row = idx >> 6, oc = idx & 63;
        int n = row >> 6, c = row & 63;
        g_wc2T[idx] = wconv[(oc*64 + c)*9 + n];
    }
}

// ---------------- prep: padded channel-last x ----------------
__global__ void prep_xt(const float* __restrict__ x)
{
    int idx = blockIdx.x * blockDim.x + threadIdx.x;
    const int total = BB*130*130*64;
    if (idx >= total) return;
    int c  = idx & 63;
    int t  = idx >> 6;
    int cc = t % 130; t /= 130;
    int r  = t % 130;
    int b  = t / 130;
    float v = 0.f;
    if (r >= 1 && r <= 128 && cc >= 1 && cc <= 128)
        v = x[((b*64 + c)*128 + (r-1))*128 + (cc-1)];
    g_xt[idx] = v;
}

// ---------------- K1: 1x1 conv concat([x,ref]) -> fused ----------------
__global__ __launch_bounds__(256) void k1_fused(const float* __restrict__ x,
                                                const float* __restrict__ ref,
                                                const float* __restrict__ bcd)
{
    __shared__ float xin[32][64];
    __shared__ float wsm[32][64];
    int tid  = threadIdx.x;
    int b    = blockIdx.x >> 8;
    int pix0 = (blockIdx.x & 255) * 64;
    int ocg  = tid & 15, pixg = tid >> 4;

    float acc[4][4];
#pragma unroll
    for (int o = 0; o < 4; o++) {
        float bv = bcd[ocg*4 + o];
#pragma unroll
        for (int j = 0; j < 4; j++) acc[o][j] = bv;
    }

    for (int ci0 = 0; ci0 < 128; ci0 += 32) {
#pragma unroll
        for (int it = 0; it < 8; it++) {
            int idx = it*256 + tid;
            int ci  = idx >> 6, px = idx & 63;
            int gl  = ci0 + ci;
            float v = (gl < 64) ? x[(b*64 + gl)*HW + pix0 + px]
                                : ref[(b*64 + gl - 64)*HW + pix0 + px];
            xin[ci][px] = v;
            wsm[ci][px] = g_wcdT[(ci0 + ci)*64 + px];
        }
        __syncthreads();
#pragma unroll
        for (int ci = 0; ci < 32; ci++) {
            float4 a  = *(const float4*)&xin[ci][pixg*4];
            float4 wv = *(const float4*)&wsm[ci][ocg*4];
            float av[4]  = {a.x, a.y, a.z, a.w};
            float wvv[4] = {wv.x, wv.y, wv.z, wv.w};
#pragma unroll
            for (int o = 0; o < 4; o++)
#pragma unroll
                for (int j = 0; j < 4; j++)
                    acc[o][j] += wvv[o]*av[j];
        }
        __syncthreads();
    }
#pragma unroll
    for (int o = 0; o < 4; o++) {
        float4 st = make_float4(acc[o][0], acc[o][1], acc[o][2], acc[o][3]);
        *(float4*)&g_fused[(b*64 + ocg*4 + o)*HW + pix0 + pixg*4] = st;
    }
}

// ---------------- K2: 3x3 conv 64 -> 603(640) with activations ----------------
// in_s row padded to 20 floats (80B) so float4 loads are always 16B-aligned.
__global__ __launch_bounds__(256) void k2_conv()
{
    __shared__ float in_s[8][10][20];
    __shared__ float w_s[72][128];
    int tid    = threadIdx.x;
    int b      = blockIdx.z;
    int cobase = blockIdx.y * 128;
    int h0     = (blockIdx.x >> 3) * 8;
    int w0     = (blockIdx.x & 7) * 16;
    int ocg    = tid & 15, pixid = tid >> 4;
    int prow   = pixid & 7, pcolg = pixid >> 3;

    float acc[8][8];
#pragma unroll
    for (int o = 0; o < 8; o++) {
        float bv = g_bias640[cobase + ocg*8 + o];
#pragma unroll
        for (int j = 0; j < 8; j++) acc[o][j] = bv;
    }

    for (int ci0 = 0; ci0 < 64; ci0 += 8) {
        for (int idx = tid; idx < 1440; idx += 256) {
            int ci  = idx / 180; int rem = idx - ci*180;
            int rr  = rem / 18;  int cc2 = rem - rr*18;
            int gh  = h0 + rr - 1, gw = w0 + cc2 - 1;
            float v = 0.f;
            if (gh >= 0 && gh < 128 && gw >= 0 && gw < 128)
                v = g_fused[((b*64 + ci0 + ci)*128 + gh)*128 + gw];
            in_s[ci][rr][cc2] = v;
        }
#pragma unroll
        for (int it = 0; it < 36; it++) {
            int idx = it*256 + tid;
            int k = idx >> 7, co = idx & 127;
            w_s[k][co] = g_wpackT[(ci0*9 + k)*640 + cobase + co];
        }
        __syncthreads();

#pragma unroll 1
        for (int lc = 0; lc < 8; lc++) {
#pragma unroll
            for (int kh = 0; kh < 3; kh++) {
                const float* rp = &in_s[lc][prow + kh][pcolg*8];
                float4 r0 = *(const float4*)rp;
                float4 r1 = *(const float4*)(rp + 4);
                float rv[10] = {r0.x, r0.y, r0.z, r0.w,
                                r1.x, r1.y, r1.z, r1.w, rp[8], rp[9]};
#pragma unroll
                for (int kw = 0; kw < 3; kw++) {
                    const float* wp2 = &w_s[lc*9 + kh*3 + kw][ocg*8];
                    float4 wa = *(const float4*)wp2;
                    float4 wb = *(const float4*)(wp2 + 4);
                    float wvv[8] = {wa.x, wa.y, wa.z, wa.w,
                                    wb.x, wb.y, wb.z, wb.w};
#pragma unroll
                    for (int o = 0; o < 8; o++)
#pragma unroll
                        for (int j = 0; j < 8; j++)
                            acc[o][j] += wvv[o]*rv[kw + j];
                }
            }
        }
        __syncthreads();
    }

    int gh = h0 + prow;
#pragma unroll
    for (int o = 0; o < 8; o++) {
        int co = cobase + ocg*8 + o;
        if (co < 603) {
#pragma unroll
            for (int j = 0; j < 8; j++) {
                int gw  = w0 + pcolg*8 + j;
                int pix = gh*128 + gw;
                float v = acc[o][j];
                if (co < 18)
                    g_off[(b*27 + co)*HW + pix] = v;
                else if (co < 27)
                    g_off[(b*27 + co)*HW + pix] = 1.f/(1.f + __expf(-v));
                else {
                    int cm = co - 27; int c = cm/9, n = cm - c*9;
                    g_coff[(((size_t)b*HW + pix)*9 + n)*64 + c] = tanhf(v);
                }
            }
        }
    }
}

// ---------------- K3: deformable sampling + modulation + final conv ----------------
__global__ __launch_bounds__(256) void k3_final(float* __restrict__ out)
{
    __shared__ float val_s[16*580];
    __shared__ float ws[16*64];
    __shared__ float tg[576];
    __shared__ int   tb[576];
    __shared__ float tm[144];
    __shared__ int   tcb[144];
    __shared__ int   tvb[144];

    int tid  = threadIdx.x;
    int b    = blockIdx.x >> 10;
    int tile = blockIdx.x & 1023;
    int h    = tile >> 3;
    int w0   = (tile & 7) << 4;

    if (tid < 144) {
        int task = tid;
        int pixl = task / 9, n = task - pixl*9;
        int w      = w0 + pixl;
        int pixidx = h*128 + w;
        float offr = g_off[(b*27 + n)*HW + pixidx];
        float offc = g_off[(b*27 + 9 + n)*HW + pixidx];
        float mv   = g_off[(b*27 + 18 + n)*HW + pixidx];
        float pr = (float)(h + 1 + n/3 - 1) + offr;
        float pc = (float)(w + 1 + n%3 - 1) + offc;
        float flr = floorf(pr), flc = floorf(pc);
        float ltr = fminf(fmaxf(flr,       0.f), 129.f);
        float ltc = fminf(fmaxf(flc,       0.f), 129.f);
        float rbr = fminf(fmaxf(flr + 1.f, 0.f), 129.f);
        float rbc = fminf(fmaxf(flc + 1.f, 0.f), 129.f);
        float prc = fminf(fmaxf(pr,        0.f), 129.f);
        float pcc = fminf(fmaxf(pc,        0.f), 129.f);
        tg[task*4+0] = (1.f + (ltr - prc))*(1.f + (ltc - pcc)); // lt
        tg[task*4+1] = (1.f - (rbr - prc))*(1.f - (rbc - pcc)); // rb
        tg[task*4+2] = (1.f + (ltr - prc))*(1.f - (rbc - pcc)); // lb
        tg[task*4+3] = (1.f - (rbr - prc))*(1.f + (ltc - pcc)); // rt
        int iltr = (int)ltr, iltc = (int)ltc, irbr = (int)rbr, irbc = (int)rbc;
        int bb = b*130;
        tb[task*4+0] = ((bb + iltr)*130 + iltc)*16;
        tb[task*4+1] = ((bb + irbr)*130 + irbc)*16;
        tb[task*4+2] = ((bb + iltr)*130 + irbc)*16;
        tb[task*4+3] = ((bb + irbr)*130 + iltc)*16;
        tm[task]  = mv;
        tcb[task] = ((b*HW + pixidx)*9 + n)*64;
        tvb[task] = pixl*580 + n*64;
    }
    __syncthreads();

    // phase 1: gather + combine, c-vectorized (float4 over channels)
    {
        const float4* xt4 = (const float4*)g_xt;
        int wid = tid >> 5, lane = tid & 31, th = lane >> 4, cv = lane & 15;
        for (int tp = wid; tp < 72; tp += 8) {
            int task = tp*2 + th;
            int b0 = tb[task*4+0], b1 = tb[task*4+1];
            int b2 = tb[task*4+2], b3 = tb[task*4+3];
            float g0 = tg[task*4+0], g1 = tg[task*4+1];
            float g2 = tg[task*4+2], g3 = tg[task*4+3];
            float mv = tm[task];
            float4 v0 = xt4[b0 + cv], v1 = xt4[b1 + cv];
            float4 v2 = xt4[b2 + cv], v3 = xt4[b3 + cv];
            float4 c4 = *(const float4*)&g_coff[(size_t)tcb[task] + cv*4];
            float4 r;
            r.x = (g0*v0.x + g1*v1.x + g2*v2.x + g3*v3.x + c4.x)*mv;
            r.y = (g0*v0.y + g1*v1.y + g2*v2.y + g3*v3.y + c4.y)*mv;
            r.z = (g0*v0.z + g1*v1.z + g2*v2.z + g3*v3.z + c4.z)*mv;
            r.w = (g0*v0.w + g1*v1.w + g2*v2.w + g3*v3.w + c4.w)*mv;
            *(float4*)&val_s[tvb[task] + cv*4] = r;
        }
    }
    __syncthreads();

    // phase 2: out[oc] = sum_k w2T[k][oc] * val[pix][k]
    {
        int oc = tid & 63, pg = tid >> 6;
        float acc0 = 0.f, acc1 = 0.f, acc2 = 0.f, acc3 = 0.f;
        int r0 = pg*580, r1 = (pg+4)*580, r2 = (pg+8)*580, r3 = (pg+12)*580;
        for (int k0 = 0; k0 < 576; k0 += 16) {
#pragma unroll
            for (int it = 0; it < 4; it++) {
                int idx = it*256 + tid;
                ws[idx] = g_wc2T[k0*64 + idx];
            }
            __syncthreads();
#pragma unroll
            for (int kk = 0; kk < 16; kk++) {
                float wv = ws[kk*64 + oc];
                int k = k0 + kk;
                acc0 += wv * val_s[r0 + k];
                acc1 += wv * val_s[r1 + k];
                acc2 += wv * val_s[r2 + k];
                acc3 += wv * val_s[r3 + k];
            }
            __syncthreads();
        }
        size_t ob = ((size_t)(b*64 + oc))*HW + h*128 + w0;
        out[ob + pg     ] = acc0;
        out[ob + pg + 4 ] = acc1;
        out[ob + pg + 8 ] = acc2;
        out[ob + pg + 12] = acc3;
    }
}

// ---------------- launch ----------------
extern "C" void kernel_launch(void* const* d_in, const int* in_sizes, int n_in,
                              void* d_out, int out_size)
{
    const float* x      = (const float*)d_in[0];
    const float* ref    = (const float*)d_in[1];
    const float* w_cd   = (const float*)d_in[2];
    const float* b_cd   = (const float*)d_in[3];
    const float* w_p    = (const float*)d_in[4];
    const float* b_p    = (const float*)d_in[5];
    const float* w_m    = (const float*)d_in[6];
    const float* b_m    = (const float*)d_in[7];
    const float* w_c    = (const float*)d_in[8];
    const float* b_c    = (const float*)d_in[9];
    const float* w_conv = (const float*)d_in[10];
    float* out = (float*)d_out;

    prep_pack<<<(576*640 + 255)/256, 256>>>(w_p, b_p, w_m, b_m, w_c, b_c, w_cd, w_conv);
    prep_xt<<<(BB*130*130*64 + 255)/256, 256>>>(x);
    k1_fused<<<1024, 256>>>(x, ref, b_cd);
    k2_conv<<<dim3(128, 5, 4), 256>>>();
    k3_final<<<4096, 256>>>(out);
}

// round 7
// speedup vs baseline: 1.8557x; 1.8557x over previous
#include <cuda_runtime.h>
#include <cuda_bf16.h>
#include <math.h>
#include <stdint.h>

#define HW 16384
#define BB 4

// ---------------- device scratch ----------------
__device__ __nv_bfloat16 g_fph[(size_t)BB*130*130*64]; // padded channel-last fused, hi
__device__ __nv_bfloat16 g_fpl[(size_t)BB*130*130*64]; // lo
__device__ float g_xt[BB*130*130*64];                  // padded x, channel-last [b][r][cc][c]
__device__ float g_off[BB*27*HW];                      // offset(18)+m(9) [b][ch][hw]
__device__ float g_coff[(size_t)BB*HW*9*64];           // tanh(c_off) [b][pix][n*64+c]
__device__ __nv_bfloat16 g_wbh[9*640*64];              // [kk][co'][ci] hi
__device__ __nv_bfloat16 g_wbl[9*640*64];              // lo
__device__ float g_bias640[640];                       // co' order
__device__ float g_wcdT[128*64];                       // [ci][co]
__device__ float g_wc2T[576*64];                       // [(n*64+c)][oc] final conv weights

#define SW128(o) ((o) ^ (((o) >> 3) & 0x70))

__device__ __forceinline__ uint32_t smem_u32(const void* p) {
    uint32_t a;
    asm("{ .reg .u64 t; cvta.to.shared.u64 t, %1; cvt.u32.u64 %0, t; }" : "=r"(a) : "l"(p));
    return a;
}
__device__ __forceinline__ void ldm_x4(uint32_t* r, uint32_t addr) {
    asm volatile("ldmatrix.sync.aligned.m8n8.x4.shared.b16 {%0,%1,%2,%3}, [%4];"
        : "=r"(r[0]), "=r"(r[1]), "=r"(r[2]), "=r"(r[3]) : "r"(addr));
}
__device__ __forceinline__ void mma16816(float* d, const uint32_t* a, uint32_t b0, uint32_t b1) {
    asm volatile("mma.sync.aligned.m16n8k16.row.col.f32.bf16.bf16.f32 "
        "{%0,%1,%2,%3}, {%4,%5,%6,%7}, {%8,%9}, {%0,%1,%2,%3};"
        : "+f"(d[0]), "+f"(d[1]), "+f"(d[2]), "+f"(d[3])
        : "r"(a[0]), "r"(a[1]), "r"(a[2]), "r"(a[3]), "r"(b0), "r"(b1));
}

// ---------------- prep: zero-fill padded fused buffers ----------------
__global__ void prep_zero()
{
    int i = blockIdx.x * blockDim.x + threadIdx.x;
    const int n4 = (int)((size_t)BB*130*130*64/8);
    if (i < n4) {
        ((uint4*)g_fph)[i] = make_uint4(0,0,0,0);
        ((uint4*)g_fpl)[i] = make_uint4(0,0,0,0);
    }
}

// ---------------- prep: pack weights ----------------
__global__ void prep_pack(const float* __restrict__ wp, const float* __restrict__ bp,
                          const float* __restrict__ wm, const float* __restrict__ bm,
                          const float* __restrict__ wc, const float* __restrict__ bc,
                          const float* __restrict__ wcd, const float* __restrict__ wconv)
{
    int idx = blockIdx.x * blockDim.x + threadIdx.x;
    if (idx < 9*640*64) {
        int kk = idx / (640*64);
        int r  = idx - kk*640*64;
        int co = r >> 6, ci = r & 63;
        float v = 0.f;
        if      (co < 18)  v = wp[(co*64 + ci)*9 + kk];
        else if (co < 27)  v = wm[((co-18)*64 + ci)*9 + kk];
        else if (co < 603) { int t = co-27; int n = t >> 6, c = t & 63;
                             v = wc[((c*9 + n)*64 + ci)*9 + kk]; }
        __nv_bfloat16 hi = __float2bfloat16(v);
        g_wbh[idx] = hi;
        g_wbl[idx] = __float2bfloat16(v - __bfloat162float(hi));
    }
    if (idx < 640) {
        float bv = 0.f;
        if      (idx < 18)  bv = bp[idx];
        else if (idx < 27)  bv = bm[idx-18];
        else if (idx < 603) { int t = idx-27; int n = t >> 6, c = t & 63; bv = bc[c*9 + n]; }
        g_bias640[idx] = bv;
    }
    if (idx < 128*64) {
        int ci = idx >> 6, co = idx & 63;
        g_wcdT[idx] = wcd[co*128 + ci];
    }
    if (idx < 576*64) {
        int row = idx >> 6, oc = idx & 63;
        int n = row >> 6, c = row & 63;
        g_wc2T[idx] = wconv[(oc*64 + c)*9 + n];
    }
}

// ---------------- prep: padded channel-last x ----------------
__global__ void prep_xt(const float* __restrict__ x)
{
    int idx = blockIdx.x * blockDim.x + threadIdx.x;
    const int total = BB*130*130*64;
    if (idx >= total) return;
    int c  = idx & 63;
    int t  = idx >> 6;
    int cc = t % 130; t /= 130;
    int r  = t % 130;
    int b  = t / 130;
    float v = 0.f;
    if (r >= 1 && r <= 128 && cc >= 1 && cc <= 128)
        v = x[((b*64 + c)*128 + (r-1))*128 + (cc-1)];
    g_xt[idx] = v;
}

// ---------------- K1: 1x1 conv -> padded channel-last bf16 hi/lo ----------------
__global__ __launch_bounds__(256) void k1_fused(const float* __restrict__ x,
                                                const float* __restrict__ ref,
                                                const float* __restrict__ bcd)
{
    __shared__ float xin[32][64];
    __shared__ float wsm[32][64];
    int tid  = threadIdx.x;
    int b    = blockIdx.x >> 8;
    int pix0 = (blockIdx.x & 255) * 64;
    int ocg  = tid & 15, pixg = tid >> 4;

    float acc[4][4];
#pragma unroll
    for (int o = 0; o < 4; o++) {
        float bv = bcd[ocg*4 + o];
#pragma unroll
        for (int j = 0; j < 4; j++) acc[o][j] = bv;
    }

    for (int ci0 = 0; ci0 < 128; ci0 += 32) {
#pragma unroll
        for (int it = 0; it < 8; it++) {
            int idx = it*256 + tid;
            int ci  = idx >> 6, px = idx & 63;
            int gl  = ci0 + ci;
            float v = (gl < 64) ? x[(b*64 + gl)*HW + pix0 + px]
                                : ref[(b*64 + gl - 64)*HW + pix0 + px];
            xin[ci][px] = v;
            wsm[ci][px] = g_wcdT[(ci0 + ci)*64 + px];
        }
        __syncthreads();
#pragma unroll
        for (int ci = 0; ci < 32; ci++) {
            float4 a  = *(const float4*)&xin[ci][pixg*4];
            float4 wv = *(const float4*)&wsm[ci][ocg*4];
            float av[4]  = {a.x, a.y, a.z, a.w};
            float wvv[4] = {wv.x, wv.y, wv.z, wv.w};
#pragma unroll
            for (int o = 0; o < 4; o++)
#pragma unroll
                for (int j = 0; j < 4; j++)
                    acc[o][j] += wvv[o]*av[j];
        }
        __syncthreads();
    }
#pragma unroll
    for (int o = 0; o < 4; o++) {
#pragma unroll
        for (int j = 0; j < 4; j++) {
            int pix = pix0 + pixg*4 + j;
            int hh = pix >> 7, ww = pix & 127;
            size_t base = ((size_t)(b*130 + hh + 1)*130 + (ww + 1))*64 + (ocg*4 + o);
            float v = acc[o][j];
            __nv_bfloat16 hi = __float2bfloat16(v);
            g_fph[base] = hi;
            g_fpl[base] = __float2bfloat16(v - __bfloat162float(hi));
        }
    }
}

// ---------------- K2: HMMA implicit GEMM conv 64->603(640) ----------------
// grid (5, 512), 256 threads (8 warps), dyn smem 66048 B
// smem layout during mainloop: [0)Ah [16K)Al [32K)Wh [48K)Wl ; epilogue: 128x129 floats
__global__ __launch_bounds__(256, 2) void k2_mma()
{
    extern __shared__ __align__(16) char smem[];
    float* smem_f = (float*)smem;
    uint32_t sb = smem_u32(smem);
    int tid = threadIdx.x, wid = tid >> 5, lane = tid & 31;
    int ntile = blockIdx.x;               // 0..4 -> co' base = ntile*128
    int mt    = blockIdx.y;
    int b = mt >> 7, h = mt & 127;
    int co0 = ntile * 128;
    int warp_m = wid >> 2, warp_n = wid & 3;

    float acc[4][4][4];
#pragma unroll
    for (int i = 0; i < 4; i++)
#pragma unroll
        for (int j = 0; j < 4; j++)
#pragma unroll
            for (int q = 0; q < 4; q++) acc[i][j][q] = 0.f;

    // per-lane ldmatrix address components
    int bn_row = warp_n*32 + (lane & 7) + ((lane >> 4) << 3);  // + npair*16 -> W row (co')
    int bn_kof = ((lane >> 3) & 1) * 8;                        // + kb -> W col (ci)
    int am_row = warp_m*64 + (lane & 7) + (((lane >> 3) & 1) << 3); // + msub*16 -> A row
    int am_kof = (lane >> 4) << 3;                             // + kb -> A col

    for (int it9 = 0; it9 < 9; it9++) {
        int kh = it9 / 3, kw = it9 - kh*3;
        // ---- fill A (128x64 bf16 hi/lo) + W (128x64 hi/lo), SW128 swizzled ----
        {
            size_t rowbase = ((size_t)(b*130 + h + kh)*130 + kw) * 64;
            const uint4* sAh = (const uint4*)(g_fph + rowbase);
            const uint4* sAl = (const uint4*)(g_fpl + rowbase);
            size_t wbase = ((size_t)(it9*640 + co0)) * 64;
            const uint4* sWh = (const uint4*)(g_wbh + wbase);
            const uint4* sWl = (const uint4*)(g_wbl + wbase);
#pragma unroll
            for (int it = 0; it < 4; it++) {
                int i = it*256 + tid;
                int sw = SW128(i * 16);
                *(uint4*)(smem + sw)         = sAh[i];
                *(uint4*)(smem + 16384 + sw) = sAl[i];
                *(uint4*)(smem + 32768 + sw) = sWh[i];
                *(uint4*)(smem + 49152 + sw) = sWl[i];
            }
        }
        __syncthreads();

#pragma unroll
        for (int kc = 0; kc < 4; kc++) {
            int kb = kc * 16;
            // B fragments: bh/bl[npair*4 + {b0,b1 of even nsub, b0,b1 of odd nsub}]
            uint32_t bh[8], bl[8];
#pragma unroll
            for (int npair = 0; npair < 2; npair++) {
                uint32_t off = SW128((bn_row + npair*16)*128 + (kb + bn_kof)*2);
                ldm_x4(&bh[npair*4], sb + 32768 + off);
                ldm_x4(&bl[npair*4], sb + 49152 + off);
            }
#pragma unroll
            for (int msub = 0; msub < 4; msub++) {
                uint32_t aoff = SW128((am_row + msub*16)*128 + (kb + am_kof)*2);
                uint32_t a[4];
                ldm_x4(a, sb + aoff);              // Ah
#pragma unroll
                for (int nsub = 0; nsub < 4; nsub++) {
                    int bi = (nsub >> 1)*4 + (nsub & 1)*2;
                    mma16816(acc[msub][nsub], a, bh[bi], bh[bi+1]);  // Ah*Wh
                    mma16816(acc[msub][nsub], a, bl[bi], bl[bi+1]);  // Ah*Wl
                }
                ldm_x4(a, sb + 16384 + aoff);      // Al
#pragma unroll
                for (int nsub = 0; nsub < 4; nsub++) {
                    int bi = (nsub >> 1)*4 + (nsub & 1)*2;
                    mma16816(acc[msub][nsub], a, bh[bi], bh[bi+1]);  // Al*Wh
                }
            }
        }
        __syncthreads();
    }

    // ---------- epilogue: stage 128x128 tile in smem (stride 129) ----------
#pragma unroll
    for (int msub = 0; msub < 4; msub++) {
#pragma unroll
        for (int nsub = 0; nsub < 4; nsub++) {
            int m  = warp_m*64 + msub*16 + (lane >> 2);
            int cl = warp_n*32 + nsub*8 + (lane & 3)*2;
            smem_f[m*129 + cl]       = acc[msub][nsub][0];
            smem_f[m*129 + cl + 1]   = acc[msub][nsub][1];
            smem_f[(m+8)*129 + cl]   = acc[msub][nsub][2];
            smem_f[(m+8)*129 + cl+1] = acc[msub][nsub][3];
        }
    }
    __syncthreads();

    int pixrow = h*128;
    if (ntile == 0) {
        for (int idx = tid; idx < 27*128; idx += 256) {
            int co = idx >> 7, p = idx & 127;
            float v = smem_f[p*129 + co] + g_bias640[co];
            if (co >= 18) v = 1.f/(1.f + __expf(-v));
            g_off[(b*27 + co)*HW + pixrow + p] = v;
        }
        for (int idx = tid; idx < 128*101; idx += 256) {
            int p = idx / 101, j = idx - p*101 + 27;   // co 27..127
            float v = tanhf(smem_f[p*129 + j] + g_bias640[j]);
            g_coff[((size_t)(b*HW + pixrow + p))*576 + (j - 27)] = v;
        }
    } else {
        for (int idx = tid; idx < 128*128; idx += 256) {
            int p = idx >> 7, j = idx & 127;
            int co = co0 + j;
            if (co < 603) {
                float v = tanhf(smem_f[p*129 + j] + g_bias640[co]);
                g_coff[((size_t)(b*HW + pixrow + p))*576 + (co - 27)] = v;
            }
        }
    }
}

// ---------------- K3: deformable sampling + modulation + final conv ----------------
__global__ __launch_bounds__(256) void k3_final(float* __restrict__ out)
{
    __shared__ float val_s[16*580];
    __shared__ float ws[16*64];
    __shared__ float tg[576];
    __shared__ int   tb[576];
    __shared__ float tm[144];
    __shared__ int   tcb[144];
    __shared__ int   tvb[144];

    int tid  = threadIdx.x;
    int b    = blockIdx.x >> 10;
    int tile = blockIdx.x & 1023;
    int h    = tile >> 3;
    int w0   = (tile & 7) << 4;

    if (tid < 144) {
        int task = tid;
        int pixl = task / 9, n = task - pixl*9;
        int w      = w0 + pixl;
        int pixidx = h*128 + w;
        float offr = g_off[(b*27 + n)*HW + pixidx];
        float offc = g_off[(b*27 + 9 + n)*HW + pixidx];
        float mv   = g_off[(b*27 + 18 + n)*HW + pixidx];
        float pr = (float)(h + 1 + n/3 - 1) + offr;
        float pc = (float)(w + 1 + n%3 - 1) + offc;
        float flr = floorf(pr), flc = floorf(pc);
        float ltr = fminf(fmaxf(flr,       0.f), 129.f);
        float ltc = fminf(fmaxf(flc,       0.f), 129.f);
        float rbr = fminf(fmaxf(flr + 1.f, 0.f), 129.f);
        float rbc = fminf(fmaxf(flc + 1.f, 0.f), 129.f);
        float prc = fminf(fmaxf(pr,        0.f), 129.f);
        float pcc = fminf(fmaxf(pc,        0.f), 129.f);
        tg[task*4+0] = (1.f + (ltr - prc))*(1.f + (ltc - pcc)); // lt
        tg[task*4+1] = (1.f - (rbr - prc))*(1.f - (rbc - pcc)); // rb
        tg[task*4+2] = (1.f + (ltr - prc))*(1.f - (rbc - pcc)); // lb
        tg[task*4+3] = (1.f - (rbr - prc))*(1.f + (ltc - pcc)); // rt
        int iltr = (int)ltr, iltc = (int)ltc, irbr = (int)rbr, irbc = (int)rbc;
        int bb = b*130;
        tb[task*4+0] = ((bb + iltr)*130 + iltc)*16;
        tb[task*4+1] = ((bb + irbr)*130 + irbc)*16;
        tb[task*4+2] = ((bb + iltr)*130 + irbc)*16;
        tb[task*4+3] = ((bb + irbr)*130 + iltc)*16;
        tm[task]  = mv;
        tcb[task] = ((b*HW + pixidx)*9 + n)*64;
        tvb[task] = pixl*580 + n*64;
    }
    __syncthreads();

    // phase 1: gather + combine, c-vectorized (float4 over channels)
    {
        const float4* xt4 = (const float4*)g_xt;
        int wid = tid >> 5, lane = tid & 31, th = lane >> 4, cv = lane & 15;
        for (int tp = wid; tp < 72; tp += 8) {
            int task = tp*2 + th;
            int b0 = tb[task*4+0], b1 = tb[task*4+1];
            int b2 = tb[task*4+2], b3 = tb[task*4+3];
            float g0 = tg[task*4+0], g1 = tg[task*4+1];
            float g2 = tg[task*4+2], g3 = tg[task*4+3];
            float mv = tm[task];
            float4 v0 = xt4[b0 + cv], v1 = xt4[b1 + cv];
            float4 v2 = xt4[b2 + cv], v3 = xt4[b3 + cv];
            float4 c4 = *(const float4*)&g_coff[(size_t)tcb[task] + cv*4];
            float4 r;
            r.x = (g0*v0.x + g1*v1.x + g2*v2.x + g3*v3.x + c4.x)*mv;
            r.y = (g0*v0.y + g1*v1.y + g2*v2.y + g3*v3.y + c4.y)*mv;
            r.z = (g0*v0.z + g1*v1.z + g2*v2.z + g3*v3.z + c4.z)*mv;
            r.w = (g0*v0.w + g1*v1.w + g2*v2.w + g3*v3.w + c4.w)*mv;
            *(float4*)&val_s[tvb[task] + cv*4] = r;
        }
    }
    __syncthreads();

    // phase 2: out[oc] = sum_k w2T[k][oc] * val[pix][k]
    {
        int oc = tid & 63, pg = tid >> 6;
        float acc0 = 0.f, acc1 = 0.f, acc2 = 0.f, acc3 = 0.f;
        int r0 = pg*580, r1 = (pg+4)*580, r2 = (pg+8)*580, r3 = (pg+12)*580;
        for (int k0 = 0; k0 < 576; k0 += 16) {
#pragma unroll
            for (int it = 0; it < 4; it++) {
                int idx = it*256 + tid;
                ws[idx] = g_wc2T[k0*64 + idx];
            }
            __syncthreads();
#pragma unroll
            for (int kk = 0; kk < 16; kk++) {
                float wv = ws[kk*64 + oc];
                int k = k0 + kk;
                acc0 += wv * val_s[r0 + k];
                acc1 += wv * val_s[r1 + k];
                acc2 += wv * val_s[r2 + k];
                acc3 += wv * val_s[r3 + k];
            }
            __syncthreads();
        }
        size_t ob = ((size_t)(b*64 + oc))*HW + h*128 + w0;
        out[ob + pg     ] = acc0;
        out[ob + pg + 4 ] = acc1;
        out[ob + pg + 8 ] = acc2;
        out[ob + pg + 12] = acc3;
    }
}

// ---------------- launch ----------------
extern "C" void kernel_launch(void* const* d_in, const int* in_sizes, int n_in,
                              void* d_out, int out_size)
{
    const float* x      = (const float*)d_in[0];
    const float* ref    = (const float*)d_in[1];
    const float* w_cd   = (const float*)d_in[2];
    const float* b_cd   = (const float*)d_in[3];
    const float* w_p    = (const float*)d_in[4];
    const float* b_p    = (const float*)d_in[5];
    const float* w_m    = (const float*)d_in[6];
    const float* b_m    = (const float*)d_in[7];
    const float* w_c    = (const float*)d_in[8];
    const float* b_c    = (const float*)d_in[9];
    const float* w_conv = (const float*)d_in[10];
    float* out = (float*)d_out;

    cudaFuncSetAttribute(k2_mma, cudaFuncAttributeMaxDynamicSharedMemorySize, 66048);

    prep_zero<<<(BB*130*130*64/8 + 255)/256, 256>>>();
    prep_pack<<<(9*640*64 + 255)/256, 256>>>(w_p, b_p, w_m, b_m, w_c, b_c, w_cd, w_conv);
    prep_xt<<<(BB*130*130*64 + 255)/256, 256>>>(x);
    k1_fused<<<1024, 256>>>(x, ref, b_cd);
    k2_mma<<<dim3(5, 512), 256, 66048>>>();
    k3_final<<<4096, 256>>>(out);
}

// round 8
// speedup vs baseline: 1.9407x; 1.0458x over previous
#include <cuda_runtime.h>
#include <cuda_bf16.h>
#include <math.h>
#include <stdint.h>

#define HW 16384
#define BB 4

// ---------------- device scratch ----------------
__device__ __nv_bfloat16 g_fph[(size_t)BB*130*130*64]; // padded channel-last fused, hi
__device__ __nv_bfloat16 g_fpl[(size_t)BB*130*130*64]; // lo
__device__ float g_xt[BB*130*130*64];                  // padded x, channel-last [b][r][cc][c]
__device__ float g_off[BB*27*HW];                      // offset(18)+m(9) [b][ch][hw]
__device__ float g_coff[(size_t)BB*HW*9*64];           // tanh(c_off) [b][pix][n*64+c]
__device__ __nv_bfloat16 g_wbh[9*640*64];              // [kk][co'][ci] hi
__device__ __nv_bfloat16 g_wbl[9*640*64];              // lo
__device__ float g_bias640[640];                       // co' order
__device__ float g_wcdT[128*64];                       // [ci][co]
__device__ __nv_bfloat16 g_w2h[9*64*64];               // [n][oc][c] final conv hi
__device__ __nv_bfloat16 g_w2l[9*64*64];               // lo

#define SW128(o) ((o) ^ (((o) >> 3) & 0x70))

__device__ __forceinline__ uint32_t smem_u32(const void* p) {
    uint32_t a;
    asm("{ .reg .u64 t; cvta.to.shared.u64 t, %1; cvt.u32.u64 %0, t; }" : "=r"(a) : "l"(p));
    return a;
}
__device__ __forceinline__ void ldm_x4(uint32_t* r, uint32_t addr) {
    asm volatile("ldmatrix.sync.aligned.m8n8.x4.shared.b16 {%0,%1,%2,%3}, [%4];"
        : "=r"(r[0]), "=r"(r[1]), "=r"(r[2]), "=r"(r[3]) : "r"(addr));
}
__device__ __forceinline__ void mma16816(float* d, const uint32_t* a, uint32_t b0, uint32_t b1) {
    asm volatile("mma.sync.aligned.m16n8k16.row.col.f32.bf16.bf16.f32 "
        "{%0,%1,%2,%3}, {%4,%5,%6,%7}, {%8,%9}, {%0,%1,%2,%3};"
        : "+f"(d[0]), "+f"(d[1]), "+f"(d[2]), "+f"(d[3])
        : "r"(a[0]), "r"(a[1]), "r"(a[2]), "r"(a[3]), "r"(b0), "r"(b1));
}
__device__ __forceinline__ float tanh_fast(float v) {
    float e = __expf(2.f * v);
    return 1.f - 2.f / (e + 1.f);
}
__device__ __forceinline__ uint32_t pack_bf16_hi(float a, float b) {
    return ((uint32_t)__bfloat16_as_ushort(__float2bfloat16(b)) << 16)
         |  (uint32_t)__bfloat16_as_ushort(__float2bfloat16(a));
}
__device__ __forceinline__ uint32_t pack_bf16_lo(float a, float b) {
    __nv_bfloat16 ha = __float2bfloat16(a), hb = __float2bfloat16(b);
    float la = a - __bfloat162float(ha), lb = b - __bfloat162float(hb);
    return ((uint32_t)__bfloat16_as_ushort(__float2bfloat16(lb)) << 16)
         |  (uint32_t)__bfloat16_as_ushort(__float2bfloat16(la));
}

// ---------------- prep: zero-fill padded fused buffers ----------------
__global__ void prep_zero()
{
    int i = blockIdx.x * blockDim.x + threadIdx.x;
    const int n4 = (int)((size_t)BB*130*130*64/8);
    if (i < n4) {
        ((uint4*)g_fph)[i] = make_uint4(0,0,0,0);
        ((uint4*)g_fpl)[i] = make_uint4(0,0,0,0);
    }
}

// ---------------- prep: pack weights ----------------
__global__ void prep_pack(const float* __restrict__ wp, const float* __restrict__ bp,
                          const float* __restrict__ wm, const float* __restrict__ bm,
                          const float* __restrict__ wc, const float* __restrict__ bc,
                          const float* __restrict__ wcd, const float* __restrict__ wconv)
{
    int idx = blockIdx.x * blockDim.x + threadIdx.x;
    if (idx < 9*640*64) {
        int kk = idx / (640*64);
        int r  = idx - kk*640*64;
        int co = r >> 6, ci = r & 63;
        float v = 0.f;
        if      (co < 18)  v = wp[(co*64 + ci)*9 + kk];
        else if (co < 27)  v = wm[((co-18)*64 + ci)*9 + kk];
        else if (co < 603) { int t = co-27; int n = t >> 6, c = t & 63;
                             v = wc[((c*9 + n)*64 + ci)*9 + kk]; }
        __nv_bfloat16 hi = __float2bfloat16(v);
        g_wbh[idx] = hi;
        g_wbl[idx] = __float2bfloat16(v - __bfloat162float(hi));
    }
    if (idx < 640) {
        float bv = 0.f;
        if      (idx < 18)  bv = bp[idx];
        else if (idx < 27)  bv = bm[idx-18];
        else if (idx < 603) { int t = idx-27; int n = t >> 6, c = t & 63; bv = bc[c*9 + n]; }
        g_bias640[idx] = bv;
    }
    if (idx < 128*64) {
        int ci = idx >> 6, co = idx & 63;
        g_wcdT[idx] = wcd[co*128 + ci];
    }
    if (idx < 9*64*64) {
        int n = idx >> 12, r = idx & 4095;
        int oc = r >> 6, c = r & 63;
        float v = wconv[(oc*64 + c)*9 + n];
        __nv_bfloat16 hi = __float2bfloat16(v);
        g_w2h[idx] = hi;
        g_w2l[idx] = __float2bfloat16(v - __bfloat162float(hi));
    }
}

// ---------------- prep: padded channel-last x ----------------
__global__ void prep_xt(const float* __restrict__ x)
{
    int idx = blockIdx.x * blockDim.x + threadIdx.x;
    const int total = BB*130*130*64;
    if (idx >= total) return;
    int c  = idx & 63;
    int t  = idx >> 6;
    int cc = t % 130; t /= 130;
    int r  = t % 130;
    int b  = t / 130;
    float v = 0.f;
    if (r >= 1 && r <= 128 && cc >= 1 && cc <= 128)
        v = x[((b*64 + c)*128 + (r-1))*128 + (cc-1)];
    g_xt[idx] = v;
}

// ---------------- K1: 1x1 conv -> padded channel-last bf16 hi/lo ----------------
// block: 128 px x 64 oc, 256 threads
__global__ __launch_bounds__(256) void k1_fused(const float* __restrict__ x,
                                                const float* __restrict__ ref,
                                                const float* __restrict__ bcd)
{
    __shared__ float xin[32][128];
    __shared__ float wsm[32][64];
    int tid  = threadIdx.x;
    int b    = blockIdx.x >> 7;
    int seg  = blockIdx.x & 127;
    int pix0 = seg << 7;
    int ocg  = tid & 15, pixg = tid >> 4;

    float acc[4][8];
#pragma unroll
    for (int o = 0; o < 4; o++) {
        float bv = bcd[ocg*4 + o];
#pragma unroll
        for (int j = 0; j < 8; j++) acc[o][j] = bv;
    }

    for (int ci0 = 0; ci0 < 128; ci0 += 32) {
#pragma unroll
        for (int it = 0; it < 16; it++) {
            int idx = it*256 + tid;
            int ci  = idx >> 7, px = idx & 127;
            int gl  = ci0 + ci;
            float v = (gl < 64) ? x[(b*64 + gl)*HW + pix0 + px]
                                : ref[(b*64 + gl - 64)*HW + pix0 + px];
            xin[ci][px] = v;
        }
#pragma unroll
        for (int it = 0; it < 8; it++) {
            int idx = it*256 + tid;
            int ci = idx >> 6, oc = idx & 63;
            wsm[ci][oc] = g_wcdT[(ci0 + ci)*64 + oc];
        }
        __syncthreads();
#pragma unroll
        for (int ci = 0; ci < 32; ci++) {
            float4 wv = *(const float4*)&wsm[ci][ocg*4];
            float4 x0 = *(const float4*)&xin[ci][pixg*8];
            float4 x1 = *(const float4*)&xin[ci][pixg*8 + 4];
            float wvv[4] = {wv.x, wv.y, wv.z, wv.w};
            float xv[8]  = {x0.x, x0.y, x0.z, x0.w, x1.x, x1.y, x1.z, x1.w};
#pragma unroll
            for (int o = 0; o < 4; o++)
#pragma unroll
                for (int j = 0; j < 8; j++)
                    acc[o][j] += wvv[o]*xv[j];
        }
        __syncthreads();
    }
#pragma unroll
    for (int j = 0; j < 8; j++) {
        int ww = pixg*8 + j;
        size_t base = ((size_t)(b*130 + seg + 1)*130 + (ww + 1))*64 + ocg*4;
        *(uint32_t*)&g_fph[base]     = pack_bf16_hi(acc[0][j], acc[1][j]);
        *(uint32_t*)&g_fph[base + 2] = pack_bf16_hi(acc[2][j], acc[3][j]);
        *(uint32_t*)&g_fpl[base]     = pack_bf16_lo(acc[0][j], acc[1][j]);
        *(uint32_t*)&g_fpl[base + 2] = pack_bf16_lo(acc[2][j], acc[3][j]);
    }
}

// ---------------- K2: HMMA implicit GEMM conv 64->603(640) ----------------
__global__ __launch_bounds__(256, 2) void k2_mma()
{
    extern __shared__ __align__(16) char smem[];
    float* smem_f = (float*)smem;
    uint32_t sb = smem_u32(smem);
    int tid = threadIdx.x, wid = tid >> 5, lane = tid & 31;
    int ntile = blockIdx.x;               // 0..4 -> co' base = ntile*128
    int mt    = blockIdx.y;
    int b = mt >> 7, h = mt & 127;
    int co0 = ntile * 128;
    int warp_m = wid >> 2, warp_n = wid & 3;

    float acc[4][4][4];
#pragma unroll
    for (int i = 0; i < 4; i++)
#pragma unroll
        for (int j = 0; j < 4; j++)
#pragma unroll
            for (int q = 0; q < 4; q++) acc[i][j][q] = 0.f;

    int bn_row = warp_n*32 + (lane & 7) + ((lane >> 4) << 3);
    int bn_kof = ((lane >> 3) & 1) * 8;
    int am_row = warp_m*64 + (lane & 7) + (((lane >> 3) & 1) << 3);
    int am_kof = (lane >> 4) << 3;

    for (int it9 = 0; it9 < 9; it9++) {
        int kh = it9 / 3, kw = it9 - kh*3;
        {
            size_t rowbase = ((size_t)(b*130 + h + kh)*130 + kw) * 64;
            const uint4* sAh = (const uint4*)(g_fph + rowbase);
            const uint4* sAl = (const uint4*)(g_fpl + rowbase);
            size_t wbase = ((size_t)(it9*640 + co0)) * 64;
            const uint4* sWh = (const uint4*)(g_wbh + wbase);
            const uint4* sWl = (const uint4*)(g_wbl + wbase);
#pragma unroll
            for (int it = 0; it < 4; it++) {
                int i = it*256 + tid;
                int sw = SW128(i * 16);
                *(uint4*)(smem + sw)         = sAh[i];
                *(uint4*)(smem + 16384 + sw) = sAl[i];
                *(uint4*)(smem + 32768 + sw) = sWh[i];
                *(uint4*)(smem + 49152 + sw) = sWl[i];
            }
        }
        __syncthreads();

#pragma unroll
        for (int kc = 0; kc < 4; kc++) {
            int kb = kc * 16;
            uint32_t bh[8], bl[8];
#pragma unroll
            for (int npair = 0; npair < 2; npair++) {
                uint32_t off = SW128((bn_row + npair*16)*128 + (kb + bn_kof)*2);
                ldm_x4(&bh[npair*4], sb + 32768 + off);
                ldm_x4(&bl[npair*4], sb + 49152 + off);
            }
#pragma unroll
            for (int msub = 0; msub < 4; msub++) {
                uint32_t aoff = SW128((am_row + msub*16)*128 + (kb + am_kof)*2);
                uint32_t a[4];
                ldm_x4(a, sb + aoff);
#pragma unroll
                for (int nsub = 0; nsub < 4; nsub++) {
                    int bi = (nsub >> 1)*4 + (nsub & 1)*2;
                    mma16816(acc[msub][nsub], a, bh[bi], bh[bi+1]);
                    mma16816(acc[msub][nsub], a, bl[bi], bl[bi+1]);
                }
                ldm_x4(a, sb + 16384 + aoff);
#pragma unroll
                for (int nsub = 0; nsub < 4; nsub++) {
                    int bi = (nsub >> 1)*4 + (nsub & 1)*2;
                    mma16816(acc[msub][nsub], a, bh[bi], bh[bi+1]);
                }
            }
        }
        __syncthreads();
    }

#pragma unroll
    for (int msub = 0; msub < 4; msub++) {
#pragma unroll
        for (int nsub = 0; nsub < 4; nsub++) {
            int m  = warp_m*64 + msub*16 + (lane >> 2);
            int cl = warp_n*32 + nsub*8 + (lane & 3)*2;
            smem_f[m*129 + cl]       = acc[msub][nsub][0];
            smem_f[m*129 + cl + 1]   = acc[msub][nsub][1];
            smem_f[(m+8)*129 + cl]   = acc[msub][nsub][2];
            smem_f[(m+8)*129 + cl+1] = acc[msub][nsub][3];
        }
    }
    __syncthreads();

    int pixrow = h*128;
    if (ntile == 0) {
        for (int idx = tid; idx < 27*128; idx += 256) {
            int co = idx >> 7, p = idx & 127;
            float v = smem_f[p*129 + co] + g_bias640[co];
            if (co >= 18) v = 1.f/(1.f + __expf(-v));
            g_off[(b*27 + co)*HW + pixrow + p] = v;
        }
        for (int idx = tid; idx < 128*101; idx += 256) {
            int p = idx / 101, j = idx - p*101 + 27;
            float v = tanh_fast(smem_f[p*129 + j] + g_bias640[j]);
            g_coff[((size_t)(b*HW + pixrow + p))*576 + (j - 27)] = v;
        }
    } else {
        for (int idx = tid; idx < 128*128; idx += 256) {
            int p = idx >> 7, j = idx & 127;
            int co = co0 + j;
            if (co < 603) {
                float v = tanh_fast(smem_f[p*129 + j] + g_bias640[co]);
                g_coff[((size_t)(b*HW + pixrow + p))*576 + (co - 27)] = v;
            }
        }
    }
}

// ---------------- K3: deformable sampling + HMMA final conv ----------------
// grid 512 (b,h). CTA: 128 px x 64 oc, K=576 in 9 chunks of 64.
// dyn smem: [0,5120) tasks | [5120) Ah 16K | [21504) Al 16K | [37888) Wh 8K | [46080) Wl 8K = 54272
__global__ __launch_bounds__(256) void k3_mma(float* __restrict__ out)
{
    extern __shared__ __align__(16) char smem[];
    const int S_AH = 5120, S_AL = 21504, S_WH = 37888, S_WL = 46080;
    int*   s_cb = (int*)smem;             // [4][128]
    float* s_g  = (float*)(smem + 2048);  // [4][128]
    float* s_m  = (float*)(smem + 4096);  // [128]
    uint32_t sb = smem_u32(smem);
    int tid = threadIdx.x, wid = tid >> 5, lane = tid & 31;
    int b = blockIdx.x >> 7, h = blockIdx.x & 127;

    float acc[8][4];
#pragma unroll
    for (int i = 0; i < 8; i++)
#pragma unroll
        for (int q = 0; q < 4; q++) acc[i][q] = 0.f;

    int am_row = wid*16 + (lane & 7) + (((lane >> 3) & 1) << 3);
    int am_kof = (lane >> 4) << 3;
    int bn_row = (lane & 7) + ((lane >> 4) << 3);
    int bn_kof = ((lane >> 3) & 1) * 8;

    int px_g = tid >> 1, half = tid & 1;

    for (int n = 0; n < 9; n++) {
        // W fill (all threads)
        {
            const uint4* sWh = (const uint4*)(g_w2h + n*4096);
            const uint4* sWl = (const uint4*)(g_w2l + n*4096);
#pragma unroll
            for (int it = 0; it < 2; it++) {
                int i = it*256 + tid;
                int sw = SW128(i*16);
                *(uint4*)(smem + S_WH + sw) = sWh[i];
                *(uint4*)(smem + S_WL + sw) = sWl[i];
            }
        }
        // task params (tid < 128)
        if (tid < 128) {
            int px = tid;
            int pixidx = h*128 + px;
            float offr = g_off[(b*27 + n)*HW + pixidx];
            float offc = g_off[(b*27 + 9 + n)*HW + pixidx];
            float mv   = g_off[(b*27 + 18 + n)*HW + pixidx];
            float pr = (float)(h + 1 + n/3 - 1) + offr;
            float pc = (float)(px + 1 + n%3 - 1) + offc;
            float flr = floorf(pr), flc = floorf(pc);
            float ltr = fminf(fmaxf(flr,       0.f), 129.f);
            float ltc = fminf(fmaxf(flc,       0.f), 129.f);
            float rbr = fminf(fmaxf(flr + 1.f, 0.f), 129.f);
            float rbc = fminf(fmaxf(flc + 1.f, 0.f), 129.f);
            float prc = fminf(fmaxf(pr,        0.f), 129.f);
            float pcc = fminf(fmaxf(pc,        0.f), 129.f);
            s_g[0*128 + px] = (1.f + (ltr - prc))*(1.f + (ltc - pcc)); // lt
            s_g[1*128 + px] = (1.f - (rbr - prc))*(1.f - (rbc - pcc)); // rb
            s_g[2*128 + px] = (1.f + (ltr - prc))*(1.f - (rbc - pcc)); // lb
            s_g[3*128 + px] = (1.f - (rbr - prc))*(1.f + (ltc - pcc)); // rt
            int iltr = (int)ltr, iltc = (int)ltc, irbr = (int)rbr, irbc = (int)rbc;
            int bb = b*130;
            s_cb[0*128 + px] = ((bb + iltr)*130 + iltc)*16;
            s_cb[1*128 + px] = ((bb + irbr)*130 + irbc)*16;
            s_cb[2*128 + px] = ((bb + iltr)*130 + irbc)*16;
            s_cb[3*128 + px] = ((bb + irbr)*130 + iltc)*16;
            s_m[px] = mv;
        }
        __syncthreads();

        // gather + convert to bf16 hi/lo swizzled A tiles
        {
            const float4* xt4 = (const float4*)g_xt;
            int px = px_g;
            int c0 = s_cb[0*128 + px], c1 = s_cb[1*128 + px];
            int c2 = s_cb[2*128 + px], c3 = s_cb[3*128 + px];
            float g0 = s_g[0*128 + px], g1 = s_g[1*128 + px];
            float g2 = s_g[2*128 + px], g3 = s_g[3*128 + px];
            float mv = s_m[px];
            size_t coffbase = ((size_t)(b*HW + h*128 + px))*576 + n*64 + half*32;
#pragma unroll
            for (int jj = 0; jj < 4; jj++) {
                uint32_t hi[4], lo[4];
#pragma unroll
                for (int gg = 0; gg < 2; gg++) {
                    int cq = (half*32 + jj*8 + gg*4) >> 2;   // float4 idx in 16-wide row
                    float4 v0 = xt4[c0 + cq], v1 = xt4[c1 + cq];
                    float4 v2 = xt4[c2 + cq], v3 = xt4[c3 + cq];
                    float4 cf = *(const float4*)&g_coff[coffbase + jj*8 + gg*4];
                    float rx = (g0*v0.x + g1*v1.x + g2*v2.x + g3*v3.x + cf.x)*mv;
                    float ry = (g0*v0.y + g1*v1.y + g2*v2.y + g3*v3.y + cf.y)*mv;
                    float rz = (g0*v0.z + g1*v1.z + g2*v2.z + g3*v3.z + cf.z)*mv;
                    float rw = (g0*v0.w + g1*v1.w + g2*v2.w + g3*v3.w + cf.w)*mv;
                    hi[gg*2]   = pack_bf16_hi(rx, ry);
                    hi[gg*2+1] = pack_bf16_hi(rz, rw);
                    lo[gg*2]   = pack_bf16_lo(rx, ry);
                    lo[gg*2+1] = pack_bf16_lo(rz, rw);
                }
                int sw = SW128(px*128 + half*64 + jj*16);
                *(uint4*)(smem + S_AH + sw) = make_uint4(hi[0], hi[1], hi[2], hi[3]);
                *(uint4*)(smem + S_AL + sw) = make_uint4(lo[0], lo[1], lo[2], lo[3]);
            }
        }
        __syncthreads();

        // MMA: warp tile 16 px x 64 oc, K=64
#pragma unroll
        for (int kc = 0; kc < 4; kc++) {
            int kb = kc * 16;
            uint32_t aoff = SW128(am_row*128 + (kb + am_kof)*2);
            uint32_t ah[4], al[4];
            ldm_x4(ah, sb + S_AH + aoff);
            ldm_x4(al, sb + S_AL + aoff);
#pragma unroll
            for (int npair = 0; npair < 4; npair++) {
                uint32_t boff = SW128((bn_row + npair*16)*128 + (kb + bn_kof)*2);
                uint32_t bhf[4], blf[4];
                ldm_x4(bhf, sb + S_WH + boff);
                ldm_x4(blf, sb + S_WL + boff);
#pragma unroll
                for (int sub = 0; sub < 2; sub++) {
                    float* d = acc[npair*2 + sub];
                    mma16816(d, ah, bhf[sub*2], bhf[sub*2+1]);
                    mma16816(d, ah, blf[sub*2], blf[sub*2+1]);
                    mma16816(d, al, bhf[sub*2], bhf[sub*2+1]);
                }
            }
        }
        __syncthreads();
    }

    // ---------- epilogue: stage 128px x 64oc (pad 65), then coalesced out ----------
    float* stage = (float*)(smem + S_AH);
    {
        int r0 = wid*16 + (lane >> 2);
        int cc = (lane & 3)*2;
#pragma unroll
        for (int nsub = 0; nsub < 8; nsub++) {
            int col = nsub*8 + cc;
            stage[r0*65 + col]       = acc[nsub][0];
            stage[r0*65 + col + 1]   = acc[nsub][1];
            stage[(r0+8)*65 + col]   = acc[nsub][2];
            stage[(r0+8)*65 + col+1] = acc[nsub][3];
        }
    }
    __syncthreads();
#pragma unroll
    for (int it = 0; it < 8; it++) {
        int idx = it*256 + tid;
        int oc = idx >> 5, g = idx & 31;
        int px = g*4;
        float4 o;
        o.x = stage[px*65 + oc];
        o.y = stage[(px+1)*65 + oc];
        o.z = stage[(px+2)*65 + oc];
        o.w = stage[(px+3)*65 + oc];
        *(float4*)&out[(size_t)(b*64 + oc)*HW + h*128 + px] = o;
    }
}

// ---------------- launch ----------------
extern "C" void kernel_launch(void* const* d_in, const int* in_sizes, int n_in,
                              void* d_out, int out_size)
{
    const float* x      = (const float*)d_in[0];
    const float* ref    = (const float*)d_in[1];
    const float* w_cd   = (const float*)d_in[2];
    const float* b_cd   = (const float*)d_in[3];
    const float* w_p    = (const float*)d_in[4];
    const float* b_p    = (const float*)d_in[5];
    const float* w_m    = (const float*)d_in[6];
    const float* b_m    = (const float*)d_in[7];
    const float* w_c    = (const float*)d_in[8];
    const float* b_c    = (const float*)d_in[9];
    const float* w_conv = (const float*)d_in[10];
    float* out = (float*)d_out;

    cudaFuncSetAttribute(k2_mma, cudaFuncAttributeMaxDynamicSharedMemorySize, 66048);
    cudaFuncSetAttribute(k3_mma, cudaFuncAttributeMaxDynamicSharedMemorySize, 54272);

    prep_zero<<<(BB*130*130*64/8 + 255)/256, 256>>>();
    prep_pack<<<(9*640*64 + 255)/256, 256>>>(w_p, b_p, w_m, b_m, w_c, b_c, w_cd, w_conv);
    prep_xt<<<(BB*130*130*64 + 255)/256, 256>>>(x);
    k1_fused<<<512, 256>>>(x, ref, b_cd);
    k2_mma<<<dim3(5, 512), 256, 66048>>>();
    k3_mma<<<512, 256, 54272>>>(out);
}

// round 9
// speedup vs baseline: 2.4507x; 1.2628x over previous
#include <cuda_runtime.h>
#include <cuda_fp16.h>
#include <math.h>
#include <stdint.h>

#define HW 16384
#define BB 4

// ---------------- device scratch ----------------
__device__ __half g_fph[(size_t)BB*130*130*64];  // padded channel-last fused, hi
__device__ __half g_fpl[(size_t)BB*130*130*64];  // lo
__device__ float g_xt[BB*130*130*64];            // padded x, channel-last [b][r][cc][c]
__device__ float g_off[BB*27*HW];                // offset(18)+m(9) [b][ch][hw]
__device__ float g_coff[(size_t)BB*HW*9*64];     // tanh(c_off) [b][pix][n*64+c]
__device__ __half g_wbh[9*640*64];               // [kk][co'][ci] hi
__device__ float g_bias640[640];                 // co' order
__device__ float g_wcdT[128*64];                 // [ci][co]
__device__ __half g_w2h[9*64*64];                // [n][oc][c] final conv hi

#define SW128(o) ((o) ^ (((o) >> 3) & 0x70))

__device__ __forceinline__ uint32_t smem_u32(const void* p) {
    uint32_t a;
    asm("{ .reg .u64 t; cvta.to.shared.u64 t, %1; cvt.u32.u64 %0, t; }" : "=r"(a) : "l"(p));
    return a;
}
__device__ __forceinline__ void ldm_x4(uint32_t* r, uint32_t addr) {
    asm volatile("ldmatrix.sync.aligned.m8n8.x4.shared.b16 {%0,%1,%2,%3}, [%4];"
        : "=r"(r[0]), "=r"(r[1]), "=r"(r[2]), "=r"(r[3]) : "r"(addr));
}
__device__ __forceinline__ void mma16816(float* d, const uint32_t* a, uint32_t b0, uint32_t b1) {
    asm volatile("mma.sync.aligned.m16n8k16.row.col.f32.f16.f16.f32 "
        "{%0,%1,%2,%3}, {%4,%5,%6,%7}, {%8,%9}, {%0,%1,%2,%3};"
        : "+f"(d[0]), "+f"(d[1]), "+f"(d[2]), "+f"(d[3])
        : "r"(a[0]), "r"(a[1]), "r"(a[2]), "r"(a[3]), "r"(b0), "r"(b1));
}
__device__ __forceinline__ float tanh_fast(float v) {
    float e = __expf(2.f * v);
    return 1.f - 2.f / (e + 1.f);
}
__device__ __forceinline__ uint32_t pack_f16_hi(float a, float b) {
    return ((uint32_t)__half_as_ushort(__float2half_rn(b)) << 16)
         |  (uint32_t)__half_as_ushort(__float2half_rn(a));
}
__device__ __forceinline__ uint32_t pack_f16_lo(float a, float b) {
    __half ha = __float2half_rn(a), hb = __float2half_rn(b);
    float la = a - __half2float(ha), lb = b - __half2float(hb);
    return ((uint32_t)__half_as_ushort(__float2half_rn(lb)) << 16)
         |  (uint32_t)__half_as_ushort(__float2half_rn(la));
}

// ---------------- prep: zero only the 1-px border (interior overwritten by k1) ----------------
__global__ void prep_zero()
{
    int i = blockIdx.x * blockDim.x + threadIdx.x;
    const int n4 = (int)((size_t)BB*130*130*64/8);
    if (i >= n4) return;
    int t  = i >> 3;             // (b, r, cc)
    int cc = t % 130; t /= 130;
    int r  = t % 130;
    if (r == 0 || r == 129 || cc == 0 || cc == 129) {
        ((uint4*)g_fph)[i] = make_uint4(0,0,0,0);
        ((uint4*)g_fpl)[i] = make_uint4(0,0,0,0);
    }
}

// ---------------- prep: pack weights ----------------
__global__ void prep_pack(const float* __restrict__ wp, const float* __restrict__ bp,
                          const float* __restrict__ wm, const float* __restrict__ bm,
                          const float* __restrict__ wc, const float* __restrict__ bc,
                          const float* __restrict__ wcd, const float* __restrict__ wconv)
{
    int idx = blockIdx.x * blockDim.x + threadIdx.x;
    if (idx < 9*640*64) {
        int kk = idx / (640*64);
        int r  = idx - kk*640*64;
        int co = r >> 6, ci = r & 63;
        float v = 0.f;
        if      (co < 18)  v = wp[(co*64 + ci)*9 + kk];
        else if (co < 27)  v = wm[((co-18)*64 + ci)*9 + kk];
        else if (co < 603) { int t = co-27; int n = t >> 6, c = t & 63;
                             v = wc[((c*9 + n)*64 + ci)*9 + kk]; }
        g_wbh[idx] = __float2half_rn(v);
    }
    if (idx < 640) {
        float bv = 0.f;
        if      (idx < 18)  bv = bp[idx];
        else if (idx < 27)  bv = bm[idx-18];
        else if (idx < 603) { int t = idx-27; int n = t >> 6, c = t & 63; bv = bc[c*9 + n]; }
        g_bias640[idx] = bv;
    }
    if (idx < 128*64) {
        int ci = idx >> 6, co = idx & 63;
        g_wcdT[idx] = wcd[co*128 + ci];
    }
    if (idx < 9*64*64) {
        int n = idx >> 12, r = idx & 4095;
        int oc = r >> 6, c = r & 63;
        g_w2h[idx] = __float2half_rn(wconv[(oc*64 + c)*9 + n]);
    }
}

// ---------------- prep: padded channel-last x ----------------
__global__ void prep_xt(const float* __restrict__ x)
{
    int idx = blockIdx.x * blockDim.x + threadIdx.x;
    const int total = BB*130*130*64;
    if (idx >= total) return;
    int c  = idx & 63;
    int t  = idx >> 6;
    int cc = t % 130; t /= 130;
    int r  = t % 130;
    int b  = t / 130;
    float v = 0.f;
    if (r >= 1 && r <= 128 && cc >= 1 && cc <= 128)
        v = x[((b*64 + c)*128 + (r-1))*128 + (cc-1)];
    g_xt[idx] = v;
}

// ---------------- K1: 1x1 conv -> padded channel-last fp16 hi/lo ----------------
__global__ __launch_bounds__(256) void k1_fused(const float* __restrict__ x,
                                                const float* __restrict__ ref,
                                                const float* __restrict__ bcd)
{
    __shared__ float xin[32][128];
    __shared__ float wsm[32][64];
    int tid  = threadIdx.x;
    int b    = blockIdx.x >> 7;
    int seg  = blockIdx.x & 127;
    int pix0 = seg << 7;
    int ocg  = tid & 15, pixg = tid >> 4;

    float acc[4][8];
#pragma unroll
    for (int o = 0; o < 4; o++) {
        float bv = bcd[ocg*4 + o];
#pragma unroll
        for (int j = 0; j < 8; j++) acc[o][j] = bv;
    }

    for (int ci0 = 0; ci0 < 128; ci0 += 32) {
#pragma unroll
        for (int it = 0; it < 16; it++) {
            int idx = it*256 + tid;
            int ci  = idx >> 7, px = idx & 127;
            int gl  = ci0 + ci;
            float v = (gl < 64) ? x[(b*64 + gl)*HW + pix0 + px]
                                : ref[(b*64 + gl - 64)*HW + pix0 + px];
            xin[ci][px] = v;
        }
#pragma unroll
        for (int it = 0; it < 8; it++) {
            int idx = it*256 + tid;
            int ci = idx >> 6, oc = idx & 63;
            wsm[ci][oc] = g_wcdT[(ci0 + ci)*64 + oc];
        }
        __syncthreads();
#pragma unroll
        for (int ci = 0; ci < 32; ci++) {
            float4 wv = *(const float4*)&wsm[ci][ocg*4];
            float4 x0 = *(const float4*)&xin[ci][pixg*8];
            float4 x1 = *(const float4*)&xin[ci][pixg*8 + 4];
            float wvv[4] = {wv.x, wv.y, wv.z, wv.w};
            float xv[8]  = {x0.x, x0.y, x0.z, x0.w, x1.x, x1.y, x1.z, x1.w};
#pragma unroll
            for (int o = 0; o < 4; o++)
#pragma unroll
                for (int j = 0; j < 8; j++)
                    acc[o][j] += wvv[o]*xv[j];
        }
        __syncthreads();
    }
#pragma unroll
    for (int j = 0; j < 8; j++) {
        int ww = pixg*8 + j;
        size_t base = ((size_t)(b*130 + seg + 1)*130 + (ww + 1))*64 + ocg*4;
        *(uint32_t*)&g_fph[base]     = pack_f16_hi(acc[0][j], acc[1][j]);
        *(uint32_t*)&g_fph[base + 2] = pack_f16_hi(acc[2][j], acc[3][j]);
        *(uint32_t*)&g_fpl[base]     = pack_f16_lo(acc[0][j], acc[1][j]);
        *(uint32_t*)&g_fpl[base + 2] = pack_f16_lo(acc[2][j], acc[3][j]);
    }
}

// ---------------- K2: HMMA implicit GEMM conv 64->603(640), 2-product fp16 split ----------------
// smem mainloop: [0)Ah 16K [16K)Al 16K [32K)Wh 16K ; epilogue reuses as 128x129 f32
__global__ __launch_bounds__(256, 2) void k2_mma()
{
    extern __shared__ __align__(16) char smem[];
    float* smem_f = (float*)smem;
    uint32_t sb = smem_u32(smem);
    int tid = threadIdx.x, wid = tid >> 5, lane = tid & 31;
    int ntile = blockIdx.x;               // 0..4 -> co' base = ntile*128
    int mt    = blockIdx.y;
    int b = mt >> 7, h = mt & 127;
    int co0 = ntile * 128;
    int warp_m = wid >> 2, warp_n = wid & 3;

    float acc[4][4][4];
#pragma unroll
    for (int i = 0; i < 4; i++)
#pragma unroll
        for (int j = 0; j < 4; j++)
#pragma unroll
            for (int q = 0; q < 4; q++) acc[i][j][q] = 0.f;

    int bn_row = warp_n*32 + (lane & 7) + ((lane >> 4) << 3);
    int bn_kof = ((lane >> 3) & 1) * 8;
    int am_row = warp_m*64 + (lane & 7) + (((lane >> 3) & 1) << 3);
    int am_kof = (lane >> 4) << 3;

    for (int it9 = 0; it9 < 9; it9++) {
        int kh = it9 / 3, kw = it9 - kh*3;
        {
            size_t rowbase = ((size_t)(b*130 + h + kh)*130 + kw) * 64;
            const uint4* sAh = (const uint4*)(g_fph + rowbase);
            const uint4* sAl = (const uint4*)(g_fpl + rowbase);
            const uint4* sWh = (const uint4*)(g_wbh + ((size_t)(it9*640 + co0)) * 64);
#pragma unroll
            for (int it = 0; it < 4; it++) {
                int i = it*256 + tid;
                int sw = SW128(i * 16);
                *(uint4*)(smem + sw)         = sAh[i];
                *(uint4*)(smem + 16384 + sw) = sAl[i];
                *(uint4*)(smem + 32768 + sw) = sWh[i];
            }
        }
        __syncthreads();

#pragma unroll
        for (int kc = 0; kc < 4; kc++) {
            int kb = kc * 16;
            uint32_t bh[8];
#pragma unroll
            for (int npair = 0; npair < 2; npair++) {
                uint32_t off = SW128((bn_row + npair*16)*128 + (kb + bn_kof)*2);
                ldm_x4(&bh[npair*4], sb + 32768 + off);
            }
#pragma unroll
            for (int msub = 0; msub < 4; msub++) {
                uint32_t aoff = SW128((am_row + msub*16)*128 + (kb + am_kof)*2);
                uint32_t a[4];
                ldm_x4(a, sb + aoff);                 // Ah
#pragma unroll
                for (int nsub = 0; nsub < 4; nsub++) {
                    int bi = (nsub >> 1)*4 + (nsub & 1)*2;
                    mma16816(acc[msub][nsub], a, bh[bi], bh[bi+1]);
                }
                ldm_x4(a, sb + 16384 + aoff);         // Al
#pragma unroll
                for (int nsub = 0; nsub < 4; nsub++) {
                    int bi = (nsub >> 1)*4 + (nsub & 1)*2;
                    mma16816(acc[msub][nsub], a, bh[bi], bh[bi+1]);
                }
            }
        }
        __syncthreads();
    }

#pragma unroll
    for (int msub = 0; msub < 4; msub++) {
#pragma unroll
        for (int nsub = 0; nsub < 4; nsub++) {
            int m  = warp_m*64 + msub*16 + (lane >> 2);
            int cl = warp_n*32 + nsub*8 + (lane & 3)*2;
            smem_f[m*129 + cl]       = acc[msub][nsub][0];
            smem_f[m*129 + cl + 1]   = acc[msub][nsub][1];
            smem_f[(m+8)*129 + cl]   = acc[msub][nsub][2];
            smem_f[(m+8)*129 + cl+1] = acc[msub][nsub][3];
        }
    }
    __syncthreads();

    int pixrow = h*128;
    if (ntile == 0) {
        for (int idx = tid; idx < 27*128; idx += 256) {
            int co = idx >> 7, p = idx & 127;
            float v = smem_f[p*129 + co] + g_bias640[co];
            if (co >= 18) v = 1.f/(1.f + __expf(-v));
            g_off[(b*27 + co)*HW + pixrow + p] = v;
        }
        for (int idx = tid; idx < 128*101; idx += 256) {
            int p = idx / 101, j = idx - p*101 + 27;
            float v = tanh_fast(smem_f[p*129 + j] + g_bias640[j]);
            g_coff[((size_t)(b*HW + pixrow + p))*576 + (j - 27)] = v;
        }
    } else {
        for (int idx = tid; idx < 128*128; idx += 256) {
            int p = idx >> 7, j = idx & 127;
            int co = co0 + j;
            if (co < 603) {
                float v = tanh_fast(smem_f[p*129 + j] + g_bias640[co]);
                g_coff[((size_t)(b*HW + pixrow + p))*576 + (co - 27)] = v;
            }
        }
    }
}

// ---------------- K3: deformable sampling + HMMA final conv (2-product fp16) ----------------
// dyn smem: [0,5120) tasks | [5120) Ah 16K | [21504) Al 16K | [37888) Wh 8K = 46080
__global__ __launch_bounds__(256) void k3_mma(float* __restrict__ out)
{
    extern __shared__ __align__(16) char smem[];
    const int S_AH = 5120, S_AL = 21504, S_WH = 37888;
    int*   s_cb = (int*)smem;             // [4][128]
    float* s_g  = (float*)(smem + 2048);  // [4][128]
    float* s_m  = (float*)(smem + 4096);  // [128]
    uint32_t sb = smem_u32(smem);
    int tid = threadIdx.x, wid = tid >> 5, lane = tid & 31;
    int b = blockIdx.x >> 7, h = blockIdx.x & 127;

    float acc[8][4];
#pragma unroll
    for (int i = 0; i < 8; i++)
#pragma unroll
        for (int q = 0; q < 4; q++) acc[i][q] = 0.f;

    int am_row = wid*16 + (lane & 7) + (((lane >> 3) & 1) << 3);
    int am_kof = (lane >> 4) << 3;
    int bn_row = (lane & 7) + ((lane >> 4) << 3);
    int bn_kof = ((lane >> 3) & 1) * 8;

    int px_g = tid >> 1, half = tid & 1;

    for (int n = 0; n < 9; n++) {
        {
            const uint4* sWh = (const uint4*)(g_w2h + n*4096);
#pragma unroll
            for (int it = 0; it < 2; it++) {
                int i = it*256 + tid;
                int sw = SW128(i*16);
                *(uint4*)(smem + S_WH + sw) = sWh[i];
            }
        }
        if (tid < 128) {
            int px = tid;
            int pixidx = h*128 + px;
            float offr = g_off[(b*27 + n)*HW + pixidx];
            float offc = g_off[(b*27 + 9 + n)*HW + pixidx];
            float mv   = g_off[(b*27 + 18 + n)*HW + pixidx];
            float pr = (float)(h + 1 + n/3 - 1) + offr;
            float pc = (float)(px + 1 + n%3 - 1) + offc;
            float flr = floorf(pr), flc = floorf(pc);
            float ltr = fminf(fmaxf(flr,       0.f), 129.f);
            float ltc = fminf(fmaxf(flc,       0.f), 129.f);
            float rbr = fminf(fmaxf(flr + 1.f, 0.f), 129.f);
            float rbc = fminf(fmaxf(flc + 1.f, 0.f), 129.f);
            float prc = fminf(fmaxf(pr,        0.f), 129.f);
            float pcc = fminf(fmaxf(pc,        0.f), 129.f);
            s_g[0*128 + px] = (1.f + (ltr - prc))*(1.f + (ltc - pcc)); // lt
            s_g[1*128 + px] = (1.f - (rbr - prc))*(1.f - (rbc - pcc)); // rb
            s_g[2*128 + px] = (1.f + (ltr - prc))*(1.f - (rbc - pcc)); // lb
            s_g[3*128 + px] = (1.f - (rbr - prc))*(1.f + (ltc - pcc)); // rt
            int iltr = (int)ltr, iltc = (int)ltc, irbr = (int)rbr, irbc = (int)rbc;
            int bb = b*130;
            s_cb[0*128 + px] = ((bb + iltr)*130 + iltc)*16;
            s_cb[1*128 + px] = ((bb + irbr)*130 + irbc)*16;
            s_cb[2*128 + px] = ((bb + iltr)*130 + irbc)*16;
            s_cb[3*128 + px] = ((bb + irbr)*130 + iltc)*16;
            s_m[px] = mv;
        }
        __syncthreads();

        // gather + convert to fp16 hi/lo swizzled A tiles
        {
            const float4* xt4 = (const float4*)g_xt;
            int px = px_g;
            int c0 = s_cb[0*128 + px], c1 = s_cb[1*128 + px];
            int c2 = s_cb[2*128 + px], c3 = s_cb[3*128 + px];
            float g0 = s_g[0*128 + px], g1 = s_g[1*128 + px];
            float g2 = s_g[2*128 + px], g3 = s_g[3*128 + px];
            float mv = s_m[px];
            size_t coffbase = ((size_t)(b*HW + h*128 + px))*576 + n*64 + half*32;
#pragma unroll
            for (int jj = 0; jj < 4; jj++) {
                uint32_t hi[4], lo[4];
#pragma unroll
                for (int gg = 0; gg < 2; gg++) {
                    int cq = (half*32 + jj*8 + gg*4) >> 2;
                    float4 v0 = xt4[c0 + cq], v1 = xt4[c1 + cq];
                    float4 v2 = xt4[c2 + cq], v3 = xt4[c3 + cq];
                    float4 cf = *(const float4*)&g_coff[coffbase + jj*8 + gg*4];
                    float rx = (g0*v0.x + g1*v1.x + g2*v2.x + g3*v3.x + cf.x)*mv;
                    float ry = (g0*v0.y + g1*v1.y + g2*v2.y + g3*v3.y + cf.y)*mv;
                    float rz = (g0*v0.z + g1*v1.z + g2*v2.z + g3*v3.z + cf.z)*mv;
                    float rw = (g0*v0.w + g1*v1.w + g2*v2.w + g3*v3.w + cf.w)*mv;
                    hi[gg*2]   = pack_f16_hi(rx, ry);
                    hi[gg*2+1] = pack_f16_hi(rz, rw);
                    lo[gg*2]   = pack_f16_lo(rx, ry);
                    lo[gg*2+1] = pack_f16_lo(rz, rw);
                }
                int sw = SW128(px*128 + half*64 + jj*16);
                *(uint4*)(smem + S_AH + sw) = make_uint4(hi[0], hi[1], hi[2], hi[3]);
                *(uint4*)(smem + S_AL + sw) = make_uint4(lo[0], lo[1], lo[2], lo[3]);
            }
        }
        __syncthreads();

        // MMA: warp tile 16 px x 64 oc, K=64
#pragma unroll
        for (int kc = 0; kc < 4; kc++) {
            int kb = kc * 16;
            uint32_t aoff = SW128(am_row*128 + (kb + am_kof)*2);
            uint32_t ah[4], al[4];
            ldm_x4(ah, sb + S_AH + aoff);
            ldm_x4(al, sb + S_AL + aoff);
#pragma unroll
            for (int npair = 0; npair < 4; npair++) {
                uint32_t boff = SW128((bn_row + npair*16)*128 + (kb + bn_kof)*2);
                uint32_t bhf[4];
                ldm_x4(bhf, sb + S_WH + boff);
#pragma unroll
                for (int sub = 0; sub < 2; sub++) {
                    float* d = acc[npair*2 + sub];
                    mma16816(d, ah, bhf[sub*2], bhf[sub*2+1]);
                    mma16816(d, al, bhf[sub*2], bhf[sub*2+1]);
                }
            }
        }
        __syncthreads();
    }

    // ---------- epilogue: stage 128px x 64oc (pad 65), then coalesced out ----------
    float* stage = (float*)(smem + S_AH);
    {
        int r0 = wid*16 + (lane >> 2);
        int cc = (lane & 3)*2;
#pragma unroll
        for (int nsub = 0; nsub < 8; nsub++) {
            int col = nsub*8 + cc;
            stage[r0*65 + col]       = acc[nsub][0];
            stage[r0*65 + col + 1]   = acc[nsub][1];
            stage[(r0+8)*65 + col]   = acc[nsub][2];
            stage[(r0+8)*65 + col+1] = acc[nsub][3];
        }
    }
    __syncthreads();
#pragma unroll
    for (int it = 0; it < 8; it++) {
        int idx = it*256 + tid;
        int oc = idx >> 5, g = idx & 31;
        int px = g*4;
        float4 o;
        o.x = stage[px*65 + oc];
        o.y = stage[(px+1)*65 + oc];
        o.z = stage[(px+2)*65 + oc];
        o.w = stage[(px+3)*65 + oc];
        *(float4*)&out[(size_t)(b*64 + oc)*HW + h*128 + px] = o;
    }
}

// ---------------- launch ----------------
extern "C" void kernel_launch(void* const* d_in, const int* in_sizes, int n_in,
                              void* d_out, int out_size)
{
    const float* x      = (const float*)d_in[0];
    const float* ref    = (const float*)d_in[1];
    const float* w_cd   = (const float*)d_in[2];
    const float* b_cd   = (const float*)d_in[3];
    const float* w_p    = (const float*)d_in[4];
    const float* b_p    = (const float*)d_in[5];
    const float* w_m    = (const float*)d_in[6];
    const float* b_m    = (const float*)d_in[7];
    const float* w_c    = (const float*)d_in[8];
    const float* b_c    = (const float*)d_in[9];
    const float* w_conv = (const float*)d_in[10];
    float* out = (float*)d_out;

    cudaFuncSetAttribute(k2_mma, cudaFuncAttributeMaxDynamicSharedMemorySize, 66048);
    cudaFuncSetAttribute(k3_mma, cudaFuncAttributeMaxDynamicSharedMemorySize, 46080);

    prep_zero<<<(BB*130*130*64/8 + 255)/256, 256>>>();
    prep_pack<<<(9*640*64 + 255)/256, 256>>>(w_p, b_p, w_m, b_m, w_c, b_c, w_cd, w_conv);
    prep_xt<<<(BB*130*130*64 + 255)/256, 256>>>(x);
    k1_fused<<<512, 256>>>(x, ref, b_cd);
    k2_mma<<<dim3(5, 512), 256, 66048>>>();
    k3_mma<<<512, 256, 46080>>>(out);
}

// round 10
// speedup vs baseline: 2.6590x; 1.0850x over previous
#include <cuda_runtime.h>
#include <cuda_fp16.h>
#include <math.h>
#include <stdint.h>

#define HW 16384
#define BB 4

// ---------------- device scratch ----------------
__device__ __half g_fph[(size_t)BB*130*130*64];  // padded channel-last fused, hi
__device__ __half g_fpl[(size_t)BB*130*130*64];  // lo
__device__ float g_xt[BB*130*130*64];            // padded x, channel-last [b][r][cc][c]
__device__ float g_off[BB*27*HW];                // offset(18)+m(9) [b][ch][hw]
__device__ float g_coff[(size_t)BB*HW*9*64];     // tanh(c_off) [b][pix][n*64+c]
__device__ __half g_wbh[9*640*64];               // [kk][co'][ci] hi
__device__ float g_bias640[640];                 // co' order
__device__ float g_wcdT[128*64];                 // [ci][co]
__device__ __half g_w2h[9*64*64];                // [n][oc][c] final conv hi

#define SW128(o) ((o) ^ (((o) >> 3) & 0x70))

__device__ __forceinline__ uint32_t smem_u32(const void* p) {
    uint32_t a;
    asm("{ .reg .u64 t; cvta.to.shared.u64 t, %1; cvt.u32.u64 %0, t; }" : "=r"(a) : "l"(p));
    return a;
}
__device__ __forceinline__ void ldm_x4(uint32_t* r, uint32_t addr) {
    asm volatile("ldmatrix.sync.aligned.m8n8.x4.shared.b16 {%0,%1,%2,%3}, [%4];"
        : "=r"(r[0]), "=r"(r[1]), "=r"(r[2]), "=r"(r[3]) : "r"(addr));
}
__device__ __forceinline__ void mma16816(float* d, const uint32_t* a, uint32_t b0, uint32_t b1) {
    asm volatile("mma.sync.aligned.m16n8k16.row.col.f32.f16.f16.f32 "
        "{%0,%1,%2,%3}, {%4,%5,%6,%7}, {%8,%9}, {%0,%1,%2,%3};"
        : "+f"(d[0]), "+f"(d[1]), "+f"(d[2]), "+f"(d[3])
        : "r"(a[0]), "r"(a[1]), "r"(a[2]), "r"(a[3]), "r"(b0), "r"(b1));
}
__device__ __forceinline__ void cp16(uint32_t dst, const void* src) {
    asm volatile("cp.async.cg.shared.global [%0], [%1], 16;" :: "r"(dst), "l"(src));
}
__device__ __forceinline__ void cp_commit() { asm volatile("cp.async.commit_group;" ::: "memory"); }
template<int N> __device__ __forceinline__ void cp_wait() {
    asm volatile("cp.async.wait_group %0;" :: "n"(N) : "memory");
}
__device__ __forceinline__ float tanh_fast(float v) {
    float e = __expf(2.f * v);
    return 1.f - 2.f / (e + 1.f);
}
__device__ __forceinline__ uint32_t pack_f16_hi(float a, float b) {
    return ((uint32_t)__half_as_ushort(__float2half_rn(b)) << 16)
         |  (uint32_t)__half_as_ushort(__float2half_rn(a));
}
__device__ __forceinline__ uint32_t pack_f16_lo(float a, float b) {
    __half ha = __float2half_rn(a), hb = __float2half_rn(b);
    float la = a - __half2float(ha), lb = b - __half2float(hb);
    return ((uint32_t)__half_as_ushort(__float2half_rn(lb)) << 16)
         |  (uint32_t)__half_as_ushort(__float2half_rn(la));
}

// ---------------- prep: zero only the 1-px border ----------------
__global__ void prep_zero()
{
    int i = blockIdx.x * blockDim.x + threadIdx.x;
    const int n4 = (int)((size_t)BB*130*130*64/8);
    if (i >= n4) return;
    int t  = i >> 3;
    int cc = t % 130; t /= 130;
    int r  = t % 130;
    if (r == 0 || r == 129 || cc == 0 || cc == 129) {
        ((uint4*)g_fph)[i] = make_uint4(0,0,0,0);
        ((uint4*)g_fpl)[i] = make_uint4(0,0,0,0);
    }
}

// ---------------- prep: pack weights ----------------
__global__ void prep_pack(const float* __restrict__ wp, const float* __restrict__ bp,
                          const float* __restrict__ wm, const float* __restrict__ bm,
                          const float* __restrict__ wc, const float* __restrict__ bc,
                          const float* __restrict__ wcd, const float* __restrict__ wconv)
{
    int idx = blockIdx.x * blockDim.x + threadIdx.x;
    if (idx < 9*640*64) {
        int kk = idx / (640*64);
        int r  = idx - kk*640*64;
        int co = r >> 6, ci = r & 63;
        float v = 0.f;
        if      (co < 18)  v = wp[(co*64 + ci)*9 + kk];
        else if (co < 27)  v = wm[((co-18)*64 + ci)*9 + kk];
        else if (co < 603) { int t = co-27; int n = t >> 6, c = t & 63;
                             v = wc[((c*9 + n)*64 + ci)*9 + kk]; }
        g_wbh[idx] = __float2half_rn(v);
    }
    if (idx < 640) {
        float bv = 0.f;
        if      (idx < 18)  bv = bp[idx];
        else if (idx < 27)  bv = bm[idx-18];
        else if (idx < 603) { int t = idx-27; int n = t >> 6, c = t & 63; bv = bc[c*9 + n]; }
        g_bias640[idx] = bv;
    }
    if (idx < 128*64) {
        int ci = idx >> 6, co = idx & 63;
        g_wcdT[idx] = wcd[co*128 + ci];
    }
    if (idx < 9*64*64) {
        int n = idx >> 12, r = idx & 4095;
        int oc = r >> 6, c = r & 63;
        g_w2h[idx] = __float2half_rn(wconv[(oc*64 + c)*9 + n]);
    }
}

// ---------------- prep: padded channel-last x ----------------
__global__ void prep_xt(const float* __restrict__ x)
{
    int idx = blockIdx.x * blockDim.x + threadIdx.x;
    const int total = BB*130*130*64;
    if (idx >= total) return;
    int c  = idx & 63;
    int t  = idx >> 6;
    int cc = t % 130; t /= 130;
    int r  = t % 130;
    int b  = t / 130;
    float v = 0.f;
    if (r >= 1 && r <= 128 && cc >= 1 && cc <= 128)
        v = x[((b*64 + c)*128 + (r-1))*128 + (cc-1)];
    g_xt[idx] = v;
}

// ---------------- K1: 1x1 conv -> padded channel-last fp16 hi/lo ----------------
__global__ __launch_bounds__(256) void k1_fused(const float* __restrict__ x,
                                                const float* __restrict__ ref,
                                                const float* __restrict__ bcd)
{
    __shared__ float xin[32][128];
    __shared__ float wsm[32][64];
    int tid  = threadIdx.x;
    int b    = blockIdx.x >> 7;
    int seg  = blockIdx.x & 127;
    int pix0 = seg << 7;
    int ocg  = tid & 15, pixg = tid >> 4;

    float acc[4][8];
#pragma unroll
    for (int o = 0; o < 4; o++) {
        float bv = bcd[ocg*4 + o];
#pragma unroll
        for (int j = 0; j < 8; j++) acc[o][j] = bv;
    }

    for (int ci0 = 0; ci0 < 128; ci0 += 32) {
#pragma unroll
        for (int it = 0; it < 16; it++) {
            int idx = it*256 + tid;
            int ci  = idx >> 7, px = idx & 127;
            int gl  = ci0 + ci;
            float v = (gl < 64) ? x[(b*64 + gl)*HW + pix0 + px]
                                : ref[(b*64 + gl - 64)*HW + pix0 + px];
            xin[ci][px] = v;
        }
#pragma unroll
        for (int it = 0; it < 8; it++) {
            int idx = it*256 + tid;
            int ci = idx >> 6, oc = idx & 63;
            wsm[ci][oc] = g_wcdT[(ci0 + ci)*64 + oc];
        }
        __syncthreads();
#pragma unroll
        for (int ci = 0; ci < 32; ci++) {
            float4 wv = *(const float4*)&wsm[ci][ocg*4];
            float4 x0 = *(const float4*)&xin[ci][pixg*8];
            float4 x1 = *(const float4*)&xin[ci][pixg*8 + 4];
            float wvv[4] = {wv.x, wv.y, wv.z, wv.w};
            float xv[8]  = {x0.x, x0.y, x0.z, x0.w, x1.x, x1.y, x1.z, x1.w};
#pragma unroll
            for (int o = 0; o < 4; o++)
#pragma unroll
                for (int j = 0; j < 8; j++)
                    acc[o][j] += wvv[o]*xv[j];
        }
        __syncthreads();
    }
#pragma unroll
    for (int j = 0; j < 8; j++) {
        int ww = pixg*8 + j;
        size_t base = ((size_t)(b*130 + seg + 1)*130 + (ww + 1))*64 + ocg*4;
        *(uint32_t*)&g_fph[base]     = pack_f16_hi(acc[0][j], acc[1][j]);
        *(uint32_t*)&g_fph[base + 2] = pack_f16_hi(acc[2][j], acc[3][j]);
        *(uint32_t*)&g_fpl[base]     = pack_f16_lo(acc[0][j], acc[1][j]);
        *(uint32_t*)&g_fpl[base + 2] = pack_f16_lo(acc[2][j], acc[3][j]);
    }
}

// ---------------- K2: HMMA implicit GEMM conv, cp.async double-buffered ----------------
// dyn smem: 2 stages x 48KB (Ah 16K | Al 16K | Wh 16K) = 98304; epilogue reuses [0,66048)
__global__ __launch_bounds__(256, 2) void k2_mma()
{
    extern __shared__ __align__(16) char smem[];
    float* smem_f = (float*)smem;
    uint32_t sb = smem_u32(smem);
    int tid = threadIdx.x, wid = tid >> 5, lane = tid & 31;
    int ntile = blockIdx.x;
    int mt    = blockIdx.y;
    int b = mt >> 7, h = mt & 127;
    int co0 = ntile * 128;
    int warp_m = wid >> 2, warp_n = wid & 3;
    const int STG = 49152;

    float acc[4][4][4];
#pragma unroll
    for (int i = 0; i < 4; i++)
#pragma unroll
        for (int j = 0; j < 4; j++)
#pragma unroll
            for (int q = 0; q < 4; q++) acc[i][j][q] = 0.f;

    int bn_row = warp_n*32 + (lane & 7) + ((lane >> 4) << 3);
    int bn_kof = ((lane >> 3) & 1) * 8;
    int am_row = warp_m*64 + (lane & 7) + (((lane >> 3) & 1) << 3);
    int am_kof = (lane >> 4) << 3;

    // stage fill via cp.async: 12 x 16B per thread
    auto issue_fill = [&](int it9, int stg) {
        int kh = it9 / 3, kw = it9 - kh*3;
        size_t rowbase = ((size_t)(b*130 + h + kh)*130 + kw) * 64;
        const uint4* sAh = (const uint4*)(g_fph + rowbase);
        const uint4* sAl = (const uint4*)(g_fpl + rowbase);
        const uint4* sWh = (const uint4*)(g_wbh + ((size_t)(it9*640 + co0)) * 64);
        uint32_t base = sb + stg*STG;
#pragma unroll
        for (int it = 0; it < 4; it++) {
            int i = it*256 + tid;
            uint32_t sw = SW128(i * 16);
            cp16(base + sw,         sAh + i);
            cp16(base + 16384 + sw, sAl + i);
            cp16(base + 32768 + sw, sWh + i);
        }
        cp_commit();
    };

    issue_fill(0, 0);
    for (int it9 = 0; it9 < 9; it9++) {
        if (it9 < 8) { issue_fill(it9 + 1, (it9 + 1) & 1); cp_wait<1>(); }
        else         { cp_wait<0>(); }
        __syncthreads();

        uint32_t bbase = sb + (it9 & 1)*STG;
#pragma unroll
        for (int kc = 0; kc < 4; kc++) {
            int kb = kc * 16;
            uint32_t bh[8];
#pragma unroll
            for (int npair = 0; npair < 2; npair++) {
                uint32_t off = SW128((bn_row + npair*16)*128 + (kb + bn_kof)*2);
                ldm_x4(&bh[npair*4], bbase + 32768 + off);
            }
#pragma unroll
            for (int msub = 0; msub < 4; msub++) {
                uint32_t aoff = SW128((am_row + msub*16)*128 + (kb + am_kof)*2);
                uint32_t a[4];
                ldm_x4(a, bbase + aoff);                 // Ah
#pragma unroll
                for (int nsub = 0; nsub < 4; nsub++) {
                    int bi = (nsub >> 1)*4 + (nsub & 1)*2;
                    mma16816(acc[msub][nsub], a, bh[bi], bh[bi+1]);
                }
                ldm_x4(a, bbase + 16384 + aoff);         // Al
#pragma unroll
                for (int nsub = 0; nsub < 4; nsub++) {
                    int bi = (nsub >> 1)*4 + (nsub & 1)*2;
                    mma16816(acc[msub][nsub], a, bh[bi], bh[bi+1]);
                }
            }
        }
        __syncthreads();
    }

#pragma unroll
    for (int msub = 0; msub < 4; msub++) {
#pragma unroll
        for (int nsub = 0; nsub < 4; nsub++) {
            int m  = warp_m*64 + msub*16 + (lane >> 2);
            int cl = warp_n*32 + nsub*8 + (lane & 3)*2;
            smem_f[m*129 + cl]       = acc[msub][nsub][0];
            smem_f[m*129 + cl + 1]   = acc[msub][nsub][1];
            smem_f[(m+8)*129 + cl]   = acc[msub][nsub][2];
            smem_f[(m+8)*129 + cl+1] = acc[msub][nsub][3];
        }
    }
    __syncthreads();

    int pixrow = h*128;
    if (ntile == 0) {
        for (int idx = tid; idx < 27*128; idx += 256) {
            int co = idx >> 7, p = idx & 127;
            float v = smem_f[p*129 + co] + g_bias640[co];
            if (co >= 18) v = 1.f/(1.f + __expf(-v));
            g_off[(b*27 + co)*HW + pixrow + p] = v;
        }
        for (int idx = tid; idx < 128*101; idx += 256) {
            int p = idx / 101, j = idx - p*101 + 27;
            float v = tanh_fast(smem_f[p*129 + j] + g_bias640[j]);
            g_coff[((size_t)(b*HW + pixrow + p))*576 + (j - 27)] = v;
        }
    } else {
        for (int idx = tid; idx < 128*128; idx += 256) {
            int p = idx >> 7, j = idx & 127;
            int co = co0 + j;
            if (co < 603) {
                float v = tanh_fast(smem_f[p*129 + j] + g_bias640[co]);
                g_coff[((size_t)(b*HW + pixrow + p))*576 + (co - 27)] = v;
            }
        }
    }
}

// ---------------- K3: deformable sampling + HMMA final conv ----------------
// dyn smem: [0,5120) tasks | [5120) Ah 16K | [21504) Al 16K | [37888) Wh 8K = 46080
__global__ __launch_bounds__(256) void k3_mma(float* __restrict__ out)
{
    extern __shared__ __align__(16) char smem[];
    const int S_AH = 5120, S_AL = 21504, S_WH = 37888;
    int*   s_cb = (int*)smem;
    float* s_g  = (float*)(smem + 2048);
    float* s_m  = (float*)(smem + 4096);
    uint32_t sb = smem_u32(smem);
    int tid = threadIdx.x, wid = tid >> 5, lane = tid & 31;
    int b = blockIdx.x >> 7, h = blockIdx.x & 127;

    float acc[8][4];
#pragma unroll
    for (int i = 0; i < 8; i++)
#pragma unroll
        for (int q = 0; q < 4; q++) acc[i][q] = 0.f;

    int am_row = wid*16 + (lane & 7) + (((lane >> 3) & 1) << 3);
    int am_kof = (lane >> 4) << 3;
    int bn_row = (lane & 7) + ((lane >> 4) << 3);
    int bn_kof = ((lane >> 3) & 1) * 8;

    int px_g = tid >> 1, half = tid & 1;

    for (int n = 0; n < 9; n++) {
        // W fill via cp.async — overlaps with params + gather, waited before MMA
        {
            const uint4* sWh = (const uint4*)(g_w2h + n*4096);
#pragma unroll
            for (int it = 0; it < 2; it++) {
                int i = it*256 + tid;
                uint32_t sw = SW128(i*16);
                cp16(sb + S_WH + sw, sWh + i);
            }
            cp_commit();
        }
        if (tid < 128) {
            int px = tid;
            int pixidx = h*128 + px;
            float offr = g_off[(b*27 + n)*HW + pixidx];
            float offc = g_off[(b*27 + 9 + n)*HW + pixidx];
            float mv   = g_off[(b*27 + 18 + n)*HW + pixidx];
            float pr = (float)(h + 1 + n/3 - 1) + offr;
            float pc = (float)(px + 1 + n%3 - 1) + offc;
            float flr = floorf(pr), flc = floorf(pc);
            float ltr = fminf(fmaxf(flr,       0.f), 129.f);
            float ltc = fminf(fmaxf(flc,       0.f), 129.f);
            float rbr = fminf(fmaxf(flr + 1.f, 0.f), 129.f);
            float rbc = fminf(fmaxf(flc + 1.f, 0.f), 129.f);
            float prc = fminf(fmaxf(pr,        0.f), 129.f);
            float pcc = fminf(fmaxf(pc,        0.f), 129.f);
            s_g[0*128 + px] = (1.f + (ltr - prc))*(1.f + (ltc - pcc)); // lt
            s_g[1*128 + px] = (1.f - (rbr - prc))*(1.f - (rbc - pcc)); // rb
            s_g[2*128 + px] = (1.f + (ltr - prc))*(1.f - (rbc - pcc)); // lb
            s_g[3*128 + px] = (1.f - (rbr - prc))*(1.f + (ltc - pcc)); // rt
            int iltr = (int)ltr, iltc = (int)ltc, irbr = (int)rbr, irbc = (int)rbc;
            int bb = b*130;
            s_cb[0*128 + px] = ((bb + iltr)*130 + iltc)*16;
            s_cb[1*128 + px] = ((bb + irbr)*130 + irbc)*16;
            s_cb[2*128 + px] = ((bb + iltr)*130 + irbc)*16;
            s_cb[3*128 + px] = ((bb + irbr)*130 + iltc)*16;
            s_m[px] = mv;
        }
        __syncthreads();

        // gather + convert to fp16 hi/lo swizzled A tiles
        {
            const float4* xt4 = (const float4*)g_xt;
            int px = px_g;
            int c0 = s_cb[0*128 + px], c1 = s_cb[1*128 + px];
            int c2 = s_cb[2*128 + px], c3 = s_cb[3*128 + px];
            float g0 = s_g[0*128 + px], g1 = s_g[1*128 + px];
            float g2 = s_g[2*128 + px], g3 = s_g[3*128 + px];
            float mv = s_m[px];
            size_t coffbase = ((size_t)(b*HW + h*128 + px))*576 + n*64 + half*32;
#pragma unroll
            for (int jj = 0; jj < 4; jj++) {
                uint32_t hi[4], lo[4];
#pragma unroll
                for (int gg = 0; gg < 2; gg++) {
                    int cq = (half*32 + jj*8 + gg*4) >> 2;
                    float4 v0 = xt4[c0 + cq], v1 = xt4[c1 + cq];
                    float4 v2 = xt4[c2 + cq], v3 = xt4[c3 + cq];
                    float4 cf = *(const float4*)&g_coff[coffbase + jj*8 + gg*4];
                    float rx = (g0*v0.x + g1*v1.x + g2*v2.x + g3*v3.x + cf.x)*mv;
                    float ry = (g0*v0.y + g1*v1.y + g2*v2.y + g3*v3.y + cf.y)*mv;
                    float rz = (g0*v0.z + g1*v1.z + g2*v2.z + g3*v3.z + cf.z)*mv;
                    float rw = (g0*v0.w + g1*v1.w + g2*v2.w + g3*v3.w + cf.w)*mv;
                    hi[gg*2]   = pack_f16_hi(rx, ry);
                    hi[gg*2+1] = pack_f16_hi(rz, rw);
                    lo[gg*2]   = pack_f16_lo(rx, ry);
                    lo[gg*2+1] = pack_f16_lo(rz, rw);
                }
                int sw = SW128(px*128 + half*64 + jj*16);
                *(uint4*)(smem + S_AH + sw) = make_uint4(hi[0], hi[1], hi[2], hi[3]);
                *(uint4*)(smem + S_AL + sw) = make_uint4(lo[0], lo[1], lo[2], lo[3]);
            }
        }
        cp_wait<0>();
        __syncthreads();

        // MMA: warp tile 16 px x 64 oc, K=64
#pragma unroll
        for (int kc = 0; kc < 4; kc++) {
            int kb = kc * 16;
            uint32_t aoff = SW128(am_row*128 + (kb + am_kof)*2);
            uint32_t ah[4], al[4];
            ldm_x4(ah, sb + S_AH + aoff);
            ldm_x4(al, sb + S_AL + aoff);
#pragma unroll
            for (int npair = 0; npair < 4; npair++) {
                uint32_t boff = SW128((bn_row + npair*16)*128 + (kb + bn_kof)*2);
                uint32_t bhf[4];
                ldm_x4(bhf, sb + S_WH + boff);
#pragma unroll
                for (int sub = 0; sub < 2; sub++) {
                    float* d = acc[npair*2 + sub];
                    mma16816(d, ah, bhf[sub*2], bhf[sub*2+1]);
                    mma16816(d, al, bhf[sub*2], bhf[sub*2+1]);
                }
            }
        }
        __syncthreads();
    }

    // ---------- epilogue ----------
    float* stage = (float*)(smem + S_AH);
    {
        int r0 = wid*16 + (lane >> 2);
        int cc = (lane & 3)*2;
#pragma unroll
        for (int nsub = 0; nsub < 8; nsub++) {
            int col = nsub*8 + cc;
            stage[r0*65 + col]       = acc[nsub][0];
            stage[r0*65 + col + 1]   = acc[nsub][1];
            stage[(r0+8)*65 + col]   = acc[nsub][2];
            stage[(r0+8)*65 + col+1] = acc[nsub][3];
        }
    }
    __syncthreads();
#pragma unroll
    for (int it = 0; it < 8; it++) {
        int idx = it*256 + tid;
        int oc = idx >> 5, g = idx & 31;
        int px = g*4;
        float4 o;
        o.x = stage[px*65 + oc];
        o.y = stage[(px+1)*65 + oc];
        o.z = stage[(px+2)*65 + oc];
        o.w = stage[(px+3)*65 + oc];
        *(float4*)&out[(size_t)(b*64 + oc)*HW + h*128 + px] = o;
    }
}

// ---------------- launch ----------------
extern "C" void kernel_launch(void* const* d_in, const int* in_sizes, int n_in,
                              void* d_out, int out_size)
{
    const float* x      = (const float*)d_in[0];
    const float* ref    = (const float*)d_in[1];
    const float* w_cd   = (const float*)d_in[2];
    const float* b_cd   = (const float*)d_in[3];
    const float* w_p    = (const float*)d_in[4];
    const float* b_p    = (const float*)d_in[5];
    const float* w_m    = (const float*)d_in[6];
    const float* b_m    = (const float*)d_in[7];
    const float* w_c    = (const float*)d_in[8];
    const float* b_c    = (const float*)d_in[9];
    const float* w_conv = (const float*)d_in[10];
    float* out = (float*)d_out;

    cudaFuncSetAttribute(k2_mma, cudaFuncAttributeMaxDynamicSharedMemorySize, 98304);
    cudaFuncSetAttribute(k3_mma, cudaFuncAttributeMaxDynamicSharedMemorySize, 46080);

    prep_zero<<<(BB*130*130*64/8 + 255)/256, 256>>>();
    prep_pack<<<(9*640*64 + 255)/256, 256>>>(w_p, b_p, w_m, b_m, w_c, b_c, w_cd, w_conv);
    prep_xt<<<(BB*130*130*64 + 255)/256, 256>>>(x);
    k1_fused<<<512, 256>>>(x, ref, b_cd);
    k2_mma<<<dim3(5, 512), 256, 98304>>>();
    k3_mma<<<512, 256, 46080>>>(out);
}

// round 11
// speedup vs baseline: 3.1424x; 1.1818x over previous
#include <cuda_runtime.h>
#include <cuda_fp16.h>
#include <math.h>
#include <stdint.h>

#define HW 16384
#define BB 4

// ---------------- device scratch ----------------
__device__ __half g_fph[(size_t)BB*130*130*64];  // padded channel-last fused (fp16)
__device__ float g_xt[BB*130*130*64];            // padded x, channel-last [b][r][cc][c]
__device__ float g_off[BB*27*HW];                // offset(18)+m(9) [b][ch][hw]
__device__ float g_coff[(size_t)BB*HW*9*64];     // tanh(c_off) [b][pix][n*64+c]
__device__ __half g_wbh[9*640*64];               // [kk][co'][ci]
__device__ float g_bias640[640];                 // co' order
__device__ float g_wcdT[128*64];                 // [ci][co]
__device__ __half g_w2h[9*64*64];                // [n][oc][c] final conv

#define SW128(o) ((o) ^ (((o) >> 3) & 0x70))

__device__ __forceinline__ uint32_t smem_u32(const void* p) {
    uint32_t a;
    asm("{ .reg .u64 t; cvta.to.shared.u64 t, %1; cvt.u32.u64 %0, t; }" : "=r"(a) : "l"(p));
    return a;
}
__device__ __forceinline__ void ldm_x4(uint32_t* r, uint32_t addr) {
    asm volatile("ldmatrix.sync.aligned.m8n8.x4.shared.b16 {%0,%1,%2,%3}, [%4];"
        : "=r"(r[0]), "=r"(r[1]), "=r"(r[2]), "=r"(r[3]) : "r"(addr));
}
__device__ __forceinline__ void mma16816(float* d, const uint32_t* a, uint32_t b0, uint32_t b1) {
    asm volatile("mma.sync.aligned.m16n8k16.row.col.f32.f16.f16.f32 "
        "{%0,%1,%2,%3}, {%4,%5,%6,%7}, {%8,%9}, {%0,%1,%2,%3};"
        : "+f"(d[0]), "+f"(d[1]), "+f"(d[2]), "+f"(d[3])
        : "r"(a[0]), "r"(a[1]), "r"(a[2]), "r"(a[3]), "r"(b0), "r"(b1));
}
__device__ __forceinline__ void cp16(uint32_t dst, const void* src) {
    asm volatile("cp.async.cg.shared.global [%0], [%1], 16;" :: "r"(dst), "l"(src));
}
__device__ __forceinline__ void cp_commit() { asm volatile("cp.async.commit_group;" ::: "memory"); }
template<int N> __device__ __forceinline__ void cp_wait() {
    asm volatile("cp.async.wait_group %0;" :: "n"(N) : "memory");
}
__device__ __forceinline__ float tanh_fast(float v) {
    float e = __expf(2.f * v);
    return 1.f - 2.f / (e + 1.f);
}
__device__ __forceinline__ uint32_t pack_f16_hi(float a, float b) {
    return ((uint32_t)__half_as_ushort(__float2half_rn(b)) << 16)
         |  (uint32_t)__half_as_ushort(__float2half_rn(a));
}
__device__ __forceinline__ uint32_t pack_f16_lo(float a, float b) {
    __half ha = __float2half_rn(a), hb = __float2half_rn(b);
    float la = a - __half2float(ha), lb = b - __half2float(hb);
    return ((uint32_t)__half_as_ushort(__float2half_rn(lb)) << 16)
         |  (uint32_t)__half_as_ushort(__float2half_rn(la));
}

// ---------------- prep: zero only the 1-px border ----------------
__global__ void prep_zero()
{
    int i = blockIdx.x * blockDim.x + threadIdx.x;
    const int n4 = (int)((size_t)BB*130*130*64/8);
    if (i >= n4) return;
    int t  = i >> 3;
    int cc = t % 130; t /= 130;
    int r  = t % 130;
    if (r == 0 || r == 129 || cc == 0 || cc == 129)
        ((uint4*)g_fph)[i] = make_uint4(0,0,0,0);
}

// ---------------- prep: pack weights ----------------
__global__ void prep_pack(const float* __restrict__ wp, const float* __restrict__ bp,
                          const float* __restrict__ wm, const float* __restrict__ bm,
                          const float* __restrict__ wc, const float* __restrict__ bc,
                          const float* __restrict__ wcd, const float* __restrict__ wconv)
{
    int idx = blockIdx.x * blockDim.x + threadIdx.x;
    if (idx < 9*640*64) {
        int kk = idx / (640*64);
        int r  = idx - kk*640*64;
        int co = r >> 6, ci = r & 63;
        float v = 0.f;
        if      (co < 18)  v = wp[(co*64 + ci)*9 + kk];
        else if (co < 27)  v = wm[((co-18)*64 + ci)*9 + kk];
        else if (co < 603) { int t = co-27; int n = t >> 6, c = t & 63;
                             v = wc[((c*9 + n)*64 + ci)*9 + kk]; }
        g_wbh[idx] = __float2half_rn(v);
    }
    if (idx < 640) {
        float bv = 0.f;
        if      (idx < 18)  bv = bp[idx];
        else if (idx < 27)  bv = bm[idx-18];
        else if (idx < 603) { int t = idx-27; int n = t >> 6, c = t & 63; bv = bc[c*9 + n]; }
        g_bias640[idx] = bv;
    }
    if (idx < 128*64) {
        int ci = idx >> 6, co = idx & 63;
        g_wcdT[idx] = wcd[co*128 + ci];
    }
    if (idx < 9*64*64) {
        int n = idx >> 12, r = idx & 4095;
        int oc = r >> 6, c = r & 63;
        g_w2h[idx] = __float2half_rn(wconv[(oc*64 + c)*9 + n]);
    }
}

// ---------------- prep: padded channel-last x ----------------
__global__ void prep_xt(const float* __restrict__ x)
{
    int idx = blockIdx.x * blockDim.x + threadIdx.x;
    const int total = BB*130*130*64;
    if (idx >= total) return;
    int c  = idx & 63;
    int t  = idx >> 6;
    int cc = t % 130; t /= 130;
    int r  = t % 130;
    int b  = t / 130;
    float v = 0.f;
    if (r >= 1 && r <= 128 && cc >= 1 && cc <= 128)
        v = x[((b*64 + c)*128 + (r-1))*128 + (cc-1)];
    g_xt[idx] = v;
}

// ---------------- K1: 1x1 conv -> padded channel-last fp16 ----------------
__global__ __launch_bounds__(256) void k1_fused(const float* __restrict__ x,
                                                const float* __restrict__ ref,
                                                const float* __restrict__ bcd)
{
    __shared__ float xin[32][128];
    __shared__ float wsm[32][64];
    int tid  = threadIdx.x;
    int b    = blockIdx.x >> 7;
    int seg  = blockIdx.x & 127;
    int pix0 = seg << 7;
    int ocg  = tid & 15, pixg = tid >> 4;

    float acc[4][8];
#pragma unroll
    for (int o = 0; o < 4; o++) {
        float bv = bcd[ocg*4 + o];
#pragma unroll
        for (int j = 0; j < 8; j++) acc[o][j] = bv;
    }

    for (int ci0 = 0; ci0 < 128; ci0 += 32) {
#pragma unroll
        for (int it = 0; it < 16; it++) {
            int idx = it*256 + tid;
            int ci  = idx >> 7, px = idx & 127;
            int gl  = ci0 + ci;
            float v = (gl < 64) ? x[(b*64 + gl)*HW + pix0 + px]
                                : ref[(b*64 + gl - 64)*HW + pix0 + px];
            xin[ci][px] = v;
        }
#pragma unroll
        for (int it = 0; it < 8; it++) {
            int idx = it*256 + tid;
            int ci = idx >> 6, oc = idx & 63;
            wsm[ci][oc] = g_wcdT[(ci0 + ci)*64 + oc];
        }
        __syncthreads();
#pragma unroll
        for (int ci = 0; ci < 32; ci++) {
            float4 wv = *(const float4*)&wsm[ci][ocg*4];
            float4 x0 = *(const float4*)&xin[ci][pixg*8];
            float4 x1 = *(const float4*)&xin[ci][pixg*8 + 4];
            float wvv[4] = {wv.x, wv.y, wv.z, wv.w};
            float xv[8]  = {x0.x, x0.y, x0.z, x0.w, x1.x, x1.y, x1.z, x1.w};
#pragma unroll
            for (int o = 0; o < 4; o++)
#pragma unroll
                for (int j = 0; j < 8; j++)
                    acc[o][j] += wvv[o]*xv[j];
        }
        __syncthreads();
    }
#pragma unroll
    for (int j = 0; j < 8; j++) {
        int ww = pixg*8 + j;
        size_t base = ((size_t)(b*130 + seg + 1)*130 + (ww + 1))*64 + ocg*4;
        *(uint32_t*)&g_fph[base]     = pack_f16_hi(acc[0][j], acc[1][j]);
        *(uint32_t*)&g_fph[base + 2] = pack_f16_hi(acc[2][j], acc[3][j]);
    }
}

// ---------------- K2: HMMA implicit GEMM conv, 1-product fp16, cp.async 2-stage ----------------
// dyn smem: 2 stages x 32KB (Ah 16K | Wh 16K) = 65536; epilogue reuses as 128x129 f32 (66048)
__global__ __launch_bounds__(256, 2) void k2_mma()
{
    extern __shared__ __align__(16) char smem[];
    float* smem_f = (float*)smem;
    uint32_t sb = smem_u32(smem);
    int tid = threadIdx.x, wid = tid >> 5, lane = tid & 31;
    int ntile = blockIdx.x;
    int mt    = blockIdx.y;
    int b = mt >> 7, h = mt & 127;
    int co0 = ntile * 128;
    int warp_m = wid >> 2, warp_n = wid & 3;
    const int STG = 32768;

    float acc[4][4][4];
#pragma unroll
    for (int i = 0; i < 4; i++)
#pragma unroll
        for (int j = 0; j < 4; j++)
#pragma unroll
            for (int q = 0; q < 4; q++) acc[i][j][q] = 0.f;

    int bn_row = warp_n*32 + (lane & 7) + ((lane >> 4) << 3);
    int bn_kof = ((lane >> 3) & 1) * 8;
    int am_row = warp_m*64 + (lane & 7) + (((lane >> 3) & 1) << 3);
    int am_kof = (lane >> 4) << 3;

    auto issue_fill = [&](int it9, int stg) {
        int kh = it9 / 3, kw = it9 - kh*3;
        size_t rowbase = ((size_t)(b*130 + h + kh)*130 + kw) * 64;
        const uint4* sAh = (const uint4*)(g_fph + rowbase);
        const uint4* sWh = (const uint4*)(g_wbh + ((size_t)(it9*640 + co0)) * 64);
        uint32_t base = sb + stg*STG;
#pragma unroll
        for (int it = 0; it < 4; it++) {
            int i = it*256 + tid;
            uint32_t sw = SW128(i * 16);
            cp16(base + sw,         sAh + i);
            cp16(base + 16384 + sw, sWh + i);
        }
        cp_commit();
    };

    issue_fill(0, 0);
    for (int it9 = 0; it9 < 9; it9++) {
        if (it9 < 8) { issue_fill(it9 + 1, (it9 + 1) & 1); cp_wait<1>(); }
        else         { cp_wait<0>(); }
        __syncthreads();

        uint32_t bbase = sb + (it9 & 1)*STG;
#pragma unroll
        for (int kc = 0; kc < 4; kc++) {
            int kb = kc * 16;
            uint32_t bh[8];
#pragma unroll
            for (int npair = 0; npair < 2; npair++) {
                uint32_t off = SW128((bn_row + npair*16)*128 + (kb + bn_kof)*2);
                ldm_x4(&bh[npair*4], bbase + 16384 + off);
            }
#pragma unroll
            for (int msub = 0; msub < 4; msub++) {
                uint32_t aoff = SW128((am_row + msub*16)*128 + (kb + am_kof)*2);
                uint32_t a[4];
                ldm_x4(a, bbase + aoff);
#pragma unroll
                for (int nsub = 0; nsub < 4; nsub++) {
                    int bi = (nsub >> 1)*4 + (nsub & 1)*2;
                    mma16816(acc[msub][nsub], a, bh[bi], bh[bi+1]);
                }
            }
        }
        __syncthreads();
    }

#pragma unroll
    for (int msub = 0; msub < 4; msub++) {
#pragma unroll
        for (int nsub = 0; nsub < 4; nsub++) {
            int m  = warp_m*64 + msub*16 + (lane >> 2);
            int cl = warp_n*32 + nsub*8 + (lane & 3)*2;
            smem_f[m*129 + cl]       = acc[msub][nsub][0];
            smem_f[m*129 + cl + 1]   = acc[msub][nsub][1];
            smem_f[(m+8)*129 + cl]   = acc[msub][nsub][2];
            smem_f[(m+8)*129 + cl+1] = acc[msub][nsub][3];
        }
    }
    __syncthreads();

    int pixrow = h*128;
    if (ntile == 0) {
        for (int idx = tid; idx < 27*128; idx += 256) {
            int co = idx >> 7, p = idx & 127;
            float v = smem_f[p*129 + co] + g_bias640[co];
            if (co >= 18) v = 1.f/(1.f + __expf(-v));
            g_off[(b*27 + co)*HW + pixrow + p] = v;
        }
        for (int idx = tid; idx < 128*101; idx += 256) {
            int p = idx / 101, j = idx - p*101 + 27;
            float v = tanh_fast(smem_f[p*129 + j] + g_bias640[j]);
            g_coff[((size_t)(b*HW + pixrow + p))*576 + (j - 27)] = v;
        }
    } else {
        for (int idx = tid; idx < 128*128; idx += 256) {
            int p = idx >> 7, j = idx & 127;
            int co = co0 + j;
            if (co < 603) {
                float v = tanh_fast(smem_f[p*129 + j] + g_bias640[co]);
                g_coff[((size_t)(b*HW + pixrow + p))*576 + (co - 27)] = v;
            }
        }
    }
}

// ---------------- K3: deformable sampling + HMMA final conv (2-product fp16) ----------------
// dyn smem: [0,5120) tasks | [5120) Ah 16K | [21504) Al 16K | [37888) Wh 8K = 46080
__global__ __launch_bounds__(256) void k3_mma(float* __restrict__ out)
{
    extern __shared__ __align__(16) char smem[];
    const int S_AH = 5120, S_AL = 21504, S_WH = 37888;
    int*   s_cb = (int*)smem;
    float* s_g  = (float*)(smem + 2048);
    float* s_m  = (float*)(smem + 4096);
    uint32_t sb = smem_u32(smem);
    int tid = threadIdx.x, wid = tid >> 5, lane = tid & 31;
    int b = blockIdx.x >> 7, h = blockIdx.x & 127;

    float acc[8][4];
#pragma unroll
    for (int i = 0; i < 8; i++)
#pragma unroll
        for (int q = 0; q < 4; q++) acc[i][q] = 0.f;

    int am_row = wid*16 + (lane & 7) + (((lane >> 3) & 1) << 3);
    int am_kof = (lane >> 4) << 3;
    int bn_row = (lane & 7) + ((lane >> 4) << 3);
    int bn_kof = ((lane >> 3) & 1) * 8;

    int px_g = tid >> 1, half = tid & 1;

    for (int n = 0; n < 9; n++) {
        {
            const uint4* sWh = (const uint4*)(g_w2h + n*4096);
#pragma unroll
            for (int it = 0; it < 2; it++) {
                int i = it*256 + tid;
                uint32_t sw = SW128(i*16);
                cp16(sb + S_WH + sw, sWh + i);
            }
            cp_commit();
        }
        if (tid < 128) {
            int px = tid;
            int pixidx = h*128 + px;
            float offr = g_off[(b*27 + n)*HW + pixidx];
            float offc = g_off[(b*27 + 9 + n)*HW + pixidx];
            float mv   = g_off[(b*27 + 18 + n)*HW + pixidx];
            float pr = (float)(h + 1 + n/3 - 1) + offr;
            float pc = (float)(px + 1 + n%3 - 1) + offc;
            float flr = floorf(pr), flc = floorf(pc);
            float ltr = fminf(fmaxf(flr,       0.f), 129.f);
            float ltc = fminf(fmaxf(flc,       0.f), 129.f);
            float rbr = fminf(fmaxf(flr + 1.f, 0.f), 129.f);
            float rbc = fminf(fmaxf(flc + 1.f, 0.f), 129.f);
            float prc = fminf(fmaxf(pr,        0.f), 129.f);
            float pcc = fminf(fmaxf(pc,        0.f), 129.f);
            s_g[0*128 + px] = (1.f + (ltr - prc))*(1.f + (ltc - pcc)); // lt
            s_g[1*128 + px] = (1.f - (rbr - prc))*(1.f - (rbc - pcc)); // rb
            s_g[2*128 + px] = (1.f + (ltr - prc))*(1.f - (rbc - pcc)); // lb
            s_g[3*128 + px] = (1.f - (rbr - prc))*(1.f + (ltc - pcc)); // rt
            int iltr = (int)ltr, iltc = (int)ltc, irbr = (int)rbr, irbc = (int)rbc;
            int bb = b*130;
            s_cb[0*128 + px] = ((bb + iltr)*130 + iltc)*16;
            s_cb[1*128 + px] = ((bb + irbr)*130 + irbc)*16;
            s_cb[2*128 + px] = ((bb + iltr)*130 + irbc)*16;
            s_cb[3*128 + px] = ((bb + irbr)*130 + iltc)*16;
            s_m[px] = mv;
        }
        __syncthreads();

        // gather + convert to fp16 hi/lo swizzled A tiles
        {
            const float4* xt4 = (const float4*)g_xt;
            int px = px_g;
            int c0 = s_cb[0*128 + px], c1 = s_cb[1*128 + px];
            int c2 = s_cb[2*128 + px], c3 = s_cb[3*128 + px];
            float g0 = s_g[0*128 + px], g1 = s_g[1*128 + px];
            float g2 = s_g[2*128 + px], g3 = s_g[3*128 + px];
            float mv = s_m[px];
            size_t coffbase = ((size_t)(b*HW + h*128 + px))*576 + n*64 + half*32;
#pragma unroll
            for (int jj = 0; jj < 4; jj++) {
                uint32_t hi[4], lo[4];
#pragma unroll
                for (int gg = 0; gg < 2; gg++) {
                    int cq = (half*32 + jj*8 + gg*4) >> 2;
                    float4 v0 = xt4[c0 + cq], v1 = xt4[c1 + cq];
                    float4 v2 = xt4[c2 + cq], v3 = xt4[c3 + cq];
                    float4 cf = *(const float4*)&g_coff[coffbase + jj*8 + gg*4];
                    float rx = (g0*v0.x + g1*v1.x + g2*v2.x + g3*v3.x + cf.x)*mv;
                    float ry = (g0*v0.y + g1*v1.y + g2*v2.y + g3*v3.y + cf.y)*mv;
                    float rz = (g0*v0.z + g1*v1.z + g2*v2.z + g3*v3.z + cf.z)*mv;
                    float rw = (g0*v0.w + g1*v1.w + g2*v2.w + g3*v3.w + cf.w)*mv;
                    hi[gg*2]   = pack_f16_hi(rx, ry);
                    hi[gg*2+1] = pack_f16_hi(rz, rw);
                    lo[gg*2]   = pack_f16_lo(rx, ry);
                    lo[gg*2+1] = pack_f16_lo(rz, rw);
                }
                int sw = SW128(px*128 + half*64 + jj*16);
                *(uint4*)(smem + S_AH + sw) = make_uint4(hi[0], hi[1], hi[2], hi[3]);
                *(uint4*)(smem + S_AL + sw) = make_uint4(lo[0], lo[1], lo[2], lo[3]);
            }
        }
        cp_wait<0>();
        __syncthreads();

        // MMA: warp tile 16 px x 64 oc, K=64
#pragma unroll
        for (int kc = 0; kc < 4; kc++) {
            int kb = kc * 16;
            uint32_t aoff = SW128(am_row*128 + (kb + am_kof)*2);
            uint32_t ah[4], al[4];
            ldm_x4(ah, sb + S_AH + aoff);
            ldm_x4(al, sb + S_AL + aoff);
#pragma unroll
            for (int npair = 0; npair < 4; npair++) {
                uint32_t boff = SW128((bn_row + npair*16)*128 + (kb + bn_kof)*2);
                uint32_t bhf[4];
                ldm_x4(bhf, sb + S_WH + boff);
#pragma unroll
                for (int sub = 0; sub < 2; sub++) {
                    float* d = acc[npair*2 + sub];
                    mma16816(d, ah, bhf[sub*2], bhf[sub*2+1]);
                    mma16816(d, al, bhf[sub*2], bhf[sub*2+1]);
                }
            }
        }
        __syncthreads();
    }

    // ---------- epilogue ----------
    float* stage = (float*)(smem + S_AH);
    {
        int r0 = wid*16 + (lane >> 2);
        int cc = (lane & 3)*2;
#pragma unroll
        for (int nsub = 0; nsub < 8; nsub++) {
            int col = nsub*8 + cc;
            stage[r0*65 + col]       = acc[nsub][0];
            stage[r0*65 + col + 1]   = acc[nsub][1];
            stage[(r0+8)*65 + col]   = acc[nsub][2];
            stage[(r0+8)*65 + col+1] = acc[nsub][3];
        }
    }
    __syncthreads();
#pragma unroll
    for (int it = 0; it < 8; it++) {
        int idx = it*256 + tid;
        int oc = idx >> 5, g = idx & 31;
        int px = g*4;
        float4 o;
        o.x = stage[px*65 + oc];
        o.y = stage[(px+1)*65 + oc];
        o.z = stage[(px+2)*65 + oc];
        o.w = stage[(px+3)*65 + oc];
        *(float4*)&out[(size_t)(b*64 + oc)*HW + h*128 + px] = o;
    }
}

// ---------------- launch ----------------
extern "C" void kernel_launch(void* const* d_in, const int* in_sizes, int n_in,
                              void* d_out, int out_size)
{
    const float* x      = (const float*)d_in[0];
    const float* ref    = (const float*)d_in[1];
    const float* w_cd   = (const float*)d_in[2];
    const float* b_cd   = (const float*)d_in[3];
    const float* w_p    = (const float*)d_in[4];
    const float* b_p    = (const float*)d_in[5];
    const float* w_m    = (const float*)d_in[6];
    const float* b_m    = (const float*)d_in[7];
    const float* w_c    = (const float*)d_in[8];
    const float* b_c    = (const float*)d_in[9];
    const float* w_conv = (const float*)d_in[10];
    float* out = (float*)d_out;

    cudaFuncSetAttribute(k2_mma, cudaFuncAttributeMaxDynamicSharedMemorySize, 66048);
    cudaFuncSetAttribute(k3_mma, cudaFuncAttributeMaxDynamicSharedMemorySize, 46080);

    prep_zero<<<(BB*130*130*64/8 + 255)/256, 256>>>();
    prep_pack<<<(9*640*64 + 255)/256, 256>>>(w_p, b_p, w_m, b_m, w_c, b_c, w_cd, w_conv);
    prep_xt<<<(BB*130*130*64 + 255)/256, 256>>>(x);
    k1_fused<<<512, 256>>>(x, ref, b_cd);
    k2_mma<<<dim3(5, 512), 256, 66048>>>();
    k3_mma<<<512, 256, 46080>>>(out);
}

// round 12
// speedup vs baseline: 3.3780x; 1.0750x over previous
#include <cuda_runtime.h>
#include <cuda_fp16.h>
#include <math.h>
#include <stdint.h>

#define HW 16384
#define BB 4

// ---------------- device scratch ----------------
__device__ __half g_fph[(size_t)BB*130*130*64];  // padded channel-last fused (fp16)
__device__ float g_xt[BB*130*130*64];            // padded x, channel-last [b][r][cc][c]
__device__ float g_off[BB*27*HW];                // offset(18)+m(9) [b][ch][hw]
__device__ __half g_coff[(size_t)BB*HW*9*64];    // tanh(c_off) [b][pix][n*64+c]  (fp16)
__device__ __half g_wbh[9*640*64];               // [kk][co'][ci]
__device__ float g_bias640[640];                 // co' order
__device__ float g_wcdT[128*64];                 // [ci][co]
__device__ __half g_w2h[9*64*64];                // [n][oc][c] final conv

#define SW128(o) ((o) ^ (((o) >> 3) & 0x70))

__device__ __forceinline__ uint32_t smem_u32(const void* p) {
    uint32_t a;
    asm("{ .reg .u64 t; cvta.to.shared.u64 t, %1; cvt.u32.u64 %0, t; }" : "=r"(a) : "l"(p));
    return a;
}
__device__ __forceinline__ void ldm_x4(uint32_t* r, uint32_t addr) {
    asm volatile("ldmatrix.sync.aligned.m8n8.x4.shared.b16 {%0,%1,%2,%3}, [%4];"
        : "=r"(r[0]), "=r"(r[1]), "=r"(r[2]), "=r"(r[3]) : "r"(addr));
}
__device__ __forceinline__ void mma16816(float* d, const uint32_t* a, uint32_t b0, uint32_t b1) {
    asm volatile("mma.sync.aligned.m16n8k16.row.col.f32.f16.f16.f32 "
        "{%0,%1,%2,%3}, {%4,%5,%6,%7}, {%8,%9}, {%0,%1,%2,%3};"
        : "+f"(d[0]), "+f"(d[1]), "+f"(d[2]), "+f"(d[3])
        : "r"(a[0]), "r"(a[1]), "r"(a[2]), "r"(a[3]), "r"(b0), "r"(b1));
}
__device__ __forceinline__ void cp16(uint32_t dst, const void* src) {
    asm volatile("cp.async.cg.shared.global [%0], [%1], 16;" :: "r"(dst), "l"(src));
}
__device__ __forceinline__ void cp_commit() { asm volatile("cp.async.commit_group;" ::: "memory"); }
template<int N> __device__ __forceinline__ void cp_wait() {
    asm volatile("cp.async.wait_group %0;" :: "n"(N) : "memory");
}
__device__ __forceinline__ float tanh_fast(float v) {
    float e = __expf(2.f * v);
    return 1.f - 2.f / (e + 1.f);
}
__device__ __forceinline__ uint32_t pack_f16_hi(float a, float b) {
    return ((uint32_t)__half_as_ushort(__float2half_rn(b)) << 16)
         |  (uint32_t)__half_as_ushort(__float2half_rn(a));
}
__device__ __forceinline__ uint32_t pack_f16_lo(float a, float b) {
    __half ha = __float2half_rn(a), hb = __float2half_rn(b);
    float la = a - __half2float(ha), lb = b - __half2float(hb);
    return ((uint32_t)__half_as_ushort(__float2half_rn(lb)) << 16)
         |  (uint32_t)__half_as_ushort(__float2half_rn(la));
}

// ---------------- prep: zero only the 1-px border ----------------
__global__ void prep_zero()
{
    int i = blockIdx.x * blockDim.x + threadIdx.x;
    const int n4 = (int)((size_t)BB*130*130*64/8);
    if (i >= n4) return;
    int t  = i >> 3;
    int cc = t % 130; t /= 130;
    int r  = t % 130;
    if (r == 0 || r == 129 || cc == 0 || cc == 129)
        ((uint4*)g_fph)[i] = make_uint4(0,0,0,0);
}

// ---------------- prep: pack weights ----------------
__global__ void prep_pack(const float* __restrict__ wp, const float* __restrict__ bp,
                          const float* __restrict__ wm, const float* __restrict__ bm,
                          const float* __restrict__ wc, const float* __restrict__ bc,
                          const float* __restrict__ wcd, const float* __restrict__ wconv)
{
    int idx = blockIdx.x * blockDim.x + threadIdx.x;
    if (idx < 9*640*64) {
        int kk = idx / (640*64);
        int r  = idx - kk*640*64;
        int co = r >> 6, ci = r & 63;
        float v = 0.f;
        if      (co < 18)  v = wp[(co*64 + ci)*9 + kk];
        else if (co < 27)  v = wm[((co-18)*64 + ci)*9 + kk];
        else if (co < 603) { int t = co-27; int n = t >> 6, c = t & 63;
                             v = wc[((c*9 + n)*64 + ci)*9 + kk]; }
        g_wbh[idx] = __float2half_rn(v);
    }
    if (idx < 640) {
        float bv = 0.f;
        if      (idx < 18)  bv = bp[idx];
        else if (idx < 27)  bv = bm[idx-18];
        else if (idx < 603) { int t = idx-27; int n = t >> 6, c = t & 63; bv = bc[c*9 + n]; }
        g_bias640[idx] = bv;
    }
    if (idx < 128*64) {
        int ci = idx >> 6, co = idx & 63;
        g_wcdT[idx] = wcd[co*128 + ci];
    }
    if (idx < 9*64*64) {
        int n = idx >> 12, r = idx & 4095;
        int oc = r >> 6, c = r & 63;
        g_w2h[idx] = __float2half_rn(wconv[(oc*64 + c)*9 + n]);
    }
}

// ---------------- prep: padded channel-last x ----------------
__global__ void prep_xt(const float* __restrict__ x)
{
    int idx = blockIdx.x * blockDim.x + threadIdx.x;
    const int total = BB*130*130*64;
    if (idx >= total) return;
    int c  = idx & 63;
    int t  = idx >> 6;
    int cc = t % 130; t /= 130;
    int r  = t % 130;
    int b  = t / 130;
    float v = 0.f;
    if (r >= 1 && r <= 128 && cc >= 1 && cc <= 128)
        v = x[((b*64 + c)*128 + (r-1))*128 + (cc-1)];
    g_xt[idx] = v;
}

// ---------------- K1: 1x1 conv -> padded channel-last fp16 ----------------
__global__ __launch_bounds__(256) void k1_fused(const float* __restrict__ x,
                                                const float* __restrict__ ref,
                                                const float* __restrict__ bcd)
{
    __shared__ float xin[32][128];
    __shared__ float wsm[32][64];
    int tid  = threadIdx.x;
    int b    = blockIdx.x >> 7;
    int seg  = blockIdx.x & 127;
    int pix0 = seg << 7;
    int ocg  = tid & 15, pixg = tid >> 4;

    float acc[4][8];
#pragma unroll
    for (int o = 0; o < 4; o++) {
        float bv = bcd[ocg*4 + o];
#pragma unroll
        for (int j = 0; j < 8; j++) acc[o][j] = bv;
    }

    for (int ci0 = 0; ci0 < 128; ci0 += 32) {
#pragma unroll
        for (int it = 0; it < 16; it++) {
            int idx = it*256 + tid;
            int ci  = idx >> 7, px = idx & 127;
            int gl  = ci0 + ci;
            float v = (gl < 64) ? x[(b*64 + gl)*HW + pix0 + px]
                                : ref[(b*64 + gl - 64)*HW + pix0 + px];
            xin[ci][px] = v;
        }
#pragma unroll
        for (int it = 0; it < 8; it++) {
            int idx = it*256 + tid;
            int ci = idx >> 6, oc = idx & 63;
            wsm[ci][oc] = g_wcdT[(ci0 + ci)*64 + oc];
        }
        __syncthreads();
#pragma unroll
        for (int ci = 0; ci < 32; ci++) {
            float4 wv = *(const float4*)&wsm[ci][ocg*4];
            float4 x0 = *(const float4*)&xin[ci][pixg*8];
            float4 x1 = *(const float4*)&xin[ci][pixg*8 + 4];
            float wvv[4] = {wv.x, wv.y, wv.z, wv.w};
            float xv[8]  = {x0.x, x0.y, x0.z, x0.w, x1.x, x1.y, x1.z, x1.w};
#pragma unroll
            for (int o = 0; o < 4; o++)
#pragma unroll
                for (int j = 0; j < 8; j++)
                    acc[o][j] += wvv[o]*xv[j];
        }
        __syncthreads();
    }
#pragma unroll
    for (int j = 0; j < 8; j++) {
        int ww = pixg*8 + j;
        size_t base = ((size_t)(b*130 + seg + 1)*130 + (ww + 1))*64 + ocg*4;
        *(uint32_t*)&g_fph[base]     = pack_f16_hi(acc[0][j], acc[1][j]);
        *(uint32_t*)&g_fph[base + 2] = pack_f16_hi(acc[2][j], acc[3][j]);
    }
}

// ---------------- K2: HMMA implicit GEMM conv, 1-product fp16, cp.async 2-stage ----------------
// dyn smem: 2 stages x 32KB (Ah 16K | Wh 16K) = 65536; epilogue reuses as 128x129 f32 (66048)
__global__ __launch_bounds__(256, 2) void k2_mma()
{
    extern __shared__ __align__(16) char smem[];
    float* smem_f = (float*)smem;
    uint32_t sb = smem_u32(smem);
    int tid = threadIdx.x, wid = tid >> 5, lane = tid & 31;
    int ntile = blockIdx.x;
    int mt    = blockIdx.y;
    int b = mt >> 7, h = mt & 127;
    int co0 = ntile * 128;
    int warp_m = wid >> 2, warp_n = wid & 3;
    const int STG = 32768;

    float acc[4][4][4];
#pragma unroll
    for (int i = 0; i < 4; i++)
#pragma unroll
        for (int j = 0; j < 4; j++)
#pragma unroll
            for (int q = 0; q < 4; q++) acc[i][j][q] = 0.f;

    int bn_row = warp_n*32 + (lane & 7) + ((lane >> 4) << 3);
    int bn_kof = ((lane >> 3) & 1) * 8;
    int am_row = warp_m*64 + (lane & 7) + (((lane >> 3) & 1) << 3);
    int am_kof = (lane >> 4) << 3;

    auto issue_fill = [&](int it9, int stg) {
        int kh = it9 / 3, kw = it9 - kh*3;
        size_t rowbase = ((size_t)(b*130 + h + kh)*130 + kw) * 64;
        const uint4* sAh = (const uint4*)(g_fph + rowbase);
        const uint4* sWh = (const uint4*)(g_wbh + ((size_t)(it9*640 + co0)) * 64);
        uint32_t base = sb + stg*STG;
#pragma unroll
        for (int it = 0; it < 4; it++) {
            int i = it*256 + tid;
            uint32_t sw = SW128(i * 16);
            cp16(base + sw,         sAh + i);
            cp16(base + 16384 + sw, sWh + i);
        }
        cp_commit();
    };

    issue_fill(0, 0);
    for (int it9 = 0; it9 < 9; it9++) {
        if (it9 < 8) { issue_fill(it9 + 1, (it9 + 1) & 1); cp_wait<1>(); }
        else         { cp_wait<0>(); }
        __syncthreads();

        uint32_t bbase = sb + (it9 & 1)*STG;
#pragma unroll
        for (int kc = 0; kc < 4; kc++) {
            int kb = kc * 16;
            uint32_t bh[8];
#pragma unroll
            for (int npair = 0; npair < 2; npair++) {
                uint32_t off = SW128((bn_row + npair*16)*128 + (kb + bn_kof)*2);
                ldm_x4(&bh[npair*4], bbase + 16384 + off);
            }
#pragma unroll
            for (int msub = 0; msub < 4; msub++) {
                uint32_t aoff = SW128((am_row + msub*16)*128 + (kb + am_kof)*2);
                uint32_t a[4];
                ldm_x4(a, bbase + aoff);
#pragma unroll
                for (int nsub = 0; nsub < 4; nsub++) {
                    int bi = (nsub >> 1)*4 + (nsub & 1)*2;
                    mma16816(acc[msub][nsub], a, bh[bi], bh[bi+1]);
                }
            }
        }
        __syncthreads();
    }

#pragma unroll
    for (int msub = 0; msub < 4; msub++) {
#pragma unroll
        for (int nsub = 0; nsub < 4; nsub++) {
            int m  = warp_m*64 + msub*16 + (lane >> 2);
            int cl = warp_n*32 + nsub*8 + (lane & 3)*2;
            smem_f[m*129 + cl]       = acc[msub][nsub][0];
            smem_f[m*129 + cl + 1]   = acc[msub][nsub][1];
            smem_f[(m+8)*129 + cl]   = acc[msub][nsub][2];
            smem_f[(m+8)*129 + cl+1] = acc[msub][nsub][3];
        }
    }
    __syncthreads();

    int pixrow = h*128;
    if (ntile == 0) {
        for (int idx = tid; idx < 27*128; idx += 256) {
            int co = idx >> 7, p = idx & 127;
            float v = smem_f[p*129 + co] + g_bias640[co];
            if (co >= 18) v = 1.f/(1.f + __expf(-v));
            g_off[(b*27 + co)*HW + pixrow + p] = v;
        }
        for (int idx = tid; idx < 128*101; idx += 256) {
            int p = idx / 101, j = idx - p*101 + 27;
            float v = tanh_fast(smem_f[p*129 + j] + g_bias640[j]);
            g_coff[((size_t)(b*HW + pixrow + p))*576 + (j - 27)] = __float2half_rn(v);
        }
    } else {
        for (int idx = tid; idx < 128*128; idx += 256) {
            int p = idx >> 7, j = idx & 127;
            int co = co0 + j;
            if (co < 603) {
                float v = tanh_fast(smem_f[p*129 + j] + g_bias640[co]);
                g_coff[((size_t)(b*HW + pixrow + p))*576 + (co - 27)] = __float2half_rn(v);
            }
        }
    }
}

// ---------------- K3: deformable sampling + HMMA final conv (2-product fp16) ----------------
// dyn smem: [0) Ah 16K | [16384) Al 16K | [32768) Wh 8K = 40960; epilogue stage reuses [0)
__global__ __launch_bounds__(256) void k3_mma(float* __restrict__ out)
{
    extern __shared__ __align__(16) char smem[];
    const int S_AH = 0, S_AL = 16384, S_WH = 32768;
    uint32_t sb = smem_u32(smem);
    int tid = threadIdx.x, wid = tid >> 5, lane = tid & 31;
    int b = blockIdx.x >> 7, h = blockIdx.x & 127;

    float acc[8][4];
#pragma unroll
    for (int i = 0; i < 8; i++)
#pragma unroll
        for (int q = 0; q < 4; q++) acc[i][q] = 0.f;

    int am_row = wid*16 + (lane & 7) + (((lane >> 3) & 1) << 3);
    int am_kof = (lane >> 4) << 3;
    int bn_row = (lane & 7) + ((lane >> 4) << 3);
    int bn_kof = ((lane >> 3) & 1) * 8;

    int px = tid >> 1, half = tid & 1;
    int pixidx = h*128 + px;

    for (int n = 0; n < 9; n++) {
        // W fill via cp.async — overlaps with gather, waited before MMA
        {
            const uint4* sWh = (const uint4*)(g_w2h + n*4096);
#pragma unroll
            for (int it = 0; it < 2; it++) {
                int i = it*256 + tid;
                uint32_t sw = SW128(i*16);
                cp16(sb + S_WH + sw, sWh + i);
            }
            cp_commit();
        }

        // params in registers (each of the 2 threads per pixel computes redundantly)
        float offr = g_off[(b*27 + n)*HW + pixidx];
        float offc = g_off[(b*27 + 9 + n)*HW + pixidx];
        float mv   = g_off[(b*27 + 18 + n)*HW + pixidx];
        float pr = (float)(h + 1 + n/3 - 1) + offr;
        float pc = (float)(px + 1 + n%3 - 1) + offc;
        float flr = floorf(pr), flc = floorf(pc);
        float ltr = fminf(fmaxf(flr,       0.f), 129.f);
        float ltc = fminf(fmaxf(flc,       0.f), 129.f);
        float rbr = fminf(fmaxf(flr + 1.f, 0.f), 129.f);
        float rbc = fminf(fmaxf(flc + 1.f, 0.f), 129.f);
        float prc = fminf(fmaxf(pr,        0.f), 129.f);
        float pcc = fminf(fmaxf(pc,        0.f), 129.f);
        float g0 = (1.f + (ltr - prc))*(1.f + (ltc - pcc)); // lt
        float g1 = (1.f - (rbr - prc))*(1.f - (rbc - pcc)); // rb
        float g2 = (1.f + (ltr - prc))*(1.f - (rbc - pcc)); // lb
        float g3 = (1.f - (rbr - prc))*(1.f + (ltc - pcc)); // rt
        int iltr = (int)ltr, iltc = (int)ltc, irbr = (int)rbr, irbc = (int)rbc;
        int bb = b*130;
        int c0 = ((bb + iltr)*130 + iltc)*16;
        int c1 = ((bb + irbr)*130 + irbc)*16;
        int c2 = ((bb + iltr)*130 + irbc)*16;
        int c3 = ((bb + irbr)*130 + iltc)*16;

        // gather + convert to fp16 hi/lo swizzled A tiles
        {
            const float4* xt4 = (const float4*)g_xt;
            size_t coffbase = ((size_t)(b*HW + h*128 + px))*576 + n*64 + half*32;
#pragma unroll
            for (int jj = 0; jj < 4; jj++) {
                uint4 cr = *(const uint4*)(g_coff + coffbase + jj*8);
                float2 cf01 = __half22float2(*(__half2*)&cr.x);
                float2 cf23 = __half22float2(*(__half2*)&cr.y);
                float2 cf45 = __half22float2(*(__half2*)&cr.z);
                float2 cf67 = __half22float2(*(__half2*)&cr.w);
                float cfv[8] = {cf01.x, cf01.y, cf23.x, cf23.y,
                                cf45.x, cf45.y, cf67.x, cf67.y};
                uint32_t hi[4], lo[4];
#pragma unroll
                for (int gg = 0; gg < 2; gg++) {
                    int cq = (half*32 + jj*8 + gg*4) >> 2;
                    float4 v0 = xt4[c0 + cq], v1 = xt4[c1 + cq];
                    float4 v2 = xt4[c2 + cq], v3 = xt4[c3 + cq];
                    float rx = (g0*v0.x + g1*v1.x + g2*v2.x + g3*v3.x + cfv[gg*4+0])*mv;
                    float ry = (g0*v0.y + g1*v1.y + g2*v2.y + g3*v3.y + cfv[gg*4+1])*mv;
                    float rz = (g0*v0.z + g1*v1.z + g2*v2.z + g3*v3.z + cfv[gg*4+2])*mv;
                    float rw = (g0*v0.w + g1*v1.w + g2*v2.w + g3*v3.w + cfv[gg*4+3])*mv;
                    hi[gg*2]   = pack_f16_hi(rx, ry);
                    hi[gg*2+1] = pack_f16_hi(rz, rw);
                    lo[gg*2]   = pack_f16_lo(rx, ry);
                    lo[gg*2+1] = pack_f16_lo(rz, rw);
                }
                int sw = SW128(px*128 + half*64 + jj*16);
                *(uint4*)(smem + S_AH + sw) = make_uint4(hi[0], hi[1], hi[2], hi[3]);
                *(uint4*)(smem + S_AL + sw) = make_uint4(lo[0], lo[1], lo[2], lo[3]);
            }
        }
        cp_wait<0>();
        __syncthreads();

        // MMA: warp tile 16 px x 64 oc, K=64
#pragma unroll
        for (int kc = 0; kc < 4; kc++) {
            int kb = kc * 16;
            uint32_t aoff = SW128(am_row*128 + (kb + am_kof)*2);
            uint32_t ah[4], al[4];
            ldm_x4(ah, sb + S_AH + aoff);
            ldm_x4(al, sb + S_AL + aoff);
#pragma unroll
            for (int npair = 0; npair < 4; npair++) {
                uint32_t boff = SW128((bn_row + npair*16)*128 + (kb + bn_kof)*2);
                uint32_t bhf[4];
                ldm_x4(bhf, sb + S_WH + boff);
#pragma unroll
                for (int sub = 0; sub < 2; sub++) {
                    float* d = acc[npair*2 + sub];
                    mma16816(d, ah, bhf[sub*2], bhf[sub*2+1]);
                    mma16816(d, al, bhf[sub*2], bhf[sub*2+1]);
                }
            }
        }
        __syncthreads();
    }

    // ---------- epilogue: stage 128px x 64oc (pad 65), then coalesced out ----------
    float* stage = (float*)(smem + S_AH);
    {
        int r0 = wid*16 + (lane >> 2);
        int cc = (lane & 3)*2;
#pragma unroll
        for (int nsub = 0; nsub < 8; nsub++) {
            int col = nsub*8 + cc;
            stage[r0*65 + col]       = acc[nsub][0];
            stage[r0*65 + col + 1]   = acc[nsub][1];
            stage[(r0+8)*65 + col]   = acc[nsub][2];
            stage[(r0+8)*65 + col+1] = acc[nsub][3];
        }
    }
    __syncthreads();
#pragma unroll
    for (int it = 0; it < 8; it++) {
        int idx = it*256 + tid;
        int oc = idx >> 5, g = idx & 31;
        int pxo = g*4;
        float4 o;
        o.x = stage[pxo*65 + oc];
        o.y = stage[(pxo+1)*65 + oc];
        o.z = stage[(pxo+2)*65 + oc];
        o.w = stage[(pxo+3)*65 + oc];
        *(float4*)&out[(size_t)(b*64 + oc)*HW + h*128 + pxo] = o;
    }
}

// ---------------- launch ----------------
extern "C" void kernel_launch(void* const* d_in, const int* in_sizes, int n_in,
                              void* d_out, int out_size)
{
    const float* x      = (const float*)d_in[0];
    const float* ref    = (const float*)d_in[1];
    const float* w_cd   = (const float*)d_in[2];
    const float* b_cd   = (const float*)d_in[3];
    const float* w_p    = (const float*)d_in[4];
    const float* b_p    = (const float*)d_in[5];
    const float* w_m    = (const float*)d_in[6];
    const float* b_m    = (const float*)d_in[7];
    const float* w_c    = (const float*)d_in[8];
    const float* b_c    = (const float*)d_in[9];
    const float* w_conv = (const float*)d_in[10];
    float* out = (float*)d_out;

    cudaFuncSetAttribute(k2_mma, cudaFuncAttributeMaxDynamicSharedMemorySize, 66048);
    cudaFuncSetAttribute(k3_mma, cudaFuncAttributeMaxDynamicSharedMemorySize, 40960);

    prep_zero<<<(BB*130*130*64/8 + 255)/256, 256>>>();
    prep_pack<<<(9*640*64 + 255)/256, 256>>>(w_p, b_p, w_m, b_m, w_c, b_c, w_cd, w_conv);
    prep_xt<<<(BB*130*130*64 + 255)/256, 256>>>(x);
    k1_fused<<<512, 256>>>(x, ref, b_cd);
    k2_mma<<<dim3(5, 512), 256, 66048>>>();
    k3_mma<<<512, 256, 40960>>>(out);
}

// round 13
// speedup vs baseline: 4.4995x; 1.3320x over previous
#include <cuda_runtime.h>
#include <cuda_fp16.h>
#include <math.h>
#include <stdint.h>

#define HW 16384
#define BB 4

// ---------------- device scratch ----------------
__device__ __half g_fph[(size_t)BB*130*130*64];  // padded channel-last fused (fp16)
__device__ __half g_xth[(size_t)BB*130*130*64];  // padded x, channel-last fp16
__device__ float g_off[BB*27*HW];                // offset(18)+m(9) [b][ch][hw]
__device__ __half g_coff[(size_t)BB*HW*9*64];    // tanh(c_off) [b][pix][n*64+c]  (fp16)
__device__ __half g_wbh[9*640*64];               // [kk][co'][ci]
__device__ float g_bias640[640];                 // co' order
__device__ float g_wcdT[128*64];                 // [ci][co]
__device__ __half g_w2h[9*64*64];                // [n][oc][c] final conv

#define SW128(o) ((o) ^ (((o) >> 3) & 0x70))

__device__ __forceinline__ uint32_t smem_u32(const void* p) {
    uint32_t a;
    asm("{ .reg .u64 t; cvta.to.shared.u64 t, %1; cvt.u32.u64 %0, t; }" : "=r"(a) : "l"(p));
    return a;
}
__device__ __forceinline__ void ldm_x4(uint32_t* r, uint32_t addr) {
    asm volatile("ldmatrix.sync.aligned.m8n8.x4.shared.b16 {%0,%1,%2,%3}, [%4];"
        : "=r"(r[0]), "=r"(r[1]), "=r"(r[2]), "=r"(r[3]) : "r"(addr));
}
__device__ __forceinline__ void mma16816(float* d, const uint32_t* a, uint32_t b0, uint32_t b1) {
    asm volatile("mma.sync.aligned.m16n8k16.row.col.f32.f16.f16.f32 "
        "{%0,%1,%2,%3}, {%4,%5,%6,%7}, {%8,%9}, {%0,%1,%2,%3};"
        : "+f"(d[0]), "+f"(d[1]), "+f"(d[2]), "+f"(d[3])
        : "r"(a[0]), "r"(a[1]), "r"(a[2]), "r"(a[3]), "r"(b0), "r"(b1));
}
__device__ __forceinline__ void cp16(uint32_t dst, const void* src) {
    asm volatile("cp.async.cg.shared.global [%0], [%1], 16;" :: "r"(dst), "l"(src));
}
__device__ __forceinline__ void cp_commit() { asm volatile("cp.async.commit_group;" ::: "memory"); }
template<int N> __device__ __forceinline__ void cp_wait() {
    asm volatile("cp.async.wait_group %0;" :: "n"(N) : "memory");
}
__device__ __forceinline__ float tanh_fast(float v) {
    float e = __expf(2.f * v);
    return 1.f - 2.f / (e + 1.f);
}
__device__ __forceinline__ uint32_t pack_f16_hi(float a, float b) {
    return ((uint32_t)__half_as_ushort(__float2half_rn(b)) << 16)
         |  (uint32_t)__half_as_ushort(__float2half_rn(a));
}

// ---------------- prep: zero only the 1-px border of fused ----------------
__global__ void prep_zero()
{
    int i = blockIdx.x * blockDim.x + threadIdx.x;
    const int n4 = (int)((size_t)BB*130*130*64/8);
    if (i >= n4) return;
    int t  = i >> 3;
    int cc = t % 130; t /= 130;
    int r  = t % 130;
    if (r == 0 || r == 129 || cc == 0 || cc == 129)
        ((uint4*)g_fph)[i] = make_uint4(0,0,0,0);
}

// ---------------- prep: pack weights ----------------
__global__ void prep_pack(const float* __restrict__ wp, const float* __restrict__ bp,
                          const float* __restrict__ wm, const float* __restrict__ bm,
                          const float* __restrict__ wc, const float* __restrict__ bc,
                          const float* __restrict__ wcd, const float* __restrict__ wconv)
{
    int idx = blockIdx.x * blockDim.x + threadIdx.x;
    if (idx < 9*640*64) {
        int kk = idx / (640*64);
        int r  = idx - kk*640*64;
        int co = r >> 6, ci = r & 63;
        float v = 0.f;
        if      (co < 18)  v = wp[(co*64 + ci)*9 + kk];
        else if (co < 27)  v = wm[((co-18)*64 + ci)*9 + kk];
        else if (co < 603) { int t = co-27; int n = t >> 6, c = t & 63;
                             v = wc[((c*9 + n)*64 + ci)*9 + kk]; }
        g_wbh[idx] = __float2half_rn(v);
    }
    if (idx < 640) {
        float bv = 0.f;
        if      (idx < 18)  bv = bp[idx];
        else if (idx < 27)  bv = bm[idx-18];
        else if (idx < 603) { int t = idx-27; int n = t >> 6, c = t & 63; bv = bc[c*9 + n]; }
        g_bias640[idx] = bv;
    }
    if (idx < 128*64) {
        int ci = idx >> 6, co = idx & 63;
        g_wcdT[idx] = wcd[co*128 + ci];
    }
    if (idx < 9*64*64) {
        int n = idx >> 12, r = idx & 4095;
        int oc = r >> 6, c = r & 63;
        g_w2h[idx] = __float2half_rn(wconv[(oc*64 + c)*9 + n]);
    }
}

// ---------------- prep: padded channel-last x (fp16, half2 stores) ----------------
__global__ void prep_xt(const float* __restrict__ x)
{
    int idx = blockIdx.x * blockDim.x + threadIdx.x;
    const int total = BB*130*130*32;          // half2 count
    if (idx >= total) return;
    int cp = idx & 31;                        // half2 index in row
    int t  = idx >> 5;
    int cc = t % 130; t /= 130;
    int r  = t % 130;
    int b  = t / 130;
    float v0 = 0.f, v1 = 0.f;
    if (r >= 1 && r <= 128 && cc >= 1 && cc <= 128) {
        int base = (b*64 + cp*2)*HW + (r-1)*128 + (cc-1);
        v0 = x[base];
        v1 = x[base + HW];
    }
    ((__half2*)g_xth)[idx] = __floats2half2_rn(v0, v1);
}

// ---------------- K1: 1x1 conv -> padded channel-last fp16 ----------------
__global__ __launch_bounds__(256) void k1_fused(const float* __restrict__ x,
                                                const float* __restrict__ ref,
                                                const float* __restrict__ bcd)
{
    __shared__ float xin[32][128];
    __shared__ float wsm[32][64];
    int tid  = threadIdx.x;
    int b    = blockIdx.x >> 7;
    int seg  = blockIdx.x & 127;
    int pix0 = seg << 7;
    int ocg  = tid & 15, pixg = tid >> 4;

    float acc[4][8];
#pragma unroll
    for (int o = 0; o < 4; o++) {
        float bv = bcd[ocg*4 + o];
#pragma unroll
        for (int j = 0; j < 8; j++) acc[o][j] = bv;
    }

    for (int ci0 = 0; ci0 < 128; ci0 += 32) {
#pragma unroll
        for (int it = 0; it < 16; it++) {
            int idx = it*256 + tid;
            int ci  = idx >> 7, px = idx & 127;
            int gl  = ci0 + ci;
            float v = (gl < 64) ? x[(b*64 + gl)*HW + pix0 + px]
                                : ref[(b*64 + gl - 64)*HW + pix0 + px];
            xin[ci][px] = v;
        }
#pragma unroll
        for (int it = 0; it < 8; it++) {
            int idx = it*256 + tid;
            int ci = idx >> 6, oc = idx & 63;
            wsm[ci][oc] = g_wcdT[(ci0 + ci)*64 + oc];
        }
        __syncthreads();
#pragma unroll
        for (int ci = 0; ci < 32; ci++) {
            float4 wv = *(const float4*)&wsm[ci][ocg*4];
            float4 x0 = *(const float4*)&xin[ci][pixg*8];
            float4 x1 = *(const float4*)&xin[ci][pixg*8 + 4];
            float wvv[4] = {wv.x, wv.y, wv.z, wv.w};
            float xv[8]  = {x0.x, x0.y, x0.z, x0.w, x1.x, x1.y, x1.z, x1.w};
#pragma unroll
            for (int o = 0; o < 4; o++)
#pragma unroll
                for (int j = 0; j < 8; j++)
                    acc[o][j] += wvv[o]*xv[j];
        }
        __syncthreads();
    }
#pragma unroll
    for (int j = 0; j < 8; j++) {
        int ww = pixg*8 + j;
        size_t base = ((size_t)(b*130 + seg + 1)*130 + (ww + 1))*64 + ocg*4;
        *(uint32_t*)&g_fph[base]     = pack_f16_hi(acc[0][j], acc[1][j]);
        *(uint32_t*)&g_fph[base + 2] = pack_f16_hi(acc[2][j], acc[3][j]);
    }
}

// ---------------- K2: HMMA implicit GEMM conv, 1-product fp16, cp.async 2-stage ----------------
// dyn smem: 2 stages x 32KB (Ah 16K | Wh 16K) = 65536; epilogue reuses as 128x129 f32 (66048)
__global__ __launch_bounds__(256, 2) void k2_mma()
{
    extern __shared__ __align__(16) char smem[];
    float* smem_f = (float*)smem;
    uint32_t sb = smem_u32(smem);
    int tid = threadIdx.x, wid = tid >> 5, lane = tid & 31;
    int ntile = blockIdx.x;
    int mt    = blockIdx.y;
    int b = mt >> 7, h = mt & 127;
    int co0 = ntile * 128;
    int warp_m = wid >> 2, warp_n = wid & 3;
    const int STG = 32768;

    float acc[4][4][4];
#pragma unroll
    for (int i = 0; i < 4; i++)
#pragma unroll
        for (int j = 0; j < 4; j++)
#pragma unroll
            for (int q = 0; q < 4; q++) acc[i][j][q] = 0.f;

    int bn_row = warp_n*32 + (lane & 7) + ((lane >> 4) << 3);
    int bn_kof = ((lane >> 3) & 1) * 8;
    int am_row = warp_m*64 + (lane & 7) + (((lane >> 3) & 1) << 3);
    int am_kof = (lane >> 4) << 3;

    auto issue_fill = [&](int it9, int stg) {
        int kh = it9 / 3, kw = it9 - kh*3;
        size_t rowbase = ((size_t)(b*130 + h + kh)*130 + kw) * 64;
        const uint4* sAh = (const uint4*)(g_fph + rowbase);
        const uint4* sWh = (const uint4*)(g_wbh + ((size_t)(it9*640 + co0)) * 64);
        uint32_t base = sb + stg*STG;
#pragma unroll
        for (int it = 0; it < 4; it++) {
            int i = it*256 + tid;
            uint32_t sw = SW128(i * 16);
            cp16(base + sw,         sAh + i);
            cp16(base + 16384 + sw, sWh + i);
        }
        cp_commit();
    };

    issue_fill(0, 0);
    for (int it9 = 0; it9 < 9; it9++) {
        if (it9 < 8) { issue_fill(it9 + 1, (it9 + 1) & 1); cp_wait<1>(); }
        else         { cp_wait<0>(); }
        __syncthreads();

        uint32_t bbase = sb + (it9 & 1)*STG;
#pragma unroll
        for (int kc = 0; kc < 4; kc++) {
            int kb = kc * 16;
            uint32_t bh[8];
#pragma unroll
            for (int npair = 0; npair < 2; npair++) {
                uint32_t off = SW128((bn_row + npair*16)*128 + (kb + bn_kof)*2);
                ldm_x4(&bh[npair*4], bbase + 16384 + off);
            }
#pragma unroll
            for (int msub = 0; msub < 4; msub++) {
                uint32_t aoff = SW128((am_row + msub*16)*128 + (kb + am_kof)*2);
                uint32_t a[4];
                ldm_x4(a, bbase + aoff);
#pragma unroll
                for (int nsub = 0; nsub < 4; nsub++) {
                    int bi = (nsub >> 1)*4 + (nsub & 1)*2;
                    mma16816(acc[msub][nsub], a, bh[bi], bh[bi+1]);
                }
            }
        }
        __syncthreads();
    }

#pragma unroll
    for (int msub = 0; msub < 4; msub++) {
#pragma unroll
        for (int nsub = 0; nsub < 4; nsub++) {
            int m  = warp_m*64 + msub*16 + (lane >> 2);
            int cl = warp_n*32 + nsub*8 + (lane & 3)*2;
            smem_f[m*129 + cl]       = acc[msub][nsub][0];
            smem_f[m*129 + cl + 1]   = acc[msub][nsub][1];
            smem_f[(m+8)*129 + cl]   = acc[msub][nsub][2];
            smem_f[(m+8)*129 + cl+1] = acc[msub][nsub][3];
        }
    }
    __syncthreads();

    int pixrow = h*128;
    if (ntile == 0) {
        for (int idx = tid; idx < 27*128; idx += 256) {
            int co = idx >> 7, p = idx & 127;
            float v = smem_f[p*129 + co] + g_bias640[co];
            if (co >= 18) v = 1.f/(1.f + __expf(-v));
            g_off[(b*27 + co)*HW + pixrow + p] = v;
        }
        for (int idx = tid; idx < 128*101; idx += 256) {
            int p = idx / 101, j = idx - p*101 + 27;
            float v = tanh_fast(smem_f[p*129 + j] + g_bias640[j]);
            g_coff[((size_t)(b*HW + pixrow + p))*576 + (j - 27)] = __float2half_rn(v);
        }
    } else {
        for (int idx = tid; idx < 128*128; idx += 256) {
            int p = idx >> 7, j = idx & 127;
            int co = co0 + j;
            if (co < 603) {
                float v = tanh_fast(smem_f[p*129 + j] + g_bias640[co]);
                g_coff[((size_t)(b*HW + pixrow + p))*576 + (co - 27)] = __float2half_rn(v);
            }
        }
    }
}

// ---------------- K3: deformable sampling + HMMA final conv (1-product fp16) ----------------
// dyn smem mainloop: [0) Ah 16K | [16384) Wh 8K = 24576; epilogue stage 128x65 f32 = 33280
__global__ __launch_bounds__(256) void k3_mma(float* __restrict__ out)
{
    extern __shared__ __align__(16) char smem[];
    const int S_AH = 0, S_WH = 16384;
    uint32_t sb = smem_u32(smem);
    int tid = threadIdx.x, wid = tid >> 5, lane = tid & 31;
    int b = blockIdx.x >> 7, h = blockIdx.x & 127;

    float acc[8][4];
#pragma unroll
    for (int i = 0; i < 8; i++)
#pragma unroll
        for (int q = 0; q < 4; q++) acc[i][q] = 0.f;

    int am_row = wid*16 + (lane & 7) + (((lane >> 3) & 1) << 3);
    int am_kof = (lane >> 4) << 3;
    int bn_row = (lane & 7) + ((lane >> 4) << 3);
    int bn_kof = ((lane >> 3) & 1) * 8;

    int px = tid >> 1, half = tid & 1;
    int pixidx = h*128 + px;

    for (int n = 0; n < 9; n++) {
        // W fill via cp.async — overlaps with gather, waited before MMA
        {
            const uint4* sWh = (const uint4*)(g_w2h + n*4096);
#pragma unroll
            for (int it = 0; it < 2; it++) {
                int i = it*256 + tid;
                uint32_t sw = SW128(i*16);
                cp16(sb + S_WH + sw, sWh + i);
            }
            cp_commit();
        }

        // params in registers
        float offr = g_off[(b*27 + n)*HW + pixidx];
        float offc = g_off[(b*27 + 9 + n)*HW + pixidx];
        float mv   = g_off[(b*27 + 18 + n)*HW + pixidx];
        float pr = (float)(h + 1 + n/3 - 1) + offr;
        float pc = (float)(px + 1 + n%3 - 1) + offc;
        float flr = floorf(pr), flc = floorf(pc);
        float ltr = fminf(fmaxf(flr,       0.f), 129.f);
        float ltc = fminf(fmaxf(flc,       0.f), 129.f);
        float rbr = fminf(fmaxf(flr + 1.f, 0.f), 129.f);
        float rbc = fminf(fmaxf(flc + 1.f, 0.f), 129.f);
        float prc = fminf(fmaxf(pr,        0.f), 129.f);
        float pcc = fminf(fmaxf(pc,        0.f), 129.f);
        float g0 = (1.f + (ltr - prc))*(1.f + (ltc - pcc)); // lt
        float g1 = (1.f - (rbr - prc))*(1.f - (rbc - pcc)); // rb
        float g2 = (1.f + (ltr - prc))*(1.f - (rbc - pcc)); // lb
        float g3 = (1.f - (rbr - prc))*(1.f + (ltc - pcc)); // rt
        int iltr = (int)ltr, iltc = (int)ltc, irbr = (int)rbr, irbc = (int)rbc;
        int bb = b*130;
        int c0 = ((bb + iltr)*130 + iltc)*8;   // uint4 units (8 halves)
        int c1 = ((bb + irbr)*130 + irbc)*8;
        int c2 = ((bb + iltr)*130 + irbc)*8;
        int c3 = ((bb + irbr)*130 + iltc)*8;

        // gather + combine + pack fp16 (hi only)
        {
            const uint4* xt4 = (const uint4*)g_xth;
            size_t coffbase = ((size_t)(b*HW + h*128 + px))*576 + n*64 + half*32;
#pragma unroll
            for (int jj = 0; jj < 4; jj++) {
                int cq = half*4 + jj;
                uint4 a0 = xt4[c0 + cq], a1 = xt4[c1 + cq];
                uint4 a2 = xt4[c2 + cq], a3 = xt4[c3 + cq];
                uint4 cr = *(const uint4*)(g_coff + coffbase + jj*8);
                uint32_t hi[4];
#pragma unroll
                for (int k = 0; k < 4; k++) {
                    float2 f0 = __half22float2(((const __half2*)&a0)[k]);
                    float2 f1 = __half22float2(((const __half2*)&a1)[k]);
                    float2 f2 = __half22float2(((const __half2*)&a2)[k]);
                    float2 f3 = __half22float2(((const __half2*)&a3)[k]);
                    float2 cf = __half22float2(((const __half2*)&cr)[k]);
                    float rx = (g0*f0.x + g1*f1.x + g2*f2.x + g3*f3.x + cf.x)*mv;
                    float ry = (g0*f0.y + g1*f1.y + g2*f2.y + g3*f3.y + cf.y)*mv;
                    hi[k] = pack_f16_hi(rx, ry);
                }
                int sw = SW128(px*128 + half*64 + jj*16);
                *(uint4*)(smem + S_AH + sw) = make_uint4(hi[0], hi[1], hi[2], hi[3]);
            }
        }
        cp_wait<0>();
        __syncthreads();

        // MMA: warp tile 16 px x 64 oc, K=64, 1 product
#pragma unroll
        for (int kc = 0; kc < 4; kc++) {
            int kb = kc * 16;
            uint32_t aoff = SW128(am_row*128 + (kb + am_kof)*2);
            uint32_t ah[4];
            ldm_x4(ah, sb + S_AH + aoff);
#pragma unroll
            for (int npair = 0; npair < 4; npair++) {
                uint32_t boff = SW128((bn_row + npair*16)*128 + (kb + bn_kof)*2);
                uint32_t bhf[4];
                ldm_x4(bhf, sb + S_WH + boff);
                mma16816(acc[npair*2],     ah, bhf[0], bhf[1]);
                mma16816(acc[npair*2 + 1], ah, bhf[2], bhf[3]);
            }
        }
        __syncthreads();
    }

    // ---------- epilogue: stage 128px x 64oc (pad 65), then coalesced out ----------
    float* stage = (float*)smem;
    {
        int r0 = wid*16 + (lane >> 2);
        int cc = (lane & 3)*2;
#pragma unroll
        for (int nsub = 0; nsub < 8; nsub++) {
            int col = nsub*8 + cc;
            stage[r0*65 + col]       = acc[nsub][0];
            stage[r0*65 + col + 1]   = acc[nsub][1];
            stage[(r0+8)*65 + col]   = acc[nsub][2];
            stage[(r0+8)*65 + col+1] = acc[nsub][3];
        }
    }
    __syncthreads();
#pragma unroll
    for (int it = 0; it < 8; it++) {
        int idx = it*256 + tid;
        int oc = idx >> 5, g = idx & 31;
        int pxo = g*4;
        float4 o;
        o.x = stage[pxo*65 + oc];
        o.y = stage[(pxo+1)*65 + oc];
        o.z = stage[(pxo+2)*65 + oc];
        o.w = stage[(pxo+3)*65 + oc];
        *(float4*)&out[(size_t)(b*64 + oc)*HW + h*128 + pxo] = o;
    }
}

// ---------------- launch ----------------
extern "C" void kernel_launch(void* const* d_in, const int* in_sizes, int n_in,
                              void* d_out, int out_size)
{
    const float* x      = (const float*)d_in[0];
    const float* ref    = (const float*)d_in[1];
    const float* w_cd   = (const float*)d_in[2];
    const float* b_cd   = (const float*)d_in[3];
    const float* w_p    = (const float*)d_in[4];
    const float* b_p    = (const float*)d_in[5];
    const float* w_m    = (const float*)d_in[6];
    const float* b_m    = (const float*)d_in[7];
    const float* w_c    = (const float*)d_in[8];
    const float* b_c    = (const float*)d_in[9];
    const float* w_conv = (const float*)d_in[10];
    float* out = (float*)d_out;

    cudaFuncSetAttribute(k2_mma, cudaFuncAttributeMaxDynamicSharedMemorySize, 66048);
    cudaFuncSetAttribute(k3_mma, cudaFuncAttributeMaxDynamicSharedMemorySize, 33280);

    prep_zero<<<(BB*130*130*64/8 + 255)/256, 256>>>();
    prep_pack<<<(9*640*64 + 255)/256, 256>>>(w_p, b_p, w_m, b_m, w_c, b_c, w_cd, w_conv);
    prep_xt<<<(BB*130*130*32 + 255)/256, 256>>>(x);
    k1_fused<<<512, 256>>>(x, ref, b_cd);
    k2_mma<<<dim3(5, 512), 256, 66048>>>();
    k3_mma<<<512, 256, 33280>>>(out);
}

// round 14
// speedup vs baseline: 4.6182x; 1.0264x over previous
#include <cuda_runtime.h>
#include <cuda_fp16.h>
#include <math.h>
#include <stdint.h>

#define HW 16384
#define BB 4

// ---------------- device scratch ----------------
__device__ __half g_fph[(size_t)BB*130*130*64];  // padded channel-last fused (fp16)
__device__ __half g_xth[(size_t)BB*130*130*64];  // padded x, channel-last fp16
__device__ float g_off[BB*27*HW];                // offset(18)+m(9) [b][ch][hw]
__device__ __half g_coff[(size_t)BB*HW*9*64];    // tanh(c_off) [b][pix][n*64+c]  (fp16)
__device__ __half g_wbh[9*640*64];               // [kk][co'][ci]
__device__ float g_bias640[640];                 // co' order
__device__ float g_wcdT[128*64];                 // [ci][co]
__device__ __half g_w2h[9*64*64];                // [n][oc][c] final conv

#define SW128(o) ((o) ^ (((o) >> 3) & 0x70))

__device__ __forceinline__ uint32_t smem_u32(const void* p) {
    uint32_t a;
    asm("{ .reg .u64 t; cvta.to.shared.u64 t, %1; cvt.u32.u64 %0, t; }" : "=r"(a) : "l"(p));
    return a;
}
__device__ __forceinline__ void ldm_x4(uint32_t* r, uint32_t addr) {
    asm volatile("ldmatrix.sync.aligned.m8n8.x4.shared.b16 {%0,%1,%2,%3}, [%4];"
        : "=r"(r[0]), "=r"(r[1]), "=r"(r[2]), "=r"(r[3]) : "r"(addr));
}
__device__ __forceinline__ void mma16816(float* d, const uint32_t* a, uint32_t b0, uint32_t b1) {
    asm volatile("mma.sync.aligned.m16n8k16.row.col.f32.f16.f16.f32 "
        "{%0,%1,%2,%3}, {%4,%5,%6,%7}, {%8,%9}, {%0,%1,%2,%3};"
        : "+f"(d[0]), "+f"(d[1]), "+f"(d[2]), "+f"(d[3])
        : "r"(a[0]), "r"(a[1]), "r"(a[2]), "r"(a[3]), "r"(b0), "r"(b1));
}
__device__ __forceinline__ void cp16(uint32_t dst, const void* src) {
    asm volatile("cp.async.cg.shared.global [%0], [%1], 16;" :: "r"(dst), "l"(src));
}
__device__ __forceinline__ void cp_commit() { asm volatile("cp.async.commit_group;" ::: "memory"); }
template<int N> __device__ __forceinline__ void cp_wait() {
    asm volatile("cp.async.wait_group %0;" :: "n"(N) : "memory");
}
__device__ __forceinline__ float tanh_fast(float v) {
    float e = __expf(2.f * v);
    return 1.f - 2.f / (e + 1.f);
}
__device__ __forceinline__ uint32_t pack_f16_hi(float a, float b) {
    return ((uint32_t)__half_as_ushort(__float2half_rn(b)) << 16)
         |  (uint32_t)__half_as_ushort(__float2half_rn(a));
}

// ---------------- prep: zero only the 1-px border of fused ----------------
__global__ void prep_zero()
{
    int i = blockIdx.x * blockDim.x + threadIdx.x;
    const int n4 = (int)((size_t)BB*130*130*64/8);
    if (i >= n4) return;
    int t  = i >> 3;
    int cc = t % 130; t /= 130;
    int r  = t % 130;
    if (r == 0 || r == 129 || cc == 0 || cc == 129)
        ((uint4*)g_fph)[i] = make_uint4(0,0,0,0);
}

// ---------------- prep: pack weights ----------------
__global__ void prep_pack(const float* __restrict__ wp, const float* __restrict__ bp,
                          const float* __restrict__ wm, const float* __restrict__ bm,
                          const float* __restrict__ wc, const float* __restrict__ bc,
                          const float* __restrict__ wcd, const float* __restrict__ wconv)
{
    int idx = blockIdx.x * blockDim.x + threadIdx.x;
    if (idx < 9*640*64) {
        int kk = idx / (640*64);
        int r  = idx - kk*640*64;
        int co = r >> 6, ci = r & 63;
        float v = 0.f;
        if      (co < 18)  v = wp[(co*64 + ci)*9 + kk];
        else if (co < 27)  v = wm[((co-18)*64 + ci)*9 + kk];
        else if (co < 603) { int t = co-27; int n = t >> 6, c = t & 63;
                             v = wc[((c*9 + n)*64 + ci)*9 + kk]; }
        g_wbh[idx] = __float2half_rn(v);
    }
    if (idx < 640) {
        float bv = 0.f;
        if      (idx < 18)  bv = bp[idx];
        else if (idx < 27)  bv = bm[idx-18];
        else if (idx < 603) { int t = idx-27; int n = t >> 6, c = t & 63; bv = bc[c*9 + n]; }
        g_bias640[idx] = bv;
    }
    if (idx < 128*64) {
        int ci = idx >> 6, co = idx & 63;
        g_wcdT[idx] = wcd[co*128 + ci];
    }
    if (idx < 9*64*64) {
        int n = idx >> 12, r = idx & 4095;
        int oc = r >> 6, c = r & 63;
        g_w2h[idx] = __float2half_rn(wconv[(oc*64 + c)*9 + n]);
    }
}

// ---------------- prep: padded channel-last x (fp16, half2 stores) ----------------
__global__ void prep_xt(const float* __restrict__ x)
{
    int idx = blockIdx.x * blockDim.x + threadIdx.x;
    const int total = BB*130*130*32;          // half2 count
    if (idx >= total) return;
    int cp = idx & 31;                        // half2 index in row
    int t  = idx >> 5;
    int cc = t % 130; t /= 130;
    int r  = t % 130;
    int b  = t / 130;
    float v0 = 0.f, v1 = 0.f;
    if (r >= 1 && r <= 128 && cc >= 1 && cc <= 128) {
        int base = (b*64 + cp*2)*HW + (r-1)*128 + (cc-1);
        v0 = x[base];
        v1 = x[base + HW];
    }
    ((__half2*)g_xth)[idx] = __floats2half2_rn(v0, v1);
}

// ---------------- K1: 1x1 conv -> padded channel-last fp16 ----------------
__global__ __launch_bounds__(256) void k1_fused(const float* __restrict__ x,
                                                const float* __restrict__ ref,
                                                const float* __restrict__ bcd)
{
    __shared__ float xin[32][128];
    __shared__ float wsm[32][64];
    int tid  = threadIdx.x;
    int b    = blockIdx.x >> 7;
    int seg  = blockIdx.x & 127;
    int pix0 = seg << 7;
    int ocg  = tid & 15, pixg = tid >> 4;

    float acc[4][8];
#pragma unroll
    for (int o = 0; o < 4; o++) {
        float bv = bcd[ocg*4 + o];
#pragma unroll
        for (int j = 0; j < 8; j++) acc[o][j] = bv;
    }

    for (int ci0 = 0; ci0 < 128; ci0 += 32) {
#pragma unroll
        for (int it = 0; it < 16; it++) {
            int idx = it*256 + tid;
            int ci  = idx >> 7, px = idx & 127;
            int gl  = ci0 + ci;
            float v = (gl < 64) ? x[(b*64 + gl)*HW + pix0 + px]
                                : ref[(b*64 + gl - 64)*HW + pix0 + px];
            xin[ci][px] = v;
        }
#pragma unroll
        for (int it = 0; it < 8; it++) {
            int idx = it*256 + tid;
            int ci = idx >> 6, oc = idx & 63;
            wsm[ci][oc] = g_wcdT[(ci0 + ci)*64 + oc];
        }
        __syncthreads();
#pragma unroll
        for (int ci = 0; ci < 32; ci++) {
            float4 wv = *(const float4*)&wsm[ci][ocg*4];
            float4 x0 = *(const float4*)&xin[ci][pixg*8];
            float4 x1 = *(const float4*)&xin[ci][pixg*8 + 4];
            float wvv[4] = {wv.x, wv.y, wv.z, wv.w};
            float xv[8]  = {x0.x, x0.y, x0.z, x0.w, x1.x, x1.y, x1.z, x1.w};
#pragma unroll
            for (int o = 0; o < 4; o++)
#pragma unroll
                for (int j = 0; j < 8; j++)
                    acc[o][j] += wvv[o]*xv[j];
        }
        __syncthreads();
    }
#pragma unroll
    for (int j = 0; j < 8; j++) {
        int ww = pixg*8 + j;
        size_t base = ((size_t)(b*130 + seg + 1)*130 + (ww + 1))*64 + ocg*4;
        *(uint32_t*)&g_fph[base]     = pack_f16_hi(acc[0][j], acc[1][j]);
        *(uint32_t*)&g_fph[base + 2] = pack_f16_hi(acc[2][j], acc[3][j]);
    }
}

// ---------------- K2: HMMA implicit GEMM conv, 1-product fp16, cp.async 3-stage, 1 sync/iter ----
// dyn smem: 3 stages x 32KB (Ah 16K | Wh 16K) = 98304; epilogue reuses as 128x129 f32 (66048)
__global__ __launch_bounds__(256, 2) void k2_mma()
{
    extern __shared__ __align__(16) char smem[];
    float* smem_f = (float*)smem;
    uint32_t sb = smem_u32(smem);
    int tid = threadIdx.x, wid = tid >> 5, lane = tid & 31;
    int ntile = blockIdx.x;
    int mt    = blockIdx.y;
    int b = mt >> 7, h = mt & 127;
    int co0 = ntile * 128;
    int warp_m = wid >> 2, warp_n = wid & 3;
    const int STG = 32768;

    float acc[4][4][4];
#pragma unroll
    for (int i = 0; i < 4; i++)
#pragma unroll
        for (int j = 0; j < 4; j++)
#pragma unroll
            for (int q = 0; q < 4; q++) acc[i][j][q] = 0.f;

    int bn_row = warp_n*32 + (lane & 7) + ((lane >> 4) << 3);
    int bn_kof = ((lane >> 3) & 1) * 8;
    int am_row = warp_m*64 + (lane & 7) + (((lane >> 3) & 1) << 3);
    int am_kof = (lane >> 4) << 3;

    auto issue_fill = [&](int it9, int stg) {
        int kh = it9 / 3, kw = it9 - kh*3;
        size_t rowbase = ((size_t)(b*130 + h + kh)*130 + kw) * 64;
        const uint4* sAh = (const uint4*)(g_fph + rowbase);
        const uint4* sWh = (const uint4*)(g_wbh + ((size_t)(it9*640 + co0)) * 64);
        uint32_t base = sb + stg*STG;
#pragma unroll
        for (int it = 0; it < 4; it++) {
            int i = it*256 + tid;
            uint32_t sw = SW128(i * 16);
            cp16(base + sw,         sAh + i);
            cp16(base + 16384 + sw, sWh + i);
        }
        cp_commit();
    };

    issue_fill(0, 0);
    issue_fill(1, 1);
    for (int it9 = 0; it9 < 9; it9++) {
        if (it9 < 8) cp_wait<1>(); else cp_wait<0>();
        __syncthreads();
        // safe: fills for stage (it9+2)%3 are issued post-MMA; all warps are
        // past MMA(it9-1) once through this barrier, so that stage is free.

        uint32_t bbase = sb + (it9 % 3)*STG;
#pragma unroll
        for (int kc = 0; kc < 4; kc++) {
            int kb = kc * 16;
            uint32_t bh[8];
#pragma unroll
            for (int npair = 0; npair < 2; npair++) {
                uint32_t off = SW128((bn_row + npair*16)*128 + (kb + bn_kof)*2);
                ldm_x4(&bh[npair*4], bbase + 16384 + off);
            }
#pragma unroll
            for (int msub = 0; msub < 4; msub++) {
                uint32_t aoff = SW128((am_row + msub*16)*128 + (kb + am_kof)*2);
                uint32_t a[4];
                ldm_x4(a, bbase + aoff);
#pragma unroll
                for (int nsub = 0; nsub < 4; nsub++) {
                    int bi = (nsub >> 1)*4 + (nsub & 1)*2;
                    mma16816(acc[msub][nsub], a, bh[bi], bh[bi+1]);
                }
            }
        }
        if (it9 + 2 < 9) issue_fill(it9 + 2, (it9 + 2) % 3);
    }
    __syncthreads();

#pragma unroll
    for (int msub = 0; msub < 4; msub++) {
#pragma unroll
        for (int nsub = 0; nsub < 4; nsub++) {
            int m  = warp_m*64 + msub*16 + (lane >> 2);
            int cl = warp_n*32 + nsub*8 + (lane & 3)*2;
            smem_f[m*129 + cl]       = acc[msub][nsub][0];
            smem_f[m*129 + cl + 1]   = acc[msub][nsub][1];
            smem_f[(m+8)*129 + cl]   = acc[msub][nsub][2];
            smem_f[(m+8)*129 + cl+1] = acc[msub][nsub][3];
        }
    }
    __syncthreads();

    int pixrow = h*128;
    if (ntile == 0) {
        for (int idx = tid; idx < 27*128; idx += 256) {
            int co = idx >> 7, p = idx & 127;
            float v = smem_f[p*129 + co] + g_bias640[co];
            if (co >= 18) v = 1.f/(1.f + __expf(-v));
            g_off[(b*27 + co)*HW + pixrow + p] = v;
        }
        for (int idx = tid; idx < 128*101; idx += 256) {
            int p = idx / 101, j = idx - p*101 + 27;
            float v = tanh_fast(smem_f[p*129 + j] + g_bias640[j]);
            g_coff[((size_t)(b*HW + pixrow + p))*576 + (j - 27)] = __float2half_rn(v);
        }
    } else {
        for (int idx = tid; idx < 128*128; idx += 256) {
            int p = idx >> 7, j = idx & 127;
            int co = co0 + j;
            if (co < 603) {
                float v = tanh_fast(smem_f[p*129 + j] + g_bias640[co]);
                g_coff[((size_t)(b*HW + pixrow + p))*576 + (co - 27)] = __float2half_rn(v);
            }
        }
    }
}

// ---------------- K3: deformable sampling + HMMA final conv (1-product fp16) ----------------
// dyn smem: A0 [0,16K) | A1 [16K,32K) | W0 [32K,40K) | W1 [40K,48K) = 49152
// single sync per iter; gather(n+1) overlaps MMA(n) across warps.
__global__ __launch_bounds__(256) void k3_mma(float* __restrict__ out)
{
    extern __shared__ __align__(16) char smem[];
    uint32_t sb = smem_u32(smem);
    int tid = threadIdx.x, wid = tid >> 5, lane = tid & 31;
    int b = blockIdx.x >> 7, h = blockIdx.x & 127;

    float acc[8][4];
#pragma unroll
    for (int i = 0; i < 8; i++)
#pragma unroll
        for (int q = 0; q < 4; q++) acc[i][q] = 0.f;

    int am_row = wid*16 + (lane & 7) + (((lane >> 3) & 1) << 3);
    int am_kof = (lane >> 4) << 3;
    int bn_row = (lane & 7) + ((lane >> 4) << 3);
    int bn_kof = ((lane >> 3) & 1) * 8;

    int px = tid >> 1, half = tid & 1;
    int pixidx = h*128 + px;

    auto issueW = [&](int n, int buf) {
        const uint4* sWh = (const uint4*)(g_w2h + n*4096);
#pragma unroll
        for (int it = 0; it < 2; it++) {
            int i = it*256 + tid;
            uint32_t sw = SW128(i*16);
            cp16(sb + 32768 + buf*8192 + sw, sWh + i);
        }
        cp_commit();
    };

    issueW(0, 0);
    for (int n = 0; n < 9; n++) {
        // params in registers
        float offr = g_off[(b*27 + n)*HW + pixidx];
        float offc = g_off[(b*27 + 9 + n)*HW + pixidx];
        float mv   = g_off[(b*27 + 18 + n)*HW + pixidx];
        float pr = (float)(h + 1 + n/3 - 1) + offr;
        float pc = (float)(px + 1 + n%3 - 1) + offc;
        float flr = floorf(pr), flc = floorf(pc);
        float ltr = fminf(fmaxf(flr,       0.f), 129.f);
        float ltc = fminf(fmaxf(flc,       0.f), 129.f);
        float rbr = fminf(fmaxf(flr + 1.f, 0.f), 129.f);
        float rbc = fminf(fmaxf(flc + 1.f, 0.f), 129.f);
        float prc = fminf(fmaxf(pr,        0.f), 129.f);
        float pcc = fminf(fmaxf(pc,        0.f), 129.f);
        float g0 = (1.f + (ltr - prc))*(1.f + (ltc - pcc)); // lt
        float g1 = (1.f - (rbr - prc))*(1.f - (rbc - pcc)); // rb
        float g2 = (1.f + (ltr - prc))*(1.f - (rbc - pcc)); // lb
        float g3 = (1.f - (rbr - prc))*(1.f + (ltc - pcc)); // rt
        int iltr = (int)ltr, iltc = (int)ltc, irbr = (int)rbr, irbc = (int)rbc;
        int bb = b*130;
        int c0 = ((bb + iltr)*130 + iltc)*8;   // uint4 units (8 halves)
        int c1 = ((bb + irbr)*130 + irbc)*8;
        int c2 = ((bb + iltr)*130 + irbc)*8;
        int c3 = ((bb + irbr)*130 + iltc)*8;

        // gather + combine + pack fp16 (hi only) into A[n&1]
        {
            uint32_t abase = (uint32_t)((n & 1) * 16384);
            const uint4* xt4 = (const uint4*)g_xth;
            size_t coffbase = ((size_t)(b*HW + h*128 + px))*576 + n*64 + half*32;
#pragma unroll
            for (int jj = 0; jj < 4; jj++) {
                int cq = half*4 + jj;
                uint4 a0 = xt4[c0 + cq], a1 = xt4[c1 + cq];
                uint4 a2 = xt4[c2 + cq], a3 = xt4[c3 + cq];
                uint4 cr = *(const uint4*)(g_coff + coffbase + jj*8);
                uint32_t hi[4];
#pragma unroll
                for (int k = 0; k < 4; k++) {
                    float2 f0 = __half22float2(((const __half2*)&a0)[k]);
                    float2 f1 = __half22float2(((const __half2*)&a1)[k]);
                    float2 f2 = __half22float2(((const __half2*)&a2)[k]);
                    float2 f3 = __half22float2(((const __half2*)&a3)[k]);
                    float2 cf = __half22float2(((const __half2*)&cr)[k]);
                    float rx = (g0*f0.x + g1*f1.x + g2*f2.x + g3*f3.x + cf.x)*mv;
                    float ry = (g0*f0.y + g1*f1.y + g2*f2.y + g3*f3.y + cf.y)*mv;
                    hi[k] = pack_f16_hi(rx, ry);
                }
                uint32_t sw = SW128((uint32_t)(px*128 + half*64 + jj*16));
                *(uint4*)(smem + abase + sw) = make_uint4(hi[0], hi[1], hi[2], hi[3]);
            }
        }
        cp_wait<0>();      // W[n] ready (issued last iter, post-sync)
        __syncthreads();   // all warps: A[n&1] stored, past MMA(n-1)
        if (n < 8) issueW(n + 1, (n + 1) & 1);   // safe: W[(n+1)&1] last read at MMA(n-1)

        // MMA: warp tile 16 px x 64 oc, K=64, 1 product
        uint32_t ab = sb + (n & 1)*16384;
        uint32_t wb = sb + 32768 + (n & 1)*8192;
#pragma unroll
        for (int kc = 0; kc < 4; kc++) {
            int kb = kc * 16;
            uint32_t aoff = SW128(am_row*128 + (kb + am_kof)*2);
            uint32_t ah[4];
            ldm_x4(ah, ab + aoff);
#pragma unroll
            for (int npair = 0; npair < 4; npair++) {
                uint32_t boff = SW128((bn_row + npair*16)*128 + (kb + bn_kof)*2);
                uint32_t bhf[4];
                ldm_x4(bhf, wb + boff);
                mma16816(acc[npair*2],     ah, bhf[0], bhf[1]);
                mma16816(acc[npair*2 + 1], ah, bhf[2], bhf[3]);
            }
        }
    }
    __syncthreads();

    // ---------- epilogue: stage 128px x 64oc (pad 65), then coalesced out ----------
    float* stage = (float*)smem;
    {
        int r0 = wid*16 + (lane >> 2);
        int cc = (lane & 3)*2;
#pragma unroll
        for (int nsub = 0; nsub < 8; nsub++) {
            int col = nsub*8 + cc;
            stage[r0*65 + col]       = acc[nsub][0];
            stage[r0*65 + col + 1]   = acc[nsub][1];
            stage[(r0+8)*65 + col]   = acc[nsub][2];
            stage[(r0+8)*65 + col+1] = acc[nsub][3];
        }
    }
    __syncthreads();
#pragma unroll
    for (int it = 0; it < 8; it++) {
        int idx = it*256 + tid;
        int oc = idx >> 5, g = idx & 31;
        int pxo = g*4;
        float4 o;
        o.x = stage[pxo*65 + oc];
        o.y = stage[(pxo+1)*65 + oc];
        o.z = stage[(pxo+2)*65 + oc];
        o.w = stage[(pxo+3)*65 + oc];
        *(float4*)&out[(size_t)(b*64 + oc)*HW + h*128 + pxo] = o;
    }
}

// ---------------- launch ----------------
extern "C" void kernel_launch(void* const* d_in, const int* in_sizes, int n_in,
                              void* d_out, int out_size)
{
    const float* x      = (const float*)d_in[0];
    const float* ref    = (const float*)d_in[1];
    const float* w_cd   = (const float*)d_in[2];
    const float* b_cd   = (const float*)d_in[3];
    const float* w_p    = (const float*)d_in[4];
    const float* b_p    = (const float*)d_in[5];
    const float* w_m    = (const float*)d_in[6];
    const float* b_m    = (const float*)d_in[7];
    const float* w_c    = (const float*)d_in[8];
    const float* b_c    = (const float*)d_in[9];
    const float* w_conv = (const float*)d_in[10];
    float* out = (float*)d_out;

    cudaFuncSetAttribute(k2_mma, cudaFuncAttributeMaxDynamicSharedMemorySize, 98304);
    cudaFuncSetAttribute(k3_mma, cudaFuncAttributeMaxDynamicSharedMemorySize, 49152);

    prep_zero<<<(BB*130*130*64/8 + 255)/256, 256>>>();
    prep_pack<<<(9*640*64 + 255)/256, 256>>>(w_p, b_p, w_m, b_m, w_c, b_c, w_cd, w_conv);
    prep_xt<<<(BB*130*130*32 + 255)/256, 256>>>(x);
    k1_fused<<<512, 256>>>(x, ref, b_cd);
    k2_mma<<<dim3(5, 512), 256, 98304>>>();
    k3_mma<<<512, 256, 49152>>>(out);
}

// round 15
// speedup vs baseline: 4.9576x; 1.0735x over previous
#include <cuda_runtime.h>
#include <cuda_fp16.h>
#include <math.h>
#include <stdint.h>

#define HW 16384
#define BB 4

// ---------------- device scratch ----------------
__device__ __half g_fph[(size_t)BB*130*130*64];  // padded channel-last fused (fp16)
__device__ __half g_xth[(size_t)BB*130*130*64];  // padded x, channel-last fp16
__device__ float g_off[BB*27*HW];                // offset(18)+m(9) [b][ch][hw]
__device__ __half g_coff[(size_t)BB*HW*9*64];    // tanh(c_off) [b][pix][n*64+c]  (fp16)
__device__ __half g_wbh[9*640*64];               // [kk][co'][ci]
__device__ float g_bias640[640];                 // co' order
__device__ __half g_w1h[2*64*64];                // [khalf][oc][ci64] 1x1 conv W fp16
__device__ __half g_w2h[9*64*64];                // [n][oc][c] final conv

#define SW128(o) ((o) ^ (((o) >> 3) & 0x70))

__device__ __forceinline__ uint32_t smem_u32(const void* p) {
    uint32_t a;
    asm("{ .reg .u64 t; cvta.to.shared.u64 t, %1; cvt.u32.u64 %0, t; }" : "=r"(a) : "l"(p));
    return a;
}
__device__ __forceinline__ void ldm_x4(uint32_t* r, uint32_t addr) {
    asm volatile("ldmatrix.sync.aligned.m8n8.x4.shared.b16 {%0,%1,%2,%3}, [%4];"
        : "=r"(r[0]), "=r"(r[1]), "=r"(r[2]), "=r"(r[3]) : "r"(addr));
}
__device__ __forceinline__ void mma16816(float* d, const uint32_t* a, uint32_t b0, uint32_t b1) {
    asm volatile("mma.sync.aligned.m16n8k16.row.col.f32.f16.f16.f32 "
        "{%0,%1,%2,%3}, {%4,%5,%6,%7}, {%8,%9}, {%0,%1,%2,%3};"
        : "+f"(d[0]), "+f"(d[1]), "+f"(d[2]), "+f"(d[3])
        : "r"(a[0]), "r"(a[1]), "r"(a[2]), "r"(a[3]), "r"(b0), "r"(b1));
}
__device__ __forceinline__ void cp16(uint32_t dst, const void* src) {
    asm volatile("cp.async.cg.shared.global [%0], [%1], 16;" :: "r"(dst), "l"(src));
}
__device__ __forceinline__ void cp_commit() { asm volatile("cp.async.commit_group;" ::: "memory"); }
template<int N> __device__ __forceinline__ void cp_wait() {
    asm volatile("cp.async.wait_group %0;" :: "n"(N) : "memory");
}
__device__ __forceinline__ float tanh_fast(float v) {
    float e = __expf(2.f * v);
    return 1.f - 2.f / (e + 1.f);
}
__device__ __forceinline__ uint32_t pack_f16_hi(float a, float b) {
    return ((uint32_t)__half_as_ushort(__float2half_rn(b)) << 16)
         |  (uint32_t)__half_as_ushort(__float2half_rn(a));
}

// ---------------- prep: zero only the 1-px border of fused ----------------
__global__ void prep_zero()
{
    int i = blockIdx.x * blockDim.x + threadIdx.x;
    const int n4 = (int)((size_t)BB*130*130*64/8);
    if (i >= n4) return;
    int t  = i >> 3;
    int cc = t % 130; t /= 130;
    int r  = t % 130;
    if (r == 0 || r == 129 || cc == 0 || cc == 129)
        ((uint4*)g_fph)[i] = make_uint4(0,0,0,0);
}

// ---------------- prep: pack weights ----------------
__global__ void prep_pack(const float* __restrict__ wp, const float* __restrict__ bp,
                          const float* __restrict__ wm, const float* __restrict__ bm,
                          const float* __restrict__ wc, const float* __restrict__ bc,
                          const float* __restrict__ wcd, const float* __restrict__ wconv)
{
    int idx = blockIdx.x * blockDim.x + threadIdx.x;
    if (idx < 9*640*64) {
        int kk = idx / (640*64);
        int r  = idx - kk*640*64;
        int co = r >> 6, ci = r & 63;
        float v = 0.f;
        if      (co < 18)  v = wp[(co*64 + ci)*9 + kk];
        else if (co < 27)  v = wm[((co-18)*64 + ci)*9 + kk];
        else if (co < 603) { int t = co-27; int n = t >> 6, c = t & 63;
                             v = wc[((c*9 + n)*64 + ci)*9 + kk]; }
        g_wbh[idx] = __float2half_rn(v);
    }
    if (idx < 640) {
        float bv = 0.f;
        if      (idx < 18)  bv = bp[idx];
        else if (idx < 27)  bv = bm[idx-18];
        else if (idx < 603) { int t = idx-27; int n = t >> 6, c = t & 63; bv = bc[c*9 + n]; }
        g_bias640[idx] = bv;
    }
    if (idx < 2*64*64) {
        int t = idx >> 12, r = idx & 4095;
        int oc = r >> 6, ci = r & 63;
        g_w1h[idx] = __float2half_rn(wcd[oc*128 + t*64 + ci]);
    }
    if (idx < 9*64*64) {
        int n = idx >> 12, r = idx & 4095;
        int oc = r >> 6, c = r & 63;
        g_w2h[idx] = __float2half_rn(wconv[(oc*64 + c)*9 + n]);
    }
}

// ---------------- prep: padded channel-last x (fp16, half2 stores) ----------------
__global__ void prep_xt(const float* __restrict__ x)
{
    int idx = blockIdx.x * blockDim.x + threadIdx.x;
    const int total = BB*130*130*32;          // half2 count
    if (idx >= total) return;
    int cp = idx & 31;                        // half2 index in row
    int t  = idx >> 5;
    int cc = t % 130; t /= 130;
    int r  = t % 130;
    int b  = t / 130;
    float v0 = 0.f, v1 = 0.f;
    if (r >= 1 && r <= 128 && cc >= 1 && cc <= 128) {
        int base = (b*64 + cp*2)*HW + (r-1)*128 + (cc-1);
        v0 = x[base];
        v1 = x[base + HW];
    }
    ((__half2*)g_xth)[idx] = __floats2half2_rn(v0, v1);
}

// ---------------- K1: 1x1 conv via HMMA -> padded channel-last fp16 ----------------
// grid 512 (b,seg), 256 threads. smem: A0 [0,16K) A1 [16K,32K) W0 [32K,40K) W1 [40K,48K)
// epilogue stage (16 KB) reuses A0.
__global__ __launch_bounds__(256) void k1_mma(const float* __restrict__ x,
                                              const float* __restrict__ ref,
                                              const float* __restrict__ bcd)
{
    extern __shared__ __align__(16) char smem[];
    uint32_t sb = smem_u32(smem);
    int tid = threadIdx.x, wid = tid >> 5, lane = tid & 31;
    int b = blockIdx.x >> 7, seg = blockIdx.x & 127;
    int pix0 = seg << 7;

    // W fill via cp.async (2 tiles x 8KB)
    {
        const uint4* w4 = (const uint4*)g_w1h;   // [2][64 rows][8 chunks]
#pragma unroll
        for (int it = 0; it < 4; it++) {
            int i = it*256 + tid;                // 0..1023
            int t = i >> 9, r = i & 511;
            cp16(sb + 32768 + t*8192 + SW128(r*16), w4 + i);
        }
        cp_commit();
    }

    // A transpose fill: [px][ci] fp16, two K=64 tiles, coalesced global reads
#pragma unroll
    for (int it = 0; it < 32; it++) {
        int i = it*256 + tid;                    // 8192: ci2 = i>>7 (0..63), px = i&127
        int ci2 = i >> 7, px = i & 127;
        int gci = ci2*2;
        float v0, v1;
        if (gci < 64) {
            v0 = x[(b*64 + gci)*HW + pix0 + px];
            v1 = x[(b*64 + gci + 1)*HW + pix0 + px];
        } else {
            v0 = ref[(b*64 + gci - 64)*HW + pix0 + px];
            v1 = ref[(b*64 + gci - 63)*HW + pix0 + px];
        }
        int t = ci2 >> 5, cl = ci2 & 31;
        *(uint32_t*)(smem + t*16384 + SW128(px*128 + cl*4)) = pack_f16_hi(v0, v1);
    }
    cp_wait<0>();
    __syncthreads();

    // MMA: warp tile 16 px x 64 oc, K=128 (two K=64 tiles)
    float acc[8][4];
#pragma unroll
    for (int i = 0; i < 8; i++)
#pragma unroll
        for (int q = 0; q < 4; q++) acc[i][q] = 0.f;

    int am_row = wid*16 + (lane & 7) + (((lane >> 3) & 1) << 3);
    int am_kof = (lane >> 4) << 3;
    int bn_row = (lane & 7) + ((lane >> 4) << 3);
    int bn_kof = ((lane >> 3) & 1) * 8;

#pragma unroll
    for (int t = 0; t < 2; t++) {
        uint32_t ab = sb + t*16384;
        uint32_t wb = sb + 32768 + t*8192;
#pragma unroll
        for (int kc = 0; kc < 4; kc++) {
            int kb = kc * 16;
            uint32_t ah[4];
            ldm_x4(ah, ab + SW128(am_row*128 + (kb + am_kof)*2));
#pragma unroll
            for (int npair = 0; npair < 4; npair++) {
                uint32_t bhf[4];
                ldm_x4(bhf, wb + SW128((bn_row + npair*16)*128 + (kb + bn_kof)*2));
                mma16816(acc[npair*2],     ah, bhf[0], bhf[1]);
                mma16816(acc[npair*2 + 1], ah, bhf[2], bhf[3]);
            }
        }
    }
    __syncthreads();

    // epilogue: +bias, pack fp16, stage [px][64oc] swizzled (conflict-free), then linear copy
    {
        int r0 = lane >> 2, c0 = (lane & 3)*2;
#pragma unroll
        for (int nsub = 0; nsub < 8; nsub++) {
            float b0 = bcd[nsub*8 + c0], b1 = bcd[nsub*8 + c0 + 1];
            uint32_t p0 = pack_f16_hi(acc[nsub][0] + b0, acc[nsub][1] + b1);
            uint32_t p1 = pack_f16_hi(acc[nsub][2] + b0, acc[nsub][3] + b1);
            int colb = (nsub*8 + c0)*2;
            *(uint32_t*)(smem + SW128((wid*16 + r0)*128 + colb))     = p0;
            *(uint32_t*)(smem + SW128((wid*16 + r0 + 8)*128 + colb)) = p1;
        }
    }
    __syncthreads();
    {
        uint4* dst = (uint4*)(g_fph + ((size_t)(b*130 + seg + 1)*130 + 1)*64);
#pragma unroll
        for (int it = 0; it < 4; it++) {
            int i = it*256 + tid;                // 1024 uint4 = 16 KB
            dst[i] = *(const uint4*)(smem + SW128(i*16));
        }
    }
}

// ---------------- K2: HMMA implicit GEMM conv, 1-product fp16, cp.async 3-stage ----------------
// dyn smem: 3 stages x 32KB (Ah 16K | Wh 16K) = 98304; epilogue reuses as 128x129 f32 (66048)
__global__ __launch_bounds__(256, 2) void k2_mma()
{
    extern __shared__ __align__(16) char smem[];
    float* smem_f = (float*)smem;
    uint32_t sb = smem_u32(smem);
    int tid = threadIdx.x, wid = tid >> 5, lane = tid & 31;
    int ntile = blockIdx.x;
    int mt    = blockIdx.y;
    int b = mt >> 7, h = mt & 127;
    int co0 = ntile * 128;
    int warp_m = wid >> 2, warp_n = wid & 3;
    const int STG = 32768;

    float acc[4][4][4];
#pragma unroll
    for (int i = 0; i < 4; i++)
#pragma unroll
        for (int j = 0; j < 4; j++)
#pragma unroll
            for (int q = 0; q < 4; q++) acc[i][j][q] = 0.f;

    int bn_row = warp_n*32 + (lane & 7) + ((lane >> 4) << 3);
    int bn_kof = ((lane >> 3) & 1) * 8;
    int am_row = warp_m*64 + (lane & 7) + (((lane >> 3) & 1) << 3);
    int am_kof = (lane >> 4) << 3;

    auto issue_fill = [&](int it9, int stg) {
        int kh = it9 / 3, kw = it9 - kh*3;
        size_t rowbase = ((size_t)(b*130 + h + kh)*130 + kw) * 64;
        const uint4* sAh = (const uint4*)(g_fph + rowbase);
        const uint4* sWh = (const uint4*)(g_wbh + ((size_t)(it9*640 + co0)) * 64);
        uint32_t base = sb + stg*STG;
#pragma unroll
        for (int it = 0; it < 4; it++) {
            int i = it*256 + tid;
            uint32_t sw = SW128(i * 16);
            cp16(base + sw,         sAh + i);
            cp16(base + 16384 + sw, sWh + i);
        }
        cp_commit();
    };

    issue_fill(0, 0);
    issue_fill(1, 1);
    for (int it9 = 0; it9 < 9; it9++) {
        if (it9 < 8) cp_wait<1>(); else cp_wait<0>();
        __syncthreads();

        uint32_t bbase = sb + (it9 % 3)*STG;
#pragma unroll
        for (int kc = 0; kc < 4; kc++) {
            int kb = kc * 16;
            uint32_t bh[8];
#pragma unroll
            for (int npair = 0; npair < 2; npair++) {
                uint32_t off = SW128((bn_row + npair*16)*128 + (kb + bn_kof)*2);
                ldm_x4(&bh[npair*4], bbase + 16384 + off);
            }
#pragma unroll
            for (int msub = 0; msub < 4; msub++) {
                uint32_t aoff = SW128((am_row + msub*16)*128 + (kb + am_kof)*2);
                uint32_t a[4];
                ldm_x4(a, bbase + aoff);
#pragma unroll
                for (int nsub = 0; nsub < 4; nsub++) {
                    int bi = (nsub >> 1)*4 + (nsub & 1)*2;
                    mma16816(acc[msub][nsub], a, bh[bi], bh[bi+1]);
                }
            }
        }
        if (it9 + 2 < 9) issue_fill(it9 + 2, (it9 + 2) % 3);
    }
    __syncthreads();

#pragma unroll
    for (int msub = 0; msub < 4; msub++) {
#pragma unroll
        for (int nsub = 0; nsub < 4; nsub++) {
            int m  = warp_m*64 + msub*16 + (lane >> 2);
            int cl = warp_n*32 + nsub*8 + (lane & 3)*2;
            smem_f[m*129 + cl]       = acc[msub][nsub][0];
            smem_f[m*129 + cl + 1]   = acc[msub][nsub][1];
            smem_f[(m+8)*129 + cl]   = acc[msub][nsub][2];
            smem_f[(m+8)*129 + cl+1] = acc[msub][nsub][3];
        }
    }
    __syncthreads();

    int pixrow = h*128;
    if (ntile == 0) {
        for (int idx = tid; idx < 27*128; idx += 256) {
            int co = idx >> 7, p = idx & 127;
            float v = smem_f[p*129 + co] + g_bias640[co];
            if (co >= 18) v = 1.f/(1.f + __expf(-v));
            g_off[(b*27 + co)*HW + pixrow + p] = v;
        }
        for (int idx = tid; idx < 128*101; idx += 256) {
            int p = idx / 101, j = idx - p*101 + 27;
            float v = tanh_fast(smem_f[p*129 + j] + g_bias640[j]);
            g_coff[((size_t)(b*HW + pixrow + p))*576 + (j - 27)] = __float2half_rn(v);
        }
    } else {
        for (int idx = tid; idx < 128*128; idx += 256) {
            int p = idx >> 7, j = idx & 127;
            int co = co0 + j;
            if (co < 603) {
                float v = tanh_fast(smem_f[p*129 + j] + g_bias640[co]);
                g_coff[((size_t)(b*HW + pixrow + p))*576 + (co - 27)] = __float2half_rn(v);
            }
        }
    }
}

// ---------------- K3: deformable sampling + HMMA final conv (1-product fp16) ----------------
// dyn smem: A0 [0,16K) | A1 [16K,32K) | W0 [32K,40K) | W1 [40K,48K) = 49152
__global__ __launch_bounds__(256) void k3_mma(float* __restrict__ out)
{
    extern __shared__ __align__(16) char smem[];
    uint32_t sb = smem_u32(smem);
    int tid = threadIdx.x, wid = tid >> 5, lane = tid & 31;
    int b = blockIdx.x >> 7, h = blockIdx.x & 127;

    float acc[8][4];
#pragma unroll
    for (int i = 0; i < 8; i++)
#pragma unroll
        for (int q = 0; q < 4; q++) acc[i][q] = 0.f;

    int am_row = wid*16 + (lane & 7) + (((lane >> 3) & 1) << 3);
    int am_kof = (lane >> 4) << 3;
    int bn_row = (lane & 7) + ((lane >> 4) << 3);
    int bn_kof = ((lane >> 3) & 1) * 8;

    int px = tid >> 1, half = tid & 1;
    int pixidx = h*128 + px;

    auto issueW = [&](int n, int buf) {
        const uint4* sWh = (const uint4*)(g_w2h + n*4096);
#pragma unroll
        for (int it = 0; it < 2; it++) {
            int i = it*256 + tid;
            uint32_t sw = SW128(i*16);
            cp16(sb + 32768 + buf*8192 + sw, sWh + i);
        }
        cp_commit();
    };

    issueW(0, 0);
    for (int n = 0; n < 9; n++) {
        float offr = g_off[(b*27 + n)*HW + pixidx];
        float offc = g_off[(b*27 + 9 + n)*HW + pixidx];
        float mv   = g_off[(b*27 + 18 + n)*HW + pixidx];
        float pr = (float)(h + 1 + n/3 - 1) + offr;
        float pc = (float)(px + 1 + n%3 - 1) + offc;
        float flr = floorf(pr), flc = floorf(pc);
        float ltr = fminf(fmaxf(flr,       0.f), 129.f);
        float ltc = fminf(fmaxf(flc,       0.f), 129.f);
        float rbr = fminf(fmaxf(flr + 1.f, 0.f), 129.f);
        float rbc = fminf(fmaxf(flc + 1.f, 0.f), 129.f);
        float prc = fminf(fmaxf(pr,        0.f), 129.f);
        float pcc = fminf(fmaxf(pc,        0.f), 129.f);
        float g0 = (1.f + (ltr - prc))*(1.f + (ltc - pcc)); // lt
        float g1 = (1.f - (rbr - prc))*(1.f - (rbc - pcc)); // rb
        float g2 = (1.f + (ltr - prc))*(1.f - (rbc - pcc)); // lb
        float g3 = (1.f - (rbr - prc))*(1.f + (ltc - pcc)); // rt
        int iltr = (int)ltr, iltc = (int)ltc, irbr = (int)rbr, irbc = (int)rbc;
        int bb = b*130;
        int c0 = ((bb + iltr)*130 + iltc)*8;   // uint4 units (8 halves)
        int c1 = ((bb + irbr)*130 + irbc)*8;
        int c2 = ((bb + iltr)*130 + irbc)*8;
        int c3 = ((bb + irbr)*130 + iltc)*8;

        // gather + combine + pack fp16 (hi only) into A[n&1]
        {
            uint32_t abase = (uint32_t)((n & 1) * 16384);
            const uint4* xt4 = (const uint4*)g_xth;
            size_t coffbase = ((size_t)(b*HW + h*128 + px))*576 + n*64 + half*32;
#pragma unroll
            for (int jj = 0; jj < 4; jj++) {
                int cq = half*4 + jj;
                uint4 a0 = xt4[c0 + cq], a1 = xt4[c1 + cq];
                uint4 a2 = xt4[c2 + cq], a3 = xt4[c3 + cq];
                uint4 cr = *(const uint4*)(g_coff + coffbase + jj*8);
                uint32_t hi[4];
#pragma unroll
                for (int k = 0; k < 4; k++) {
                    float2 f0 = __half22float2(((const __half2*)&a0)[k]);
                    float2 f1 = __half22float2(((const __half2*)&a1)[k]);
                    float2 f2 = __half22float2(((const __half2*)&a2)[k]);
                    float2 f3 = __half22float2(((const __half2*)&a3)[k]);
                    float2 cf = __half22float2(((const __half2*)&cr)[k]);
                    float rx = (g0*f0.x + g1*f1.x + g2*f2.x + g3*f3.x + cf.x)*mv;
                    float ry = (g0*f0.y + g1*f1.y + g2*f2.y + g3*f3.y + cf.y)*mv;
                    hi[k] = pack_f16_hi(rx, ry);
                }
                uint32_t sw = SW128((uint32_t)(px*128 + half*64 + jj*16));
                *(uint4*)(smem + abase + sw) = make_uint4(hi[0], hi[1], hi[2], hi[3]);
            }
        }
        cp_wait<0>();
        __syncthreads();
        if (n < 8) issueW(n + 1, (n + 1) & 1);

        uint32_t ab = sb + (n & 1)*16384;
        uint32_t wb = sb + 32768 + (n & 1)*8192;
#pragma unroll
        for (int kc = 0; kc < 4; kc++) {
            int kb = kc * 16;
            uint32_t aoff = SW128(am_row*128 + (kb + am_kof)*2);
            uint32_t ah[4];
            ldm_x4(ah, ab + aoff);
#pragma unroll
            for (int npair = 0; npair < 4; npair++) {
                uint32_t boff = SW128((bn_row + npair*16)*128 + (kb + bn_kof)*2);
                uint32_t bhf[4];
                ldm_x4(bhf, wb + boff);
                mma16816(acc[npair*2],     ah, bhf[0], bhf[1]);
                mma16816(acc[npair*2 + 1], ah, bhf[2], bhf[3]);
            }
        }
    }
    __syncthreads();

    // ---------- epilogue ----------
    float* stage = (float*)smem;
    {
        int r0 = wid*16 + (lane >> 2);
        int cc = (lane & 3)*2;
#pragma unroll
        for (int nsub = 0; nsub < 8; nsub++) {
            int col = nsub*8 + cc;
            stage[r0*65 + col]       = acc[nsub][0];
            stage[r0*65 + col + 1]   = acc[nsub][1];
            stage[(r0+8)*65 + col]   = acc[nsub][2];
            stage[(r0+8)*65 + col+1] = acc[nsub][3];
        }
    }
    __syncthreads();
#pragma unroll
    for (int it = 0; it < 8; it++) {
        int idx = it*256 + tid;
        int oc = idx >> 5, g = idx & 31;
        int pxo = g*4;
        float4 o;
        o.x = stage[pxo*65 + oc];
        o.y = stage[(pxo+1)*65 + oc];
        o.z = stage[(pxo+2)*65 + oc];
        o.w = stage[(pxo+3)*65 + oc];
        *(float4*)&out[(size_t)(b*64 + oc)*HW + h*128 + pxo] = o;
    }
}

// ---------------- launch ----------------
extern "C" void kernel_launch(void* const* d_in, const int* in_sizes, int n_in,
                              void* d_out, int out_size)
{
    const float* x      = (const float*)d_in[0];
    const float* ref    = (const float*)d_in[1];
    const float* w_cd   = (const float*)d_in[2];
    const float* b_cd   = (const float*)d_in[3];
    const float* w_p    = (const float*)d_in[4];
    const float* b_p    = (const float*)d_in[5];
    const float* w_m    = (const float*)d_in[6];
    const float* b_m    = (const float*)d_in[7];
    const float* w_c    = (const float*)d_in[8];
    const float* b_c    = (const float*)d_in[9];
    const float* w_conv = (const float*)d_in[10];
    float* out = (float*)d_out;

    cudaFuncSetAttribute(k1_mma, cudaFuncAttributeMaxDynamicSharedMemorySize, 49152);
    cudaFuncSetAttribute(k2_mma, cudaFuncAttributeMaxDynamicSharedMemorySize, 98304);
    cudaFuncSetAttribute(k3_mma, cudaFuncAttributeMaxDynamicSharedMemorySize, 49152);

    prep_zero<<<(BB*130*130*64/8 + 255)/256, 256>>>();
    prep_pack<<<(9*640*64 + 255)/256, 256>>>(w_p, b_p, w_m, b_m, w_c, b_c, w_cd, w_conv);
    prep_xt<<<(BB*130*130*32 + 255)/256, 256>>>(x);
    k1_mma<<<512, 256, 49152>>>(x, ref, b_cd);
    k2_mma<<<dim3(5, 512), 256, 98304>>>();
    k3_mma<<<512, 256, 49152>>>(out);
}

// round 16
// speedup vs baseline: 5.5121x; 1.1118x over previous
#include <cuda_runtime.h>
#include <cuda_fp16.h>
#include <math.h>
#include <stdint.h>

#define HW 16384
#define BB 4

// ---------------- device scratch ----------------
__device__ __half g_fph[(size_t)BB*130*130*64];  // padded channel-last fused (fp16)
__device__ __half g_xth[(size_t)BB*130*130*64];  // padded x, channel-last fp16
__device__ float g_off[BB*27*HW];                // offset(18)+m(9) [b][ch][hw]
__device__ __half g_coff[(size_t)BB*HW*9*64];    // tanh(c_off) [b][pix][n*64+c]  (fp16)
__device__ __half g_wbh[9*640*64];               // [kk][co'][ci]
__device__ float g_bias640[640];                 // co' order
__device__ __half g_w1h[2*64*64];                // [khalf][oc][ci64] 1x1 conv W fp16
__device__ __half g_w2h[9*64*64];                // [n][oc][c] final conv

#define SW128(o) ((o) ^ (((o) >> 3) & 0x70))

__device__ __forceinline__ uint32_t smem_u32(const void* p) {
    uint32_t a;
    asm("{ .reg .u64 t; cvta.to.shared.u64 t, %1; cvt.u32.u64 %0, t; }" : "=r"(a) : "l"(p));
    return a;
}
__device__ __forceinline__ void ldm_x4(uint32_t* r, uint32_t addr) {
    asm volatile("ldmatrix.sync.aligned.m8n8.x4.shared.b16 {%0,%1,%2,%3}, [%4];"
        : "=r"(r[0]), "=r"(r[1]), "=r"(r[2]), "=r"(r[3]) : "r"(addr));
}
__device__ __forceinline__ void mma16816(float* d, const uint32_t* a, uint32_t b0, uint32_t b1) {
    asm volatile("mma.sync.aligned.m16n8k16.row.col.f32.f16.f16.f32 "
        "{%0,%1,%2,%3}, {%4,%5,%6,%7}, {%8,%9}, {%0,%1,%2,%3};"
        : "+f"(d[0]), "+f"(d[1]), "+f"(d[2]), "+f"(d[3])
        : "r"(a[0]), "r"(a[1]), "r"(a[2]), "r"(a[3]), "r"(b0), "r"(b1));
}
__device__ __forceinline__ void cp16(uint32_t dst, const void* src) {
    asm volatile("cp.async.cg.shared.global [%0], [%1], 16;" :: "r"(dst), "l"(src));
}
__device__ __forceinline__ void cp_commit() { asm volatile("cp.async.commit_group;" ::: "memory"); }
template<int N> __device__ __forceinline__ void cp_wait() {
    asm volatile("cp.async.wait_group %0;" :: "n"(N) : "memory");
}
__device__ __forceinline__ float tanh_fast(float v) {
    float r;
    asm("tanh.approx.f32 %0, %1;" : "=f"(r) : "f"(v));
    return r;
}
__device__ __forceinline__ uint32_t pack_f16_hi(float a, float b) {
    return ((uint32_t)__half_as_ushort(__float2half_rn(b)) << 16)
         |  (uint32_t)__half_as_ushort(__float2half_rn(a));
}

// ---------------- prep: pack weights + zero fused border (merged) ----------------
__global__ void prep_pack(const float* __restrict__ wp, const float* __restrict__ bp,
                          const float* __restrict__ wm, const float* __restrict__ bm,
                          const float* __restrict__ wc, const float* __restrict__ bc,
                          const float* __restrict__ wcd, const float* __restrict__ wconv)
{
    int idx = blockIdx.x * blockDim.x + threadIdx.x;
    // zero 1-px border of g_fph (uint4 granules)
    {
        const int n4 = (int)((size_t)BB*130*130*64/8);
        if (idx < n4) {
            int t  = idx >> 3;
            int cc = t % 130; t /= 130;
            int r  = t % 130;
            if (r == 0 || r == 129 || cc == 0 || cc == 129)
                ((uint4*)g_fph)[idx] = make_uint4(0,0,0,0);
        }
    }
    if (idx < 9*640*64) {
        int kk = idx / (640*64);
        int r  = idx - kk*640*64;
        int co = r >> 6, ci = r & 63;
        float v = 0.f;
        if      (co < 18)  v = wp[(co*64 + ci)*9 + kk];
        else if (co < 27)  v = wm[((co-18)*64 + ci)*9 + kk];
        else if (co < 603) { int t = co-27; int n = t >> 6, c = t & 63;
                             v = wc[((c*9 + n)*64 + ci)*9 + kk]; }
        g_wbh[idx] = __float2half_rn(v);
    }
    if (idx < 640) {
        float bv = 0.f;
        if      (idx < 18)  bv = bp[idx];
        else if (idx < 27)  bv = bm[idx-18];
        else if (idx < 603) { int t = idx-27; int n = t >> 6, c = t & 63; bv = bc[c*9 + n]; }
        g_bias640[idx] = bv;
    }
    if (idx < 2*64*64) {
        int t = idx >> 12, r = idx & 4095;
        int oc = r >> 6, ci = r & 63;
        g_w1h[idx] = __float2half_rn(wcd[oc*128 + t*64 + ci]);
    }
    if (idx < 9*64*64) {
        int n = idx >> 12, r = idx & 4095;
        int oc = r >> 6, c = r & 63;
        g_w2h[idx] = __float2half_rn(wconv[(oc*64 + c)*9 + n]);
    }
}

// ---------------- prep: padded channel-last x (fp16, half2 stores) ----------------
__global__ void prep_xt(const float* __restrict__ x)
{
    int idx = blockIdx.x * blockDim.x + threadIdx.x;
    const int total = BB*130*130*32;          // half2 count
    if (idx >= total) return;
    int cp = idx & 31;                        // half2 index in row
    int t  = idx >> 5;
    int cc = t % 130; t /= 130;
    int r  = t % 130;
    int b  = t / 130;
    float v0 = 0.f, v1 = 0.f;
    if (r >= 1 && r <= 128 && cc >= 1 && cc <= 128) {
        int base = (b*64 + cp*2)*HW + (r-1)*128 + (cc-1);
        v0 = x[base];
        v1 = x[base + HW];
    }
    ((__half2*)g_xth)[idx] = __floats2half2_rn(v0, v1);
}

// ---------------- K1: 1x1 conv via HMMA -> padded channel-last fp16 ----------------
__global__ __launch_bounds__(256) void k1_mma(const float* __restrict__ x,
                                              const float* __restrict__ ref,
                                              const float* __restrict__ bcd)
{
    extern __shared__ __align__(16) char smem[];
    uint32_t sb = smem_u32(smem);
    int tid = threadIdx.x, wid = tid >> 5, lane = tid & 31;
    int b = blockIdx.x >> 7, seg = blockIdx.x & 127;
    int pix0 = seg << 7;

    // W fill via cp.async (2 tiles x 8KB)
    {
        const uint4* w4 = (const uint4*)g_w1h;
#pragma unroll
        for (int it = 0; it < 4; it++) {
            int i = it*256 + tid;
            int t = i >> 9, r = i & 511;
            cp16(sb + 32768 + t*8192 + SW128(r*16), w4 + i);
        }
        cp_commit();
    }

    // A transpose fill: [px][ci] fp16, two K=64 tiles, coalesced global reads
#pragma unroll
    for (int it = 0; it < 32; it++) {
        int i = it*256 + tid;
        int ci2 = i >> 7, px = i & 127;
        int gci = ci2*2;
        float v0, v1;
        if (gci < 64) {
            v0 = x[(b*64 + gci)*HW + pix0 + px];
            v1 = x[(b*64 + gci + 1)*HW + pix0 + px];
        } else {
            v0 = ref[(b*64 + gci - 64)*HW + pix0 + px];
            v1 = ref[(b*64 + gci - 63)*HW + pix0 + px];
        }
        int t = ci2 >> 5, cl = ci2 & 31;
        *(uint32_t*)(smem + t*16384 + SW128(px*128 + cl*4)) = pack_f16_hi(v0, v1);
    }
    cp_wait<0>();
    __syncthreads();

    float acc[8][4];
#pragma unroll
    for (int i = 0; i < 8; i++)
#pragma unroll
        for (int q = 0; q < 4; q++) acc[i][q] = 0.f;

    int am_row = wid*16 + (lane & 7) + (((lane >> 3) & 1) << 3);
    int am_kof = (lane >> 4) << 3;
    int bn_row = (lane & 7) + ((lane >> 4) << 3);
    int bn_kof = ((lane >> 3) & 1) * 8;

#pragma unroll
    for (int t = 0; t < 2; t++) {
        uint32_t ab = sb + t*16384;
        uint32_t wb = sb + 32768 + t*8192;
#pragma unroll
        for (int kc = 0; kc < 4; kc++) {
            int kb = kc * 16;
            uint32_t ah[4];
            ldm_x4(ah, ab + SW128(am_row*128 + (kb + am_kof)*2));
#pragma unroll
            for (int npair = 0; npair < 4; npair++) {
                uint32_t bhf[4];
                ldm_x4(bhf, wb + SW128((bn_row + npair*16)*128 + (kb + bn_kof)*2));
                mma16816(acc[npair*2],     ah, bhf[0], bhf[1]);
                mma16816(acc[npair*2 + 1], ah, bhf[2], bhf[3]);
            }
        }
    }
    __syncthreads();

    // epilogue: +bias, pack fp16, stage swizzled, then linear copy
    {
        int r0 = lane >> 2, c0 = (lane & 3)*2;
#pragma unroll
        for (int nsub = 0; nsub < 8; nsub++) {
            float b0 = bcd[nsub*8 + c0], b1 = bcd[nsub*8 + c0 + 1];
            uint32_t p0 = pack_f16_hi(acc[nsub][0] + b0, acc[nsub][1] + b1);
            uint32_t p1 = pack_f16_hi(acc[nsub][2] + b0, acc[nsub][3] + b1);
            int colb = (nsub*8 + c0)*2;
            *(uint32_t*)(smem + SW128((wid*16 + r0)*128 + colb))     = p0;
            *(uint32_t*)(smem + SW128((wid*16 + r0 + 8)*128 + colb)) = p1;
        }
    }
    __syncthreads();
    {
        uint4* dst = (uint4*)(g_fph + ((size_t)(b*130 + seg + 1)*130 + 1)*64);
#pragma unroll
        for (int it = 0; it < 4; it++) {
            int i = it*256 + tid;
            dst[i] = *(const uint4*)(smem + SW128(i*16));
        }
    }
}

// ---------------- K2: HMMA implicit GEMM conv, 1-product fp16, cp.async 3-stage ----------------
__global__ __launch_bounds__(256, 2) void k2_mma()
{
    extern __shared__ __align__(16) char smem[];
    float* smem_f = (float*)smem;
    uint32_t sb = smem_u32(smem);
    int tid = threadIdx.x, wid = tid >> 5, lane = tid & 31;
    int ntile = blockIdx.x;
    int mt    = blockIdx.y;
    int b = mt >> 7, h = mt & 127;
    int co0 = ntile * 128;
    int warp_m = wid >> 2, warp_n = wid & 3;
    const int STG = 32768;

    float acc[4][4][4];
#pragma unroll
    for (int i = 0; i < 4; i++)
#pragma unroll
        for (int j = 0; j < 4; j++)
#pragma unroll
            for (int q = 0; q < 4; q++) acc[i][j][q] = 0.f;

    int bn_row = warp_n*32 + (lane & 7) + ((lane >> 4) << 3);
    int bn_kof = ((lane >> 3) & 1) * 8;
    int am_row = warp_m*64 + (lane & 7) + (((lane >> 3) & 1) << 3);
    int am_kof = (lane >> 4) << 3;

    auto issue_fill = [&](int it9, int stg) {
        int kh = it9 / 3, kw = it9 - kh*3;
        size_t rowbase = ((size_t)(b*130 + h + kh)*130 + kw) * 64;
        const uint4* sAh = (const uint4*)(g_fph + rowbase);
        const uint4* sWh = (const uint4*)(g_wbh + ((size_t)(it9*640 + co0)) * 64);
        uint32_t base = sb + stg*STG;
#pragma unroll
        for (int it = 0; it < 4; it++) {
            int i = it*256 + tid;
            uint32_t sw = SW128(i * 16);
            cp16(base + sw,         sAh + i);
            cp16(base + 16384 + sw, sWh + i);
        }
        cp_commit();
    };

    issue_fill(0, 0);
    issue_fill(1, 1);
    for (int it9 = 0; it9 < 9; it9++) {
        if (it9 < 8) cp_wait<1>(); else cp_wait<0>();
        __syncthreads();

        uint32_t bbase = sb + (it9 % 3)*STG;
#pragma unroll
        for (int kc = 0; kc < 4; kc++) {
            int kb = kc * 16;
            uint32_t bh[8];
#pragma unroll
            for (int npair = 0; npair < 2; npair++) {
                uint32_t off = SW128((bn_row + npair*16)*128 + (kb + bn_kof)*2);
                ldm_x4(&bh[npair*4], bbase + 16384 + off);
            }
#pragma unroll
            for (int msub = 0; msub < 4; msub++) {
                uint32_t aoff = SW128((am_row + msub*16)*128 + (kb + am_kof)*2);
                uint32_t a[4];
                ldm_x4(a, bbase + aoff);
#pragma unroll
                for (int nsub = 0; nsub < 4; nsub++) {
                    int bi = (nsub >> 1)*4 + (nsub & 1)*2;
                    mma16816(acc[msub][nsub], a, bh[bi], bh[bi+1]);
                }
            }
        }
        if (it9 + 2 < 9) issue_fill(it9 + 2, (it9 + 2) % 3);
    }
    __syncthreads();

#pragma unroll
    for (int msub = 0; msub < 4; msub++) {
#pragma unroll
        for (int nsub = 0; nsub < 4; nsub++) {
            int m  = warp_m*64 + msub*16 + (lane >> 2);
            int cl = warp_n*32 + nsub*8 + (lane & 3)*2;
            smem_f[m*129 + cl]       = acc[msub][nsub][0];
            smem_f[m*129 + cl + 1]   = acc[msub][nsub][1];
            smem_f[(m+8)*129 + cl]   = acc[msub][nsub][2];
            smem_f[(m+8)*129 + cl+1] = acc[msub][nsub][3];
        }
    }
    __syncthreads();

    int pixrow = h*128;
    if (ntile == 0) {
        for (int idx = tid; idx < 27*128; idx += 256) {
            int co = idx >> 7, p = idx & 127;
            float v = smem_f[p*129 + co] + g_bias640[co];
            if (co >= 18) v = 1.f/(1.f + __expf(-v));
            g_off[(b*27 + co)*HW + pixrow + p] = v;
        }
        for (int idx = tid; idx < 128*101; idx += 256) {
            int p = idx / 101, j = idx - p*101 + 27;
            float v = tanh_fast(smem_f[p*129 + j] + g_bias640[j]);
            g_coff[((size_t)(b*HW + pixrow + p))*576 + (j - 27)] = __float2half_rn(v);
        }
    } else {
        for (int idx = tid; idx < 128*128; idx += 256) {
            int p = idx >> 7, j = idx & 127;
            int co = co0 + j;
            if (co < 603) {
                float v = tanh_fast(smem_f[p*129 + j] + g_bias640[co]);
                g_coff[((size_t)(b*HW + pixrow + p))*576 + (co - 27)] = __float2half_rn(v);
            }
        }
    }
}

// ---------------- K3: deformable sampling + HMMA final conv (1-product fp16) ----------------
__global__ __launch_bounds__(256) void k3_mma(float* __restrict__ out)
{
    extern __shared__ __align__(16) char smem[];
    uint32_t sb = smem_u32(smem);
    int tid = threadIdx.x, wid = tid >> 5, lane = tid & 31;
    int b = blockIdx.x >> 7, h = blockIdx.x & 127;

    float acc[8][4];
#pragma unroll
    for (int i = 0; i < 8; i++)
#pragma unroll
        for (int q = 0; q < 4; q++) acc[i][q] = 0.f;

    int am_row = wid*16 + (lane & 7) + (((lane >> 3) & 1) << 3);
    int am_kof = (lane >> 4) << 3;
    int bn_row = (lane & 7) + ((lane >> 4) << 3);
    int bn_kof = ((lane >> 3) & 1) * 8;

    int px = tid >> 1, half = tid & 1;
    int pixidx = h*128 + px;

    auto issueW = [&](int n, int buf) {
        const uint4* sWh = (const uint4*)(g_w2h + n*4096);
#pragma unroll
        for (int it = 0; it < 2; it++) {
            int i = it*256 + tid;
            uint32_t sw = SW128(i*16);
            cp16(sb + 32768 + buf*8192 + sw, sWh + i);
        }
        cp_commit();
    };

    issueW(0, 0);
    for (int n = 0; n < 9; n++) {
        float offr = g_off[(b*27 + n)*HW + pixidx];
        float offc = g_off[(b*27 + 9 + n)*HW + pixidx];
        float mv   = g_off[(b*27 + 18 + n)*HW + pixidx];
        float pr = (float)(h + 1 + n/3 - 1) + offr;
        float pc = (float)(px + 1 + n%3 - 1) + offc;
        float flr = floorf(pr), flc = floorf(pc);
        float ltr = fminf(fmaxf(flr,       0.f), 129.f);
        float ltc = fminf(fmaxf(flc,       0.f), 129.f);
        float rbr = fminf(fmaxf(flr + 1.f, 0.f), 129.f);
        float rbc = fminf(fmaxf(flc + 1.f, 0.f), 129.f);
        float prc = fminf(fmaxf(pr,        0.f), 129.f);
        float pcc = fminf(fmaxf(pc,        0.f), 129.f);
        float g0 = (1.f + (ltr - prc))*(1.f + (ltc - pcc)); // lt
        float g1 = (1.f - (rbr - prc))*(1.f - (rbc - pcc)); // rb
        float g2 = (1.f + (ltr - prc))*(1.f - (rbc - pcc)); // lb
        float g3 = (1.f - (rbr - prc))*(1.f + (ltc - pcc)); // rt
        int iltr = (int)ltr, iltc = (int)ltc, irbr = (int)rbr, irbc = (int)rbc;
        int bb = b*130;
        int c0 = ((bb + iltr)*130 + iltc)*8;   // uint4 units (8 halves)
        int c1 = ((bb + irbr)*130 + irbc)*8;
        int c2 = ((bb + iltr)*130 + irbc)*8;
        int c3 = ((bb + irbr)*130 + iltc)*8;

        // gather + combine + pack fp16 (hi only) into A[n&1]
        {
            uint32_t abase = (uint32_t)((n & 1) * 16384);
            const uint4* xt4 = (const uint4*)g_xth;
            size_t coffbase = ((size_t)(b*HW + h*128 + px))*576 + n*64 + half*32;
#pragma unroll
            for (int jj = 0; jj < 4; jj++) {
                int cq = half*4 + jj;
                uint4 a0 = xt4[c0 + cq], a1 = xt4[c1 + cq];
                uint4 a2 = xt4[c2 + cq], a3 = xt4[c3 + cq];
                uint4 cr = *(const uint4*)(g_coff + coffbase + jj*8);
                uint32_t hi[4];
#pragma unroll
                for (int k = 0; k < 4; k++) {
                    float2 f0 = __half22float2(((const __half2*)&a0)[k]);
                    float2 f1 = __half22float2(((const __half2*)&a1)[k]);
                    float2 f2 = __half22float2(((const __half2*)&a2)[k]);
                    float2 f3 = __half22float2(((const __half2*)&a3)[k]);
                    float2 cf = __half22float2(((const __half2*)&cr)[k]);
                    float rx = (g0*f0.x + g1*f1.x + g2*f2.x + g3*f3.x + cf.x)*mv;
                    float ry = (g0*f0.y + g1*f1.y + g2*f2.y + g3*f3.y + cf.y)*mv;
                    hi[k] = pack_f16_hi(rx, ry);
                }
                uint32_t sw = SW128((uint32_t)(px*128 + half*64 + jj*16));
                *(uint4*)(smem + abase + sw) = make_uint4(hi[0], hi[1], hi[2], hi[3]);
            }
        }
        cp_wait<0>();
        __syncthreads();
        if (n < 8) issueW(n + 1, (n + 1) & 1);

        uint32_t ab = sb + (n & 1)*16384;
        uint32_t wb = sb + 32768 + (n & 1)*8192;
#pragma unroll
        for (int kc = 0; kc < 4; kc++) {
            int kb = kc * 16;
            uint32_t aoff = SW128(am_row*128 + (kb + am_kof)*2);
            uint32_t ah[4];
            ldm_x4(ah, ab + aoff);
#pragma unroll
            for (int npair = 0; npair < 4; npair++) {
                uint32_t boff = SW128((bn_row + npair*16)*128 + (kb + bn_kof)*2);
                uint32_t bhf[4];
                ldm_x4(bhf, wb + boff);
                mma16816(acc[npair*2],     ah, bhf[0], bhf[1]);
                mma16816(acc[npair*2 + 1], ah, bhf[2], bhf[3]);
            }
        }
    }
    __syncthreads();

    // ---------- epilogue ----------
    float* stage = (float*)smem;
    {
        int r0 = wid*16 + (lane >> 2);
        int cc = (lane & 3)*2;
#pragma unroll
        for (int nsub = 0; nsub < 8; nsub++) {
            int col = nsub*8 + cc;
            stage[r0*65 + col]       = acc[nsub][0];
            stage[r0*65 + col + 1]   = acc[nsub][1];
            stage[(r0+8)*65 + col]   = acc[nsub][2];
            stage[(r0+8)*65 + col+1] = acc[nsub][3];
        }
    }
    __syncthreads();
#pragma unroll
    for (int it = 0; it < 8; it++) {
        int idx = it*256 + tid;
        int oc = idx >> 5, g = idx & 31;
        int pxo = g*4;
        float4 o;
        o.x = stage[pxo*65 + oc];
        o.y = stage[(pxo+1)*65 + oc];
        o.z = stage[(pxo+2)*65 + oc];
        o.w = stage[(pxo+3)*65 + oc];
        *(float4*)&out[(size_t)(b*64 + oc)*HW + h*128 + pxo] = o;
    }
}

// ---------------- launch ----------------
extern "C" void kernel_launch(void* const* d_in, const int* in_sizes, int n_in,
                              void* d_out, int out_size)
{
    const float* x      = (const float*)d_in[0];
    const float* ref    = (const float*)d_in[1];
    const float* w_cd   = (const float*)d_in[2];
    const float* b_cd   = (const float*)d_in[3];
    const float* w_p    = (const float*)d_in[4];
    const float* b_p    = (const float*)d_in[5];
    const float* w_m    = (const float*)d_in[6];
    const float* b_m    = (const float*)d_in[7];
    const float* w_c    = (const float*)d_in[8];
    const float* b_c    = (const float*)d_in[9];
    const float* w_conv = (const float*)d_in[10];
    float* out = (float*)d_out;

    cudaFuncSetAttribute(k1_mma, cudaFuncAttributeMaxDynamicSharedMemorySize, 49152);
    cudaFuncSetAttribute(k2_mma, cudaFuncAttributeMaxDynamicSharedMemorySize, 98304);
    cudaFuncSetAttribute(k3_mma, cudaFuncAttributeMaxDynamicSharedMemorySize, 49152);

    prep_pack<<<((size_t)BB*130*130*64/8 + 255)/256, 256>>>(w_p, b_p, w_m, b_m, w_c, b_c, w_cd, w_conv);
    prep_xt<<<(BB*130*130*32 + 255)/256, 256>>>(x);
    k1_mma<<<512, 256, 49152>>>(x, ref, b_cd);
    k2_mma<<<dim3(5, 512), 256, 98304>>>();
    k3_mma<<<512, 256, 49152>>>(out);
}